// round 9
// baseline (speedup 1.0000x reference)
#include <cuda_runtime.h>
#include <math.h>
#include <stdint.h>

namespace {
constexpr int kBn = 2, kS = 1024, kD = 1024, kH = 16, kDH = 64, kL = 4;
constexpr int kBS = kBn * kS;          // 2048 rows
constexpr int kBH = kBn * kH;          // 32 (b,h) pairs
constexpr int TR = 16;                 // query rows per attention block
constexpr int NT16 = kS / TR;          // 64 tiles per (b,h)
constexpr int SCP = 1028;              // padded score-row stride (stride%32==4)
constexpr int ATTN_THREADS = 256;      // 8 warps
// smem: scores + phase3 reduction buffer + per-warp softmax stats
constexpr int ATTN_SMEM = (TR * SCP + TR * kDH + TR * 8 * 2) * 4;  // 70912 B
// GEMM tiling: 128x64 blocks -> 256/512 CTA grids, multi-CTA/SM residency
constexpr int BM = 128, BN = 64, BK = 32;
constexpr int ASTR = 36, BSTR = 72;    // padded smem strides
constexpr int GEMM_SMEM = (2 * BM * ASTR + 2 * BK * BSTR) * 4;  // 55296 B
}

// Scratch (static device allocations; no runtime allocs)
__device__ float g_x[kBS * kD];
__device__ float g_qh[kBH * kS * kDH];
__device__ float g_vh[kBH * kS * kDH];
__device__ float g_ao[kBS * kD];
__device__ float g_proj[kBS * kD];

// ---------------------------------------------------------------------------
__device__ __forceinline__ uint32_t f2tf(float x) {
    uint32_t r;
    asm("cvt.rna.tf32.f32 %0, %1;" : "=r"(r) : "f"(x));
    return r;
}
__device__ __forceinline__ float sqrt_approx(float x) {
    float r;
    asm("sqrt.approx.f32 %0, %1;" : "=f"(r) : "f"(x));
    return r;
}
__device__ __forceinline__ void mma8(float* d, const uint32_t* a, const uint32_t* b) {
    asm volatile(
        "mma.sync.aligned.m16n8k8.row.col.f32.tf32.tf32.f32 "
        "{%0,%1,%2,%3}, {%4,%5,%6,%7}, {%8,%9}, {%0,%1,%2,%3};\n"
        : "+f"(d[0]), "+f"(d[1]), "+f"(d[2]), "+f"(d[3])
        : "r"(a[0]), "r"(a[1]), "r"(a[2]), "r"(a[3]), "r"(b[0]), "r"(b[1]));
}
// online softmax accumulate
__device__ __forceinline__ void osm(float v, float& m, float& s) {
    if (v > m) { s = s * __expf(m - v) + 1.f; m = v; }
    else       s += __expf(v - m);
}
// merge two (m,s) online-softmax states
__device__ __forceinline__ void osm_merge(float om, float os, float& m, float& s) {
    float nm = fmaxf(m, om);
    s = s * __expf(m - nm) + os * __expf(om - nm);
    m = nm;
}

// ---------------------------------------------------------------------------
// Shared GEMM body: C[2048,1024] = A @ W + bias, tf32 mma, cp.async dbuf.
// Block tile 128x64, 8 warps (4x2) of 32x32.
template<bool SCATTER>
__device__ __forceinline__ void gemm_body(const float* __restrict__ A,
                                          const float* __restrict__ W,
                                          const float* __restrict__ bias,
                                          float* __restrict__ C,
                                          int bxx, int byy, float* sm) {
    float* As = sm;
    float* Bs = sm + 2 * BM * ASTR;
    const int tid = threadIdx.x, lane = tid & 31, w = tid >> 5;
    const int gid = lane >> 2, l4 = lane & 3;
    const int warpM = w & 3, warpN = w >> 2;
    const int mbase = byy * BM, nbase = bxx * BN;
    const uint32_t sA = (uint32_t)__cvta_generic_to_shared(As);
    const uint32_t sB = (uint32_t)__cvta_generic_to_shared(Bs);

    auto prefetch = [&](int kt, int buf) {
        #pragma unroll
        for (int i = 0; i < 4; i++) {
            int cid = tid + i * 256;
            int m = cid >> 3, kc = cid & 7;
            uint32_t dst = sA + (uint32_t)((buf * BM * ASTR + m * ASTR + kc * 4) * 4);
            const float* src = A + (size_t)(mbase + m) * kD + kt * BK + kc * 4;
            asm volatile("cp.async.cg.shared.global [%0], [%1], 16;\n" ::"r"(dst), "l"(src));
        }
        #pragma unroll
        for (int i = 0; i < 2; i++) {
            int cid = tid + i * 256;
            int k = cid >> 4, nc = cid & 15;   // full 32 x 64 tile
            uint32_t dst = sB + (uint32_t)((buf * BK * BSTR + k * BSTR + nc * 4) * 4);
            const float* src = W + (size_t)(kt * BK + k) * kD + nbase + nc * 4;
            asm volatile("cp.async.cg.shared.global [%0], [%1], 16;\n" ::"r"(dst), "l"(src));
        }
        asm volatile("cp.async.commit_group;\n");
    };

    float acc[2][4][4] = {};
    prefetch(0, 0);
    const int nK = kD / BK;
    for (int kt = 0; kt < nK; kt++) {
        asm volatile("cp.async.wait_group 0;\n");
        __syncthreads();
        if (kt + 1 < nK) prefetch(kt + 1, (kt + 1) & 1);
        const float* as = As + (kt & 1) * BM * ASTR;
        const float* bs = Bs + (kt & 1) * BK * BSTR;
        #pragma unroll
        for (int ks = 0; ks < 4; ks++) {
            uint32_t af[2][4];
            #pragma unroll
            for (int mt = 0; mt < 2; mt++) {
                int r = warpM * 32 + mt * 16 + gid;
                const float* p = as + r * ASTR + ks * 8 + l4;
                af[mt][0] = f2tf(p[0]);
                af[mt][1] = f2tf(p[8 * ASTR]);
                af[mt][2] = f2tf(p[4]);
                af[mt][3] = f2tf(p[8 * ASTR + 4]);
            }
            #pragma unroll
            for (int nt = 0; nt < 4; nt++) {
                uint32_t bf[2];
                int cn = warpN * 32 + nt * 8 + gid;
                const float* p = bs + (ks * 8 + l4) * BSTR + cn;
                bf[0] = f2tf(p[0]);
                bf[1] = f2tf(p[4 * BSTR]);
                #pragma unroll
                for (int mt = 0; mt < 2; mt++) mma8(acc[mt][nt], af[mt], bf);
            }
        }
        __syncthreads();
    }
    #pragma unroll
    for (int mt = 0; mt < 2; mt++) {
        int r0 = mbase + warpM * 32 + mt * 16 + gid;
        #pragma unroll
        for (int nt = 0; nt < 4; nt++) {
            int cc = nbase + warpN * 32 + nt * 8 + l4 * 2;
            float b0 = bias[cc], b1 = bias[cc + 1];
            float2 u = make_float2(acc[mt][nt][0] + b0, acc[mt][nt][1] + b1);
            float2 v = make_float2(acc[mt][nt][2] + b0, acc[mt][nt][3] + b1);
            if (SCATTER) {
                int bb = r0 / kS, s = r0 - bb * kS;
                int h = cc >> 6, d = cc & 63;
                *(float2*)&C[(((size_t)bb * kH + h) * kS + s) * kDH + d] = u;
                *(float2*)&C[(((size_t)bb * kH + h) * kS + s + 8) * kDH + d] = v;
            } else {
                *(float2*)&C[(size_t)r0 * kD + cc] = u;
                *(float2*)&C[(size_t)(r0 + 8) * kD + cc] = v;
            }
        }
    }
}

// Fused Wq+Wv projections: blockIdx.z selects which GEMM. 512 CTAs.
__global__ void __launch_bounds__(256) gemm_qv(const float* __restrict__ A,
                                               const float* __restrict__ Wq,
                                               const float* __restrict__ bq,
                                               const float* __restrict__ Wv,
                                               const float* __restrict__ bv,
                                               float* __restrict__ Cq,
                                               float* __restrict__ Cv) {
    extern __shared__ float sm[];
    const float* W = blockIdx.z ? Wv : Wq;
    const float* bias = blockIdx.z ? bv : bq;
    float* C = blockIdx.z ? Cv : Cq;
    gemm_body<true>(A, W, bias, C, blockIdx.x, blockIdx.y, sm);
}

__global__ void __launch_bounds__(256) gemm_o(const float* __restrict__ A,
                                              const float* __restrict__ W,
                                              const float* __restrict__ bias,
                                              float* __restrict__ C) {
    extern __shared__ float sm[];
    gemm_body<false>(A, W, bias, C, blockIdx.x, blockIdx.y, sm);
}

// ---------------------------------------------------------------------------
// Gamma attention, 16 query rows per block, 8 warps, 3 CTAs/SM.
// Softmax-1 stats fused into phase 1; phase 3 split 4 col-groups x 2 halves.
__global__ void __launch_bounds__(ATTN_THREADS, 3) attn_k(const float* __restrict__ gam) {
    extern __shared__ float sc[];                 // [TR][SCP] score rows
    float* red = sc + TR * SCP;                   // [TR][64] phase-3 partials
    float* wstat = red + TR * kDH;                // [TR][8][2] per-warp (m,s)

    const int bx = blockIdx.x;
    const int bh = bx & (kBH - 1);
    const int tile = (NT16 - 1) - (bx >> 5);
    const int h = bh & (kH - 1);
    const int b = bh >> 4;
    const int base = tile * TR;
    const int tid = threadIdx.x, lane = tid & 31, w = tid >> 5;
    const int gid = lane >> 2, l4 = lane & 3;
    const float* qb = g_qh + (size_t)bh * kS * kDH;
    const float* vb = g_vh + (size_t)bh * kS * kDH;
    const int nkt = tile + 1, kLimit = nkt * TR;

    // ---- Phase 1: scores = QK^T / 8 with fused online softmax-1 stats.
    {
        uint32_t qa[8][4];
        #pragma unroll
        for (int ks = 0; ks < 8; ks++) {
            const float* p = qb + (size_t)(base + gid) * kDH + ks * 8 + l4;
            qa[ks][0] = f2tf(p[0]);
            qa[ks][1] = f2tf(p[8 * kDH]);
            qa[ks][2] = f2tf(p[4]);
            qa[ks][3] = f2tf(p[8 * kDH + 4]);
        }
        const int i0 = base + gid, i1 = base + gid + 8;  // this lane's rows
        float m0 = -3.4e38f, s0 = 0.f, m1 = -3.4e38f, s1 = 0.f;
        for (int kt = w; kt < nkt; kt += 8) {
            const float* kp = qb + (size_t)kt * TR * kDH;
            float acc[2][4] = {};
            #pragma unroll
            for (int ks = 0; ks < 8; ks++) {
                #pragma unroll
                for (int nt = 0; nt < 2; nt++) {
                    uint32_t bf[2];
                    const float* p = kp + (size_t)(nt * 8 + gid) * kDH + ks * 8 + l4;
                    bf[0] = f2tf(p[0]);
                    bf[1] = f2tf(p[4]);
                    mma8(acc[nt], qa[ks], bf);
                }
            }
            const bool diag = (kt == tile);
            #pragma unroll
            for (int nt = 0; nt < 2; nt++) {
                int c0 = kt * TR + nt * 8 + l4 * 2;
                float v00 = acc[nt][0] * 0.125f, v01 = acc[nt][1] * 0.125f;
                float v10 = acc[nt][2] * 0.125f, v11 = acc[nt][3] * 0.125f;
                *(float2*)&sc[gid * SCP + c0] = make_float2(v00, v01);
                *(float2*)&sc[(gid + 8) * SCP + c0] = make_float2(v10, v11);
                if (!diag) {            // all cols strictly below both rows
                    osm(v00, m0, s0); osm(v01, m0, s0);
                    osm(v10, m1, s1); osm(v11, m1, s1);
                } else {                // diagonal tile: mask j < i
                    if (c0 < i0)     osm(v00, m0, s0);
                    if (c0 + 1 < i0) osm(v01, m0, s0);
                    if (c0 < i1)     osm(v10, m1, s1);
                    if (c0 + 1 < i1) osm(v11, m1, s1);
                }
            }
        }
        // quad reduce (lanes sharing gid are l4 = 0..3)
        #pragma unroll
        for (int o = 1; o <= 2; o <<= 1) {
            float om = __shfl_xor_sync(~0u, m0, o), os = __shfl_xor_sync(~0u, s0, o);
            osm_merge(om, os, m0, s0);
            om = __shfl_xor_sync(~0u, m1, o); os = __shfl_xor_sync(~0u, s1, o);
            osm_merge(om, os, m1, s1);
        }
        if (l4 == 0) {
            wstat[(gid * 8 + w) * 2] = m0;
            wstat[(gid * 8 + w) * 2 + 1] = s0;
            wstat[((gid + 8) * 8 + w) * 2] = m1;
            wstat[((gid + 8) * 8 + w) * 2 + 1] = s1;
        }
    }
    __syncthreads();

    // ---- Phase 2: combine stats -> scan decay (online stats2) -> finalize.
    {
        const float gm = -fabsf(gam[h]);
        const int i0r = base + w;
        const int i1r = i0r + 8;
        float* row0 = sc + w * SCP;
        float* row1 = sc + (w + 8) * SCP;
        const int nv0 = i0r, nv1 = i1r;   // strict causal: keys j < i

        // combine the 8 per-warp partials for this warp's two rows
        float m0 = -3.4e38f, s0 = 0.f, m1 = -3.4e38f, s1 = 0.f;
        #pragma unroll
        for (int p = 0; p < 8; p++) {
            osm_merge(wstat[(w * 8 + p) * 2], wstat[(w * 8 + p) * 2 + 1], m0, s0);
            osm_merge(wstat[((w + 8) * 8 + p) * 2], wstat[((w + 8) * 8 + p) * 2 + 1], m1, s1);
        }
        const float inv0 = (nv0 > 0) ? 1.f / s0 : 0.f;
        const float inv1 = 1.f / s1;

        // Pass B: warp-scan cumsum of p, apply decay, store s2, online stats2.
        float carry0 = 0.f, carry1 = 0.f;
        float n0 = -3.4e38f, t0 = 0.f, n1 = -3.4e38f, t1 = 0.f;
        for (int c0 = 0; c0 < nv1; c0 += 32) {
            int j = c0 + lane;
            if (c0 < nv0) {
                bool vld = j < nv0;
                float sv = vld ? row0[j] : 0.f;
                float p = vld ? __expf(sv - m0) * inv0 : 0.f;
                #pragma unroll
                for (int o = 1; o < 32; o <<= 1) {
                    float t = __shfl_up_sync(~0u, p, o);
                    if (lane >= o) p += t;
                }
                float cum = p + carry0;
                carry0 = __shfl_sync(~0u, cum, 31);
                if (vld) {
                    float rem = 1.0f - cum;              // disttotal == 1
                    float tt = fmaxf(rem * (float)(i0r - j), 0.f);
                    float eff = fmaxf(__expf(gm * sqrt_approx(tt)), 1e-5f);
                    float s2 = sv * eff;
                    row0[j] = s2;
                    osm(s2, n0, t0);
                }
            }
            {
                bool vld = j < nv1;
                float sv = vld ? row1[j] : 0.f;
                float p = vld ? __expf(sv - m1) * inv1 : 0.f;
                #pragma unroll
                for (int o = 1; o < 32; o <<= 1) {
                    float t = __shfl_up_sync(~0u, p, o);
                    if (lane >= o) p += t;
                }
                float cum = p + carry1;
                carry1 = __shfl_sync(~0u, cum, 31);
                if (vld) {
                    float rem = 1.0f - cum;
                    float tt = fmaxf(rem * (float)(i1r - j), 0.f);
                    float eff = fmaxf(__expf(gm * sqrt_approx(tt)), 1e-5f);
                    float s2 = sv * eff;
                    row1[j] = s2;
                    osm(s2, n1, t1);
                }
            }
        }
        #pragma unroll
        for (int o = 16; o; o >>= 1) {
            float om = __shfl_xor_sync(~0u, n0, o), os = __shfl_xor_sync(~0u, t0, o);
            osm_merge(om, os, n0, t0);
            om = __shfl_xor_sync(~0u, n1, o); os = __shfl_xor_sync(~0u, t1, o);
            osm_merge(om, os, n1, t1);
        }
        // maxout: max(attn) = 1/sum2 exactly => scale = min(sum2,5)/sum2
        const float sf0 = (nv0 > 0) ? fminf(t0, 5.f) / t0 : 0.f;
        const float sf1 = fminf(t1, 5.f) / t1;

        // Pass C: finalize attn values, zero-fill the causal tail.
        for (int j = lane; j < kLimit; j += 32) {
            float o0 = (j < nv0) ? __expf(row0[j] - n0) * sf0 : 0.f;
            float o1 = (j < nv1) ? __expf(row1[j] - n1) * sf1 : 0.f;
            row0[j] = o0;
            row1[j] = o1;
        }
    }
    __syncthreads();

    // ---- Phase 3: out = attn @ V. 4 column groups (16 cols) x 2 kt halves.
    {
        const int cg = w & 3;          // cols [cg*16, cg*16+16)
        const int half = w >> 2;       // kt parity
        float oacc[2][4] = {};
        for (int kt = half; kt < nkt; kt += 2) {
            const float* vp = vb + (size_t)kt * TR * kDH;
            #pragma unroll
            for (int kk = 0; kk < 2; kk++) {
                uint32_t af[4];
                const float* q = sc + gid * SCP + kt * TR + kk * 8 + l4;
                af[0] = f2tf(q[0]);
                af[1] = f2tf(q[8 * SCP]);
                af[2] = f2tf(q[4]);
                af[3] = f2tf(q[8 * SCP + 4]);
                #pragma unroll
                for (int nt = 0; nt < 2; nt++) {
                    uint32_t bf[2];
                    const float* p = vp + (size_t)(kk * 8 + l4) * kDH + cg * 16 + nt * 8 + gid;
                    bf[0] = f2tf(p[0]);
                    bf[1] = f2tf(p[4 * kDH]);
                    mma8(oacc[nt], af, bf);
                }
            }
        }
        if (half == 1) {
            #pragma unroll
            for (int nt = 0; nt < 2; nt++) {
                int cc = cg * 16 + nt * 8 + l4 * 2;
                *(float2*)&red[gid * kDH + cc] = make_float2(oacc[nt][0], oacc[nt][1]);
                *(float2*)&red[(gid + 8) * kDH + cc] = make_float2(oacc[nt][2], oacc[nt][3]);
            }
        }
        __syncthreads();
        if (half == 0) {
            const int i0 = base + gid;
            float* op0 = g_ao + ((size_t)b * kS + i0) * kD + h * kDH;
            #pragma unroll
            for (int nt = 0; nt < 2; nt++) {
                int cc = cg * 16 + nt * 8 + l4 * 2;
                float2 p0 = *(const float2*)&red[gid * kDH + cc];
                float2 p1 = *(const float2*)&red[(gid + 8) * kDH + cc];
                *(float2*)(op0 + cc) =
                    make_float2(oacc[nt][0] + p0.x, oacc[nt][1] + p0.y);
                *(float2*)(op0 + 8 * kD + cc) =
                    make_float2(oacc[nt][2] + p1.x, oacc[nt][3] + p1.y);
            }
        }
    }
}

// ---------------------------------------------------------------------------
template<bool ADD>
__global__ void __launch_bounds__(256) ln_k(const float* __restrict__ X,
                                            const float* __restrict__ Aadd,
                                            const float* __restrict__ g,
                                            const float* __restrict__ bt,
                                            float* __restrict__ out) {
    __shared__ float red[8];
    const int row = blockIdx.x;
    const int tid = threadIdx.x;
    const int lane = tid & 31, w = tid >> 5;
    const float* xr = X + (size_t)row * kD;
    float v[4];
    float s = 0.f;
    #pragma unroll
    for (int t = 0; t < 4; t++) {
        int d = tid + t * 256;
        float val = xr[d];
        if (ADD) val += Aadd[(size_t)row * kD + d];
        v[t] = val;
        s += val;
    }
    #pragma unroll
    for (int o = 16; o; o >>= 1) s += __shfl_xor_sync(~0u, s, o);
    if (lane == 0) red[w] = s;
    __syncthreads();
    float tot = 0.f;
    #pragma unroll
    for (int k = 0; k < 8; k++) tot += red[k];
    const float mu = tot * (1.0f / kD);
    __syncthreads();
    float s2 = 0.f;
    #pragma unroll
    for (int t = 0; t < 4; t++) { float dv = v[t] - mu; s2 += dv * dv; }
    #pragma unroll
    for (int o = 16; o; o >>= 1) s2 += __shfl_xor_sync(~0u, s2, o);
    if (lane == 0) red[w] = s2;
    __syncthreads();
    float tot2 = 0.f;
    #pragma unroll
    for (int k = 0; k < 8; k++) tot2 += red[k];
    const float rs = rsqrtf(tot2 * (1.0f / kD) + 1e-5f);
    #pragma unroll
    for (int t = 0; t < 4; t++) {
        int d = tid + t * 256;
        out[(size_t)row * kD + d] = (v[t] - mu) * rs * g[d] + bt[d];
    }
}

// ---------------------------------------------------------------------------
extern "C" void kernel_launch(void* const* d_in, const int* in_sizes, int n_in,
                              void* d_out, int out_size) {
    (void)in_sizes; (void)n_in; (void)out_size;
    const float* q   = (const float*)d_in[0];
    // d_in[1] = lens (unused in eval mode)
    const float* Wq  = (const float*)d_in[2];
    const float* bq  = (const float*)d_in[3];
    const float* Wv  = (const float*)d_in[4];
    const float* bv  = (const float*)d_in[5];
    const float* Wo  = (const float*)d_in[6];
    const float* bo  = (const float*)d_in[7];
    const float* gm  = (const float*)d_in[8];
    const float* lng = (const float*)d_in[9];
    const float* lnb = (const float*)d_in[10];
    const float* fg  = (const float*)d_in[11];
    const float* fb  = (const float*)d_in[12];
    float* out = (float*)d_out;

    cudaFuncSetAttribute(attn_k, cudaFuncAttributeMaxDynamicSharedMemorySize, ATTN_SMEM);
    cudaFuncSetAttribute(gemm_qv, cudaFuncAttributeMaxDynamicSharedMemorySize, GEMM_SMEM);
    cudaFuncSetAttribute(gemm_o,  cudaFuncAttributeMaxDynamicSharedMemorySize, GEMM_SMEM);

    void* p;
    float *xg, *qhg, *vhg, *aog, *pjg;
    cudaGetSymbolAddress(&p, g_x);    xg  = (float*)p;
    cudaGetSymbolAddress(&p, g_qh);   qhg = (float*)p;
    cudaGetSymbolAddress(&p, g_vh);   vhg = (float*)p;
    cudaGetSymbolAddress(&p, g_ao);   aog = (float*)p;
    cudaGetSymbolAddress(&p, g_proj); pjg = (float*)p;

    dim3 gqv(kD / BN, kBS / BM, 2);  // (16, 16, 2) = 512 CTAs
    dim3 ggo(kD / BN, kBS / BM);     // (16, 16) = 256 CTAs
    for (int l = 0; l < kL; l++) {
        const float* xin = (l == 0) ? q : xg;   // layer 0 reads input directly
        gemm_qv<<<gqv, 256, GEMM_SMEM>>>(xin,
            Wq + (size_t)l * kD * kD, bq + l * kD,
            Wv + (size_t)l * kD * kD, bv + l * kD, qhg, vhg);
        attn_k<<<kBH * NT16, ATTN_THREADS, ATTN_SMEM>>>(gm + l * kH);
        gemm_o<<<ggo, 256, GEMM_SMEM>>>(aog, Wo + (size_t)l * kD * kD, bo + l * kD, pjg);
        ln_k<true ><<<kBS, 256>>>(xin, pjg, lng + l * kD, lnb + l * kD, xg);
    }
    ln_k<false><<<kBS, 256>>>(xg, nullptr, fg, fb, out);
}

// round 10
// speedup vs baseline: 1.0756x; 1.0756x over previous
#include <cuda_runtime.h>
#include <math.h>
#include <stdint.h>

namespace {
constexpr int kBn = 2, kS = 1024, kD = 1024, kH = 16, kDH = 64, kL = 4;
constexpr int kBS = kBn * kS;          // 2048 rows
constexpr int kBH = kBn * kH;          // 32 (b,h) pairs
constexpr int TR = 16;                 // query rows per attention block
constexpr int NT16 = kS / TR;          // 64 tiles per (b,h)
constexpr int SCP = 1028;              // padded score-row stride (stride%32==4)
constexpr int ATTN_THREADS = 256;      // 8 warps
// smem: scores + phase3 reduction buffer + per-warp softmax stats
constexpr int ATTN_SMEM = (TR * SCP + TR * kDH + TR * 8 * 2) * 4;  // 70912 B
// GEMM tiling: 128x128 block, 8 warps of 32x64 (R8 proven config)
constexpr int BM = 128, BN = 128, BK = 32;
constexpr int ASTR = 36, BSTR = 136;   // padded smem strides
constexpr int GEMM_SMEM = (2 * BM * ASTR + 2 * BK * BSTR) * 4;  // 71680 B
}

// Scratch (static device allocations; no runtime allocs)
__device__ float g_x[kBS * kD];
__device__ float g_qh[kBH * kS * kDH];
__device__ float g_vh[kBH * kS * kDH];
__device__ float g_ao[kBS * kD];
__device__ float g_proj[kBS * kD];
__device__ float g_proj2[kBS * kD];    // split-K partial for gemm_o

// ---------------------------------------------------------------------------
__device__ __forceinline__ uint32_t f2tf(float x) {
    uint32_t r;
    asm("cvt.rna.tf32.f32 %0, %1;" : "=r"(r) : "f"(x));
    return r;
}
__device__ __forceinline__ float sqrt_approx(float x) {
    float r;
    asm("sqrt.approx.f32 %0, %1;" : "=f"(r) : "f"(x));
    return r;
}
__device__ __forceinline__ void mma8(float* d, const uint32_t* a, const uint32_t* b) {
    asm volatile(
        "mma.sync.aligned.m16n8k8.row.col.f32.tf32.tf32.f32 "
        "{%0,%1,%2,%3}, {%4,%5,%6,%7}, {%8,%9}, {%0,%1,%2,%3};\n"
        : "+f"(d[0]), "+f"(d[1]), "+f"(d[2]), "+f"(d[3])
        : "r"(a[0]), "r"(a[1]), "r"(a[2]), "r"(a[3]), "r"(b[0]), "r"(b[1]));
}
// online softmax accumulate
__device__ __forceinline__ void osm(float v, float& m, float& s) {
    if (v > m) { s = s * __expf(m - v) + 1.f; m = v; }
    else       s += __expf(v - m);
}
// merge two (m,s) online-softmax states
__device__ __forceinline__ void osm_merge(float om, float os, float& m, float& s) {
    float nm = fmaxf(m, om);
    s = s * __expf(m - nm) + os * __expf(om - nm);
    m = nm;
}

// ---------------------------------------------------------------------------
// Shared GEMM body: C[2048,1024] = A[:, kbase:kbase+nK*BK] @ W + (bias) .
// tf32 mma, cp.async double buffering. Block 128x128, 8 warps of 32x64.
template<bool SCATTER>
__device__ __forceinline__ void gemm_body(const float* __restrict__ A,
                                          const float* __restrict__ W,
                                          const float* __restrict__ bias,
                                          float* __restrict__ C,
                                          int bxx, int byy, int kbase, int nK,
                                          float* sm) {
    float* As = sm;
    float* Bs = sm + 2 * BM * ASTR;
    const int tid = threadIdx.x, lane = tid & 31, w = tid >> 5;
    const int gid = lane >> 2, l4 = lane & 3;
    const int warpM = w & 3, warpN = w >> 2;
    const int mbase = byy * BM, nbase = bxx * BN;
    const uint32_t sA = (uint32_t)__cvta_generic_to_shared(As);
    const uint32_t sB = (uint32_t)__cvta_generic_to_shared(Bs);

    auto prefetch = [&](int kt, int buf) {
        #pragma unroll
        for (int i = 0; i < 4; i++) {
            int cid = tid + i * 256;
            int m = cid >> 3, kc = cid & 7;
            uint32_t dst = sA + (uint32_t)((buf * BM * ASTR + m * ASTR + kc * 4) * 4);
            const float* src = A + (size_t)(mbase + m) * kD + kbase + kt * BK + kc * 4;
            asm volatile("cp.async.cg.shared.global [%0], [%1], 16;\n" ::"r"(dst), "l"(src));
        }
        #pragma unroll
        for (int i = 0; i < 4; i++) {
            int cid = tid + i * 256;
            int k = cid >> 5, nc = cid & 31;   // full 32 x 128 tile
            uint32_t dst = sB + (uint32_t)((buf * BK * BSTR + k * BSTR + nc * 4) * 4);
            const float* src = W + (size_t)(kbase + kt * BK + k) * kD + nbase + nc * 4;
            asm volatile("cp.async.cg.shared.global [%0], [%1], 16;\n" ::"r"(dst), "l"(src));
        }
        asm volatile("cp.async.commit_group;\n");
    };

    float acc[2][8][4] = {};
    prefetch(0, 0);
    for (int kt = 0; kt < nK; kt++) {
        asm volatile("cp.async.wait_group 0;\n");
        __syncthreads();
        if (kt + 1 < nK) prefetch(kt + 1, (kt + 1) & 1);
        const float* as = As + (kt & 1) * BM * ASTR;
        const float* bs = Bs + (kt & 1) * BK * BSTR;
        #pragma unroll
        for (int ks = 0; ks < 4; ks++) {
            uint32_t af[2][4];
            #pragma unroll
            for (int mt = 0; mt < 2; mt++) {
                int r = warpM * 32 + mt * 16 + gid;
                const float* p = as + r * ASTR + ks * 8 + l4;
                af[mt][0] = f2tf(p[0]);
                af[mt][1] = f2tf(p[8 * ASTR]);
                af[mt][2] = f2tf(p[4]);
                af[mt][3] = f2tf(p[8 * ASTR + 4]);
            }
            #pragma unroll
            for (int nt = 0; nt < 8; nt++) {
                uint32_t bf[2];
                int cn = warpN * 64 + nt * 8 + gid;
                const float* p = bs + (ks * 8 + l4) * BSTR + cn;
                bf[0] = f2tf(p[0]);
                bf[1] = f2tf(p[4 * BSTR]);
                #pragma unroll
                for (int mt = 0; mt < 2; mt++) mma8(acc[mt][nt], af[mt], bf);
            }
        }
        __syncthreads();
    }
    #pragma unroll
    for (int mt = 0; mt < 2; mt++) {
        int r0 = mbase + warpM * 32 + mt * 16 + gid;
        #pragma unroll
        for (int nt = 0; nt < 8; nt++) {
            int cc = nbase + warpN * 64 + nt * 8 + l4 * 2;
            float b0 = bias ? bias[cc] : 0.f;
            float b1 = bias ? bias[cc + 1] : 0.f;
            float2 u = make_float2(acc[mt][nt][0] + b0, acc[mt][nt][1] + b1);
            float2 v = make_float2(acc[mt][nt][2] + b0, acc[mt][nt][3] + b1);
            if (SCATTER) {
                int bb = r0 / kS, s = r0 - bb * kS;
                int h = cc >> 6, d = cc & 63;
                *(float2*)&C[(((size_t)bb * kH + h) * kS + s) * kDH + d] = u;
                *(float2*)&C[(((size_t)bb * kH + h) * kS + s + 8) * kDH + d] = v;
            } else {
                *(float2*)&C[(size_t)r0 * kD + cc] = u;
                *(float2*)&C[(size_t)(r0 + 8) * kD + cc] = v;
            }
        }
    }
}

// Fused Wq+Wv projections: blockIdx.z selects which GEMM. 256 CTAs.
__global__ void __launch_bounds__(256) gemm_qv(const float* __restrict__ A,
                                               const float* __restrict__ Wq,
                                               const float* __restrict__ bq,
                                               const float* __restrict__ Wv,
                                               const float* __restrict__ bv,
                                               float* __restrict__ Cq,
                                               float* __restrict__ Cv) {
    extern __shared__ float sm[];
    const float* W = blockIdx.z ? Wv : Wq;
    const float* bias = blockIdx.z ? bv : bq;
    float* C = blockIdx.z ? Cv : Cq;
    gemm_body<true>(A, W, bias, C, blockIdx.x, blockIdx.y, 0, kD / BK, sm);
}

// Wo projection, split-K=2 over blockIdx.z: 256 CTAs fill the chip.
// z=0 covers K[0:512) with bias -> C1; z=1 covers K[512:1024) -> C2.
__global__ void __launch_bounds__(256) gemm_o(const float* __restrict__ A,
                                              const float* __restrict__ W,
                                              const float* __restrict__ bias,
                                              float* __restrict__ C1,
                                              float* __restrict__ C2) {
    extern __shared__ float sm[];
    const int z = blockIdx.z;
    gemm_body<false>(A, W, z ? nullptr : bias, z ? C2 : C1,
                     blockIdx.x, blockIdx.y, z * (kD / 2), (kD / 2) / BK, sm);
}

// ---------------------------------------------------------------------------
// Gamma attention, 16 query rows per block, 8 warps, 3 CTAs/SM.
// Softmax-1 stats fused into phase 1; phase 3 split 4 col-groups x 2 halves.
__global__ void __launch_bounds__(ATTN_THREADS, 3) attn_k(const float* __restrict__ gam) {
    extern __shared__ float sc[];                 // [TR][SCP] score rows
    float* red = sc + TR * SCP;                   // [TR][64] phase-3 partials
    float* wstat = red + TR * kDH;                // [TR][8][2] per-warp (m,s)

    const int bx = blockIdx.x;
    const int bh = bx & (kBH - 1);
    const int tile = (NT16 - 1) - (bx >> 5);
    const int h = bh & (kH - 1);
    const int b = bh >> 4;
    const int base = tile * TR;
    const int tid = threadIdx.x, lane = tid & 31, w = tid >> 5;
    const int gid = lane >> 2, l4 = lane & 3;
    const float* qb = g_qh + (size_t)bh * kS * kDH;
    const float* vb = g_vh + (size_t)bh * kS * kDH;
    const int nkt = tile + 1, kLimit = nkt * TR;

    // ---- Phase 1: scores = QK^T / 8 with fused online softmax-1 stats.
    {
        uint32_t qa[8][4];
        #pragma unroll
        for (int ks = 0; ks < 8; ks++) {
            const float* p = qb + (size_t)(base + gid) * kDH + ks * 8 + l4;
            qa[ks][0] = f2tf(p[0]);
            qa[ks][1] = f2tf(p[8 * kDH]);
            qa[ks][2] = f2tf(p[4]);
            qa[ks][3] = f2tf(p[8 * kDH + 4]);
        }
        const int i0 = base + gid, i1 = base + gid + 8;  // this lane's rows
        float m0 = -3.4e38f, s0 = 0.f, m1 = -3.4e38f, s1 = 0.f;
        for (int kt = w; kt < nkt; kt += 8) {
            const float* kp = qb + (size_t)kt * TR * kDH;
            float acc[2][4] = {};
            #pragma unroll
            for (int ks = 0; ks < 8; ks++) {
                #pragma unroll
                for (int nt = 0; nt < 2; nt++) {
                    uint32_t bf[2];
                    const float* p = kp + (size_t)(nt * 8 + gid) * kDH + ks * 8 + l4;
                    bf[0] = f2tf(p[0]);
                    bf[1] = f2tf(p[4]);
                    mma8(acc[nt], qa[ks], bf);
                }
            }
            const bool diag = (kt == tile);
            #pragma unroll
            for (int nt = 0; nt < 2; nt++) {
                int c0 = kt * TR + nt * 8 + l4 * 2;
                float v00 = acc[nt][0] * 0.125f, v01 = acc[nt][1] * 0.125f;
                float v10 = acc[nt][2] * 0.125f, v11 = acc[nt][3] * 0.125f;
                *(float2*)&sc[gid * SCP + c0] = make_float2(v00, v01);
                *(float2*)&sc[(gid + 8) * SCP + c0] = make_float2(v10, v11);
                if (!diag) {            // all cols strictly below both rows
                    osm(v00, m0, s0); osm(v01, m0, s0);
                    osm(v10, m1, s1); osm(v11, m1, s1);
                } else {                // diagonal tile: mask j < i
                    if (c0 < i0)     osm(v00, m0, s0);
                    if (c0 + 1 < i0) osm(v01, m0, s0);
                    if (c0 < i1)     osm(v10, m1, s1);
                    if (c0 + 1 < i1) osm(v11, m1, s1);
                }
            }
        }
        // quad reduce (lanes sharing gid are l4 = 0..3)
        #pragma unroll
        for (int o = 1; o <= 2; o <<= 1) {
            float om = __shfl_xor_sync(~0u, m0, o), os = __shfl_xor_sync(~0u, s0, o);
            osm_merge(om, os, m0, s0);
            om = __shfl_xor_sync(~0u, m1, o); os = __shfl_xor_sync(~0u, s1, o);
            osm_merge(om, os, m1, s1);
        }
        if (l4 == 0) {
            wstat[(gid * 8 + w) * 2] = m0;
            wstat[(gid * 8 + w) * 2 + 1] = s0;
            wstat[((gid + 8) * 8 + w) * 2] = m1;
            wstat[((gid + 8) * 8 + w) * 2 + 1] = s1;
        }
    }
    __syncthreads();

    // ---- Phase 2: combine stats -> scan decay (online stats2) -> finalize.
    {
        const float gm = -fabsf(gam[h]);
        const int i0r = base + w;
        const int i1r = i0r + 8;
        float* row0 = sc + w * SCP;
        float* row1 = sc + (w + 8) * SCP;
        const int nv0 = i0r, nv1 = i1r;   // strict causal: keys j < i

        // combine the 8 per-warp partials for this warp's two rows
        float m0 = -3.4e38f, s0 = 0.f, m1 = -3.4e38f, s1 = 0.f;
        #pragma unroll
        for (int p = 0; p < 8; p++) {
            osm_merge(wstat[(w * 8 + p) * 2], wstat[(w * 8 + p) * 2 + 1], m0, s0);
            osm_merge(wstat[((w + 8) * 8 + p) * 2], wstat[((w + 8) * 8 + p) * 2 + 1], m1, s1);
        }
        const float inv0 = (nv0 > 0) ? 1.f / s0 : 0.f;
        const float inv1 = 1.f / s1;

        // Pass B: warp-scan cumsum of p, apply decay, store s2, online stats2.
        float carry0 = 0.f, carry1 = 0.f;
        float n0 = -3.4e38f, t0 = 0.f, n1 = -3.4e38f, t1 = 0.f;
        for (int c0 = 0; c0 < nv1; c0 += 32) {
            int j = c0 + lane;
            if (c0 < nv0) {
                bool vld = j < nv0;
                float sv = vld ? row0[j] : 0.f;
                float p = vld ? __expf(sv - m0) * inv0 : 0.f;
                #pragma unroll
                for (int o = 1; o < 32; o <<= 1) {
                    float t = __shfl_up_sync(~0u, p, o);
                    if (lane >= o) p += t;
                }
                float cum = p + carry0;
                carry0 = __shfl_sync(~0u, cum, 31);
                if (vld) {
                    float rem = 1.0f - cum;              // disttotal == 1
                    float tt = fmaxf(rem * (float)(i0r - j), 0.f);
                    float eff = fmaxf(__expf(gm * sqrt_approx(tt)), 1e-5f);
                    float s2 = sv * eff;
                    row0[j] = s2;
                    osm(s2, n0, t0);
                }
            }
            {
                bool vld = j < nv1;
                float sv = vld ? row1[j] : 0.f;
                float p = vld ? __expf(sv - m1) * inv1 : 0.f;
                #pragma unroll
                for (int o = 1; o < 32; o <<= 1) {
                    float t = __shfl_up_sync(~0u, p, o);
                    if (lane >= o) p += t;
                }
                float cum = p + carry1;
                carry1 = __shfl_sync(~0u, cum, 31);
                if (vld) {
                    float rem = 1.0f - cum;
                    float tt = fmaxf(rem * (float)(i1r - j), 0.f);
                    float eff = fmaxf(__expf(gm * sqrt_approx(tt)), 1e-5f);
                    float s2 = sv * eff;
                    row1[j] = s2;
                    osm(s2, n1, t1);
                }
            }
        }
        #pragma unroll
        for (int o = 16; o; o >>= 1) {
            float om = __shfl_xor_sync(~0u, n0, o), os = __shfl_xor_sync(~0u, t0, o);
            osm_merge(om, os, n0, t0);
            om = __shfl_xor_sync(~0u, n1, o); os = __shfl_xor_sync(~0u, t1, o);
            osm_merge(om, os, n1, t1);
        }
        // maxout: max(attn) = 1/sum2 exactly => scale = min(sum2,5)/sum2
        const float sf0 = (nv0 > 0) ? fminf(t0, 5.f) / t0 : 0.f;
        const float sf1 = fminf(t1, 5.f) / t1;

        // Pass C: finalize attn values, zero-fill the causal tail.
        for (int j = lane; j < kLimit; j += 32) {
            float o0 = (j < nv0) ? __expf(row0[j] - n0) * sf0 : 0.f;
            float o1 = (j < nv1) ? __expf(row1[j] - n1) * sf1 : 0.f;
            row0[j] = o0;
            row1[j] = o1;
        }
    }
    __syncthreads();

    // ---- Phase 3: out = attn @ V. 4 column groups (16 cols) x 2 kt halves.
    {
        const int cg = w & 3;          // cols [cg*16, cg*16+16)
        const int half = w >> 2;       // kt parity
        float oacc[2][4] = {};
        for (int kt = half; kt < nkt; kt += 2) {
            const float* vp = vb + (size_t)kt * TR * kDH;
            #pragma unroll
            for (int kk = 0; kk < 2; kk++) {
                uint32_t af[4];
                const float* q = sc + gid * SCP + kt * TR + kk * 8 + l4;
                af[0] = f2tf(q[0]);
                af[1] = f2tf(q[8 * SCP]);
                af[2] = f2tf(q[4]);
                af[3] = f2tf(q[8 * SCP + 4]);
                #pragma unroll
                for (int nt = 0; nt < 2; nt++) {
                    uint32_t bf[2];
                    const float* p = vp + (size_t)(kk * 8 + l4) * kDH + cg * 16 + nt * 8 + gid;
                    bf[0] = f2tf(p[0]);
                    bf[1] = f2tf(p[4 * kDH]);
                    mma8(oacc[nt], af, bf);
                }
            }
        }
        if (half == 1) {
            #pragma unroll
            for (int nt = 0; nt < 2; nt++) {
                int cc = cg * 16 + nt * 8 + l4 * 2;
                *(float2*)&red[gid * kDH + cc] = make_float2(oacc[nt][0], oacc[nt][1]);
                *(float2*)&red[(gid + 8) * kDH + cc] = make_float2(oacc[nt][2], oacc[nt][3]);
            }
        }
        __syncthreads();
        if (half == 0) {
            const int i0 = base + gid;
            float* op0 = g_ao + ((size_t)b * kS + i0) * kD + h * kDH;
            #pragma unroll
            for (int nt = 0; nt < 2; nt++) {
                int cc = cg * 16 + nt * 8 + l4 * 2;
                float2 p0 = *(const float2*)&red[gid * kDH + cc];
                float2 p1 = *(const float2*)&red[(gid + 8) * kDH + cc];
                *(float2*)(op0 + cc) =
                    make_float2(oacc[nt][0] + p0.x, oacc[nt][1] + p0.y);
                *(float2*)(op0 + 8 * kD + cc) =
                    make_float2(oacc[nt][2] + p1.x, oacc[nt][3] + p1.y);
            }
        }
    }
}

// ---------------------------------------------------------------------------
// LayerNorm with NADD extra addends: out = LN(X (+A1) (+A2)) * g + b.
template<int NADD>
__global__ void __launch_bounds__(256) ln_k(const float* __restrict__ X,
                                            const float* __restrict__ A1,
                                            const float* __restrict__ A2,
                                            const float* __restrict__ g,
                                            const float* __restrict__ bt,
                                            float* __restrict__ out) {
    __shared__ float red[8];
    const int row = blockIdx.x;
    const int tid = threadIdx.x;
    const int lane = tid & 31, w = tid >> 5;
    const float* xr = X + (size_t)row * kD;
    float v[4];
    float s = 0.f;
    #pragma unroll
    for (int t = 0; t < 4; t++) {
        int d = tid + t * 256;
        float val = xr[d];
        if (NADD >= 1) val += A1[(size_t)row * kD + d];
        if (NADD >= 2) val += A2[(size_t)row * kD + d];
        v[t] = val;
        s += val;
    }
    #pragma unroll
    for (int o = 16; o; o >>= 1) s += __shfl_xor_sync(~0u, s, o);
    if (lane == 0) red[w] = s;
    __syncthreads();
    float tot = 0.f;
    #pragma unroll
    for (int k = 0; k < 8; k++) tot += red[k];
    const float mu = tot * (1.0f / kD);
    __syncthreads();
    float s2 = 0.f;
    #pragma unroll
    for (int t = 0; t < 4; t++) { float dv = v[t] - mu; s2 += dv * dv; }
    #pragma unroll
    for (int o = 16; o; o >>= 1) s2 += __shfl_xor_sync(~0u, s2, o);
    if (lane == 0) red[w] = s2;
    __syncthreads();
    float tot2 = 0.f;
    #pragma unroll
    for (int k = 0; k < 8; k++) tot2 += red[k];
    const float rs = rsqrtf(tot2 * (1.0f / kD) + 1e-5f);
    #pragma unroll
    for (int t = 0; t < 4; t++) {
        int d = tid + t * 256;
        out[(size_t)row * kD + d] = (v[t] - mu) * rs * g[d] + bt[d];
    }
}

// ---------------------------------------------------------------------------
extern "C" void kernel_launch(void* const* d_in, const int* in_sizes, int n_in,
                              void* d_out, int out_size) {
    (void)in_sizes; (void)n_in; (void)out_size;
    const float* q   = (const float*)d_in[0];
    // d_in[1] = lens (unused in eval mode)
    const float* Wq  = (const float*)d_in[2];
    const float* bq  = (const float*)d_in[3];
    const float* Wv  = (const float*)d_in[4];
    const float* bv  = (const float*)d_in[5];
    const float* Wo  = (const float*)d_in[6];
    const float* bo  = (const float*)d_in[7];
    const float* gm  = (const float*)d_in[8];
    const float* lng = (const float*)d_in[9];
    const float* lnb = (const float*)d_in[10];
    const float* fg  = (const float*)d_in[11];
    const float* fb  = (const float*)d_in[12];
    float* out = (float*)d_out;

    cudaFuncSetAttribute(attn_k, cudaFuncAttributeMaxDynamicSharedMemorySize, ATTN_SMEM);
    cudaFuncSetAttribute(gemm_qv, cudaFuncAttributeMaxDynamicSharedMemorySize, GEMM_SMEM);
    cudaFuncSetAttribute(gemm_o,  cudaFuncAttributeMaxDynamicSharedMemorySize, GEMM_SMEM);

    void* p;
    float *xg, *qhg, *vhg, *aog, *pjg, *pjg2;
    cudaGetSymbolAddress(&p, g_x);     xg   = (float*)p;
    cudaGetSymbolAddress(&p, g_qh);    qhg  = (float*)p;
    cudaGetSymbolAddress(&p, g_vh);    vhg  = (float*)p;
    cudaGetSymbolAddress(&p, g_ao);    aog  = (float*)p;
    cudaGetSymbolAddress(&p, g_proj);  pjg  = (float*)p;
    cudaGetSymbolAddress(&p, g_proj2); pjg2 = (float*)p;

    dim3 gqv(kD / BN, kBS / BM, 2);  // (8, 16, 2) = 256 CTAs
    dim3 ggo(kD / BN, kBS / BM, 2);  // (8, 16, 2) = 256 CTAs (split-K)
    for (int l = 0; l < kL; l++) {
        const float* xin = (l == 0) ? q : xg;   // layer 0 reads input directly
        gemm_qv<<<gqv, 256, GEMM_SMEM>>>(xin,
            Wq + (size_t)l * kD * kD, bq + l * kD,
            Wv + (size_t)l * kD * kD, bv + l * kD, qhg, vhg);
        attn_k<<<kBH * NT16, ATTN_THREADS, ATTN_SMEM>>>(gm + l * kH);
        gemm_o<<<ggo, 256, GEMM_SMEM>>>(aog, Wo + (size_t)l * kD * kD, bo + l * kD,
                                        pjg, pjg2);
        ln_k<2><<<kBS, 256>>>(xin, pjg, pjg2, lng + l * kD, lnb + l * kD, xg);
    }
    ln_k<0><<<kBS, 256>>>(xg, nullptr, nullptr, fg, fb, out);
}

// round 11
// speedup vs baseline: 1.0817x; 1.0057x over previous
#include <cuda_runtime.h>
#include <math.h>
#include <stdint.h>

namespace {
constexpr int kBn = 2, kS = 1024, kD = 1024, kH = 16, kDH = 64, kL = 4;
constexpr int kBS = kBn * kS;          // 2048 rows
constexpr int kBH = kBn * kH;          // 32 (b,h) pairs
constexpr int TR = 16;                 // query rows per attention block
constexpr int NT16 = kS / TR;          // 64 tiles per (b,h)
constexpr int SCP = 1028;              // padded score-row stride (stride%32==4)
constexpr int ATTN_THREADS = 256;      // 8 warps
// smem: scores + phase3 reduction buffer + per-warp softmax stats
constexpr int ATTN_SMEM = (TR * SCP + TR * kDH + TR * 8 * 2) * 4;  // 70912 B
// GEMM tiling: 128x128 block, 8 warps of 32x64
constexpr int BM = 128, BN = 128, BK = 32;
constexpr int ASTR = 36, BSTR = 136;   // padded smem strides
constexpr int GEMM_SMEM = (2 * BM * ASTR + 2 * BK * BSTR) * 4;  // 71680 B
}

// Scratch (static device allocations; no runtime allocs)
__device__ float g_x[kBS * kD];
__device__ float g_qh[kBH * kS * kDH];   // tf32-pre-rounded q heads (also keys)
__device__ float g_vh[kBH * kS * kDH];   // tf32-pre-rounded v heads
__device__ float g_ao[kBS * kD];
__device__ float g_proj[kBS * kD];
__device__ float g_proj2[kBS * kD];      // split-K partial for gemm_o

// ---------------------------------------------------------------------------
__device__ __forceinline__ uint32_t f2tf(float x) {
    uint32_t r;
    asm("cvt.rna.tf32.f32 %0, %1;" : "=r"(r) : "f"(x));
    return r;
}
__device__ __forceinline__ float sqrt_approx(float x) {
    float r;
    asm("sqrt.approx.f32 %0, %1;" : "=f"(r) : "f"(x));
    return r;
}
__device__ __forceinline__ void mma8(float* d, const uint32_t* a, const uint32_t* b) {
    asm volatile(
        "mma.sync.aligned.m16n8k8.row.col.f32.tf32.tf32.f32 "
        "{%0,%1,%2,%3}, {%4,%5,%6,%7}, {%8,%9}, {%0,%1,%2,%3};\n"
        : "+f"(d[0]), "+f"(d[1]), "+f"(d[2]), "+f"(d[3])
        : "r"(a[0]), "r"(a[1]), "r"(a[2]), "r"(a[3]), "r"(b[0]), "r"(b[1]));
}
// online softmax accumulate
__device__ __forceinline__ void osm(float v, float& m, float& s) {
    if (v > m) { s = s * __expf(m - v) + 1.f; m = v; }
    else       s += __expf(v - m);
}
// merge two (m,s) online-softmax states
__device__ __forceinline__ void osm_merge(float om, float os, float& m, float& s) {
    float nm = fmaxf(m, om);
    s = s * __expf(m - nm) + os * __expf(om - nm);
    m = nm;
}

// ---------------------------------------------------------------------------
// Shared GEMM body: C[2048,1024] = A[:, kbase:kbase+nK*BK] @ W + (bias).
// tf32 mma, cp.async double buffering. Block 128x128, 8 warps of 32x64.
// SCATTER path additionally pre-rounds outputs to tf32 (consumed only as
// mma operands in attn_k; cvt is idempotent so numerics are unchanged).
template<bool SCATTER>
__device__ __forceinline__ void gemm_body(const float* __restrict__ A,
                                          const float* __restrict__ W,
                                          const float* __restrict__ bias,
                                          float* __restrict__ C,
                                          int bxx, int byy, int kbase, int nK,
                                          float* sm) {
    float* As = sm;
    float* Bs = sm + 2 * BM * ASTR;
    const int tid = threadIdx.x, lane = tid & 31, w = tid >> 5;
    const int gid = lane >> 2, l4 = lane & 3;
    const int warpM = w & 3, warpN = w >> 2;
    const int mbase = byy * BM, nbase = bxx * BN;
    const uint32_t sA = (uint32_t)__cvta_generic_to_shared(As);
    const uint32_t sB = (uint32_t)__cvta_generic_to_shared(Bs);

    auto prefetch = [&](int kt, int buf) {
        #pragma unroll
        for (int i = 0; i < 4; i++) {
            int cid = tid + i * 256;
            int m = cid >> 3, kc = cid & 7;
            uint32_t dst = sA + (uint32_t)((buf * BM * ASTR + m * ASTR + kc * 4) * 4);
            const float* src = A + (size_t)(mbase + m) * kD + kbase + kt * BK + kc * 4;
            asm volatile("cp.async.cg.shared.global [%0], [%1], 16;\n" ::"r"(dst), "l"(src));
        }
        #pragma unroll
        for (int i = 0; i < 4; i++) {
            int cid = tid + i * 256;
            int k = cid >> 5, nc = cid & 31;   // full 32 x 128 tile
            uint32_t dst = sB + (uint32_t)((buf * BK * BSTR + k * BSTR + nc * 4) * 4);
            const float* src = W + (size_t)(kbase + kt * BK + k) * kD + nbase + nc * 4;
            asm volatile("cp.async.cg.shared.global [%0], [%1], 16;\n" ::"r"(dst), "l"(src));
        }
        asm volatile("cp.async.commit_group;\n");
    };

    float acc[2][8][4] = {};
    prefetch(0, 0);
    for (int kt = 0; kt < nK; kt++) {
        asm volatile("cp.async.wait_group 0;\n");
        __syncthreads();
        if (kt + 1 < nK) prefetch(kt + 1, (kt + 1) & 1);
        const float* as = As + (kt & 1) * BM * ASTR;
        const float* bs = Bs + (kt & 1) * BK * BSTR;
        #pragma unroll
        for (int ks = 0; ks < 4; ks++) {
            uint32_t af[2][4];
            #pragma unroll
            for (int mt = 0; mt < 2; mt++) {
                int r = warpM * 32 + mt * 16 + gid;
                const float* p = as + r * ASTR + ks * 8 + l4;
                af[mt][0] = f2tf(p[0]);
                af[mt][1] = f2tf(p[8 * ASTR]);
                af[mt][2] = f2tf(p[4]);
                af[mt][3] = f2tf(p[8 * ASTR + 4]);
            }
            #pragma unroll
            for (int nt = 0; nt < 8; nt++) {
                uint32_t bf[2];
                int cn = warpN * 64 + nt * 8 + gid;
                const float* p = bs + (ks * 8 + l4) * BSTR + cn;
                bf[0] = f2tf(p[0]);
                bf[1] = f2tf(p[4 * BSTR]);
                #pragma unroll
                for (int mt = 0; mt < 2; mt++) mma8(acc[mt][nt], af[mt], bf);
            }
        }
        __syncthreads();
    }
    #pragma unroll
    for (int mt = 0; mt < 2; mt++) {
        int r0 = mbase + warpM * 32 + mt * 16 + gid;
        #pragma unroll
        for (int nt = 0; nt < 8; nt++) {
            int cc = nbase + warpN * 64 + nt * 8 + l4 * 2;
            float b0 = bias ? bias[cc] : 0.f;
            float b1 = bias ? bias[cc + 1] : 0.f;
            float2 u = make_float2(acc[mt][nt][0] + b0, acc[mt][nt][1] + b1);
            float2 v = make_float2(acc[mt][nt][2] + b0, acc[mt][nt][3] + b1);
            if (SCATTER) {
                // pre-round to tf32 so attn_k can feed mma without cvt
                u.x = __uint_as_float(f2tf(u.x));
                u.y = __uint_as_float(f2tf(u.y));
                v.x = __uint_as_float(f2tf(v.x));
                v.y = __uint_as_float(f2tf(v.y));
                int bb = r0 / kS, s = r0 - bb * kS;
                int h = cc >> 6, d = cc & 63;
                *(float2*)&C[(((size_t)bb * kH + h) * kS + s) * kDH + d] = u;
                *(float2*)&C[(((size_t)bb * kH + h) * kS + s + 8) * kDH + d] = v;
            } else {
                *(float2*)&C[(size_t)r0 * kD + cc] = u;
                *(float2*)&C[(size_t)(r0 + 8) * kD + cc] = v;
            }
        }
    }
}

// Fused Wq+Wv projections: blockIdx.z selects which GEMM. 256 CTAs.
__global__ void __launch_bounds__(256) gemm_qv(const float* __restrict__ A,
                                               const float* __restrict__ Wq,
                                               const float* __restrict__ bq,
                                               const float* __restrict__ Wv,
                                               const float* __restrict__ bv,
                                               float* __restrict__ Cq,
                                               float* __restrict__ Cv) {
    extern __shared__ float sm[];
    const float* W = blockIdx.z ? Wv : Wq;
    const float* bias = blockIdx.z ? bv : bq;
    float* C = blockIdx.z ? Cv : Cq;
    gemm_body<true>(A, W, bias, C, blockIdx.x, blockIdx.y, 0, kD / BK, sm);
}

// Wo projection, split-K=2 over blockIdx.z: 256 CTAs fill the chip.
__global__ void __launch_bounds__(256) gemm_o(const float* __restrict__ A,
                                              const float* __restrict__ W,
                                              const float* __restrict__ bias,
                                              float* __restrict__ C1,
                                              float* __restrict__ C2) {
    extern __shared__ float sm[];
    const int z = blockIdx.z;
    gemm_body<false>(A, W, z ? nullptr : bias, z ? C2 : C1,
                     blockIdx.x, blockIdx.y, z * (kD / 2), (kD / 2) / BK, sm);
}

// ---------------------------------------------------------------------------
// Gamma attention, 16 query rows per block, 8 warps, 3 CTAs/SM.
// q/v arrive pre-rounded to tf32: operand loads feed mma directly (no cvt).
__global__ void __launch_bounds__(ATTN_THREADS, 3) attn_k(const float* __restrict__ gam) {
    extern __shared__ float sc[];                 // [TR][SCP] score rows
    float* red = sc + TR * SCP;                   // [TR][64] phase-3 partials
    float* wstat = red + TR * kDH;                // [TR][8][2] per-warp (m,s)

    const int bx = blockIdx.x;
    const int bh = bx & (kBH - 1);
    const int tile = (NT16 - 1) - (bx >> 5);
    const int h = bh & (kH - 1);
    const int b = bh >> 4;
    const int base = tile * TR;
    const int tid = threadIdx.x, lane = tid & 31, w = tid >> 5;
    const int gid = lane >> 2, l4 = lane & 3;
    const float* qb = g_qh + (size_t)bh * kS * kDH;
    const float* vb = g_vh + (size_t)bh * kS * kDH;
    const int nkt = tile + 1, kLimit = nkt * TR;

    // ---- Phase 1: scores = QK^T / 8 with fused online softmax-1 stats.
    {
        uint32_t qa[8][4];
        #pragma unroll
        for (int ks = 0; ks < 8; ks++) {
            const uint32_t* p = (const uint32_t*)(qb + (size_t)(base + gid) * kDH + ks * 8 + l4);
            qa[ks][0] = p[0];
            qa[ks][1] = p[8 * kDH];
            qa[ks][2] = p[4];
            qa[ks][3] = p[8 * kDH + 4];
        }
        const int i0 = base + gid, i1 = base + gid + 8;  // this lane's rows
        float m0 = -3.4e38f, s0 = 0.f, m1 = -3.4e38f, s1 = 0.f;
        for (int kt = w; kt < nkt; kt += 8) {
            const float* kp = qb + (size_t)kt * TR * kDH;
            float acc[2][4] = {};
            #pragma unroll
            for (int ks = 0; ks < 8; ks++) {
                #pragma unroll
                for (int nt = 0; nt < 2; nt++) {
                    uint32_t bf[2];
                    const uint32_t* p = (const uint32_t*)(kp + (size_t)(nt * 8 + gid) * kDH + ks * 8 + l4);
                    bf[0] = p[0];
                    bf[1] = p[4];
                    mma8(acc[nt], qa[ks], bf);
                }
            }
            const bool diag = (kt == tile);
            #pragma unroll
            for (int nt = 0; nt < 2; nt++) {
                int c0 = kt * TR + nt * 8 + l4 * 2;
                float v00 = acc[nt][0] * 0.125f, v01 = acc[nt][1] * 0.125f;
                float v10 = acc[nt][2] * 0.125f, v11 = acc[nt][3] * 0.125f;
                *(float2*)&sc[gid * SCP + c0] = make_float2(v00, v01);
                *(float2*)&sc[(gid + 8) * SCP + c0] = make_float2(v10, v11);
                if (!diag) {            // all cols strictly below both rows
                    osm(v00, m0, s0); osm(v01, m0, s0);
                    osm(v10, m1, s1); osm(v11, m1, s1);
                } else {                // diagonal tile: mask j < i
                    if (c0 < i0)     osm(v00, m0, s0);
                    if (c0 + 1 < i0) osm(v01, m0, s0);
                    if (c0 < i1)     osm(v10, m1, s1);
                    if (c0 + 1 < i1) osm(v11, m1, s1);
                }
            }
        }
        // quad reduce (lanes sharing gid are l4 = 0..3)
        #pragma unroll
        for (int o = 1; o <= 2; o <<= 1) {
            float om = __shfl_xor_sync(~0u, m0, o), os = __shfl_xor_sync(~0u, s0, o);
            osm_merge(om, os, m0, s0);
            om = __shfl_xor_sync(~0u, m1, o); os = __shfl_xor_sync(~0u, s1, o);
            osm_merge(om, os, m1, s1);
        }
        if (l4 == 0) {
            wstat[(gid * 8 + w) * 2] = m0;
            wstat[(gid * 8 + w) * 2 + 1] = s0;
            wstat[((gid + 8) * 8 + w) * 2] = m1;
            wstat[((gid + 8) * 8 + w) * 2 + 1] = s1;
        }
    }
    __syncthreads();

    // ---- Phase 2: combine stats -> scan decay (online stats2) -> finalize.
    {
        const float gm = -fabsf(gam[h]);
        const int i0r = base + w;
        const int i1r = i0r + 8;
        float* row0 = sc + w * SCP;
        float* row1 = sc + (w + 8) * SCP;
        const int nv0 = i0r, nv1 = i1r;   // strict causal: keys j < i

        // combine the 8 per-warp partials for this warp's two rows
        float m0 = -3.4e38f, s0 = 0.f, m1 = -3.4e38f, s1 = 0.f;
        #pragma unroll
        for (int p = 0; p < 8; p++) {
            osm_merge(wstat[(w * 8 + p) * 2], wstat[(w * 8 + p) * 2 + 1], m0, s0);
            osm_merge(wstat[((w + 8) * 8 + p) * 2], wstat[((w + 8) * 8 + p) * 2 + 1], m1, s1);
        }
        const float inv0 = (nv0 > 0) ? 1.f / s0 : 0.f;
        const float inv1 = 1.f / s1;

        // Pass B: warp-scan cumsum of p, apply decay, store s2, online stats2.
        float carry0 = 0.f, carry1 = 0.f;
        float n0 = -3.4e38f, t0 = 0.f, n1 = -3.4e38f, t1 = 0.f;
        for (int c0 = 0; c0 < nv1; c0 += 32) {
            int j = c0 + lane;
            if (c0 < nv0) {
                bool vld = j < nv0;
                float sv = vld ? row0[j] : 0.f;
                float p = vld ? __expf(sv - m0) * inv0 : 0.f;
                #pragma unroll
                for (int o = 1; o < 32; o <<= 1) {
                    float t = __shfl_up_sync(~0u, p, o);
                    if (lane >= o) p += t;
                }
                float cum = p + carry0;
                carry0 = __shfl_sync(~0u, cum, 31);
                if (vld) {
                    float rem = 1.0f - cum;              // disttotal == 1
                    float tt = fmaxf(rem * (float)(i0r - j), 0.f);
                    float eff = fmaxf(__expf(gm * sqrt_approx(tt)), 1e-5f);
                    float s2 = sv * eff;
                    row0[j] = s2;
                    osm(s2, n0, t0);
                }
            }
            {
                bool vld = j < nv1;
                float sv = vld ? row1[j] : 0.f;
                float p = vld ? __expf(sv - m1) * inv1 : 0.f;
                #pragma unroll
                for (int o = 1; o < 32; o <<= 1) {
                    float t = __shfl_up_sync(~0u, p, o);
                    if (lane >= o) p += t;
                }
                float cum = p + carry1;
                carry1 = __shfl_sync(~0u, cum, 31);
                if (vld) {
                    float rem = 1.0f - cum;
                    float tt = fmaxf(rem * (float)(i1r - j), 0.f);
                    float eff = fmaxf(__expf(gm * sqrt_approx(tt)), 1e-5f);
                    float s2 = sv * eff;
                    row1[j] = s2;
                    osm(s2, n1, t1);
                }
            }
        }
        #pragma unroll
        for (int o = 16; o; o >>= 1) {
            float om = __shfl_xor_sync(~0u, n0, o), os = __shfl_xor_sync(~0u, t0, o);
            osm_merge(om, os, n0, t0);
            om = __shfl_xor_sync(~0u, n1, o); os = __shfl_xor_sync(~0u, t1, o);
            osm_merge(om, os, n1, t1);
        }
        // maxout: max(attn) = 1/sum2 exactly => scale = min(sum2,5)/sum2
        const float sf0 = (nv0 > 0) ? fminf(t0, 5.f) / t0 : 0.f;
        const float sf1 = fminf(t1, 5.f) / t1;

        // Pass C: finalize attn values as tf32 bits, zero-fill causal tail.
        for (int j = lane; j < kLimit; j += 32) {
            float o0 = (j < nv0) ? __uint_as_float(f2tf(__expf(row0[j] - n0) * sf0)) : 0.f;
            float o1 = (j < nv1) ? __uint_as_float(f2tf(__expf(row1[j] - n1) * sf1)) : 0.f;
            row0[j] = o0;
            row1[j] = o1;
        }
    }
    __syncthreads();

    // ---- Phase 3: out = attn @ V. 4 column groups (16 cols) x 2 kt halves.
    // attn (smem) and V (global) are already tf32 bit patterns -> no cvt.
    {
        const int cg = w & 3;          // cols [cg*16, cg*16+16)
        const int half = w >> 2;       // kt parity
        float oacc[2][4] = {};
        for (int kt = half; kt < nkt; kt += 2) {
            const float* vp = vb + (size_t)kt * TR * kDH;
            #pragma unroll
            for (int kk = 0; kk < 2; kk++) {
                uint32_t af[4];
                const uint32_t* q = (const uint32_t*)(sc + gid * SCP + kt * TR + kk * 8 + l4);
                af[0] = q[0];
                af[1] = q[8 * SCP];
                af[2] = q[4];
                af[3] = q[8 * SCP + 4];
                #pragma unroll
                for (int nt = 0; nt < 2; nt++) {
                    uint32_t bf[2];
                    const uint32_t* p = (const uint32_t*)(vp + (size_t)(kk * 8 + l4) * kDH + cg * 16 + nt * 8 + gid);
                    bf[0] = p[0];
                    bf[1] = p[4 * kDH];
                    mma8(oacc[nt], af, bf);
                }
            }
        }
        if (half == 1) {
            #pragma unroll
            for (int nt = 0; nt < 2; nt++) {
                int cc = cg * 16 + nt * 8 + l4 * 2;
                *(float2*)&red[gid * kDH + cc] = make_float2(oacc[nt][0], oacc[nt][1]);
                *(float2*)&red[(gid + 8) * kDH + cc] = make_float2(oacc[nt][2], oacc[nt][3]);
            }
        }
        __syncthreads();
        if (half == 0) {
            const int i0 = base + gid;
            float* op0 = g_ao + ((size_t)b * kS + i0) * kD + h * kDH;
            #pragma unroll
            for (int nt = 0; nt < 2; nt++) {
                int cc = cg * 16 + nt * 8 + l4 * 2;
                float2 p0 = *(const float2*)&red[gid * kDH + cc];
                float2 p1 = *(const float2*)&red[(gid + 8) * kDH + cc];
                *(float2*)(op0 + cc) =
                    make_float2(oacc[nt][0] + p0.x, oacc[nt][1] + p0.y);
                *(float2*)(op0 + 8 * kD + cc) =
                    make_float2(oacc[nt][2] + p1.x, oacc[nt][3] + p1.y);
            }
        }
    }
}

// ---------------------------------------------------------------------------
// LayerNorm with NADD extra addends: out = LN(X (+A1) (+A2)) * g + b.
template<int NADD>
__global__ void __launch_bounds__(256) ln_k(const float* __restrict__ X,
                                            const float* __restrict__ A1,
                                            const float* __restrict__ A2,
                                            const float* __restrict__ g,
                                            const float* __restrict__ bt,
                                            float* __restrict__ out) {
    __shared__ float red[8];
    const int row = blockIdx.x;
    const int tid = threadIdx.x;
    const int lane = tid & 31, w = tid >> 5;
    const float* xr = X + (size_t)row * kD;
    float v[4];
    float s = 0.f;
    #pragma unroll
    for (int t = 0; t < 4; t++) {
        int d = tid + t * 256;
        float val = xr[d];
        if (NADD >= 1) val += A1[(size_t)row * kD + d];
        if (NADD >= 2) val += A2[(size_t)row * kD + d];
        v[t] = val;
        s += val;
    }
    #pragma unroll
    for (int o = 16; o; o >>= 1) s += __shfl_xor_sync(~0u, s, o);
    if (lane == 0) red[w] = s;
    __syncthreads();
    float tot = 0.f;
    #pragma unroll
    for (int k = 0; k < 8; k++) tot += red[k];
    const float mu = tot * (1.0f / kD);
    __syncthreads();
    float s2 = 0.f;
    #pragma unroll
    for (int t = 0; t < 4; t++) { float dv = v[t] - mu; s2 += dv * dv; }
    #pragma unroll
    for (int o = 16; o; o >>= 1) s2 += __shfl_xor_sync(~0u, s2, o);
    if (lane == 0) red[w] = s2;
    __syncthreads();
    float tot2 = 0.f;
    #pragma unroll
    for (int k = 0; k < 8; k++) tot2 += red[k];
    const float rs = rsqrtf(tot2 * (1.0f / kD) + 1e-5f);
    #pragma unroll
    for (int t = 0; t < 4; t++) {
        int d = tid + t * 256;
        out[(size_t)row * kD + d] = (v[t] - mu) * rs * g[d] + bt[d];
    }
}

// ---------------------------------------------------------------------------
extern "C" void kernel_launch(void* const* d_in, const int* in_sizes, int n_in,
                              void* d_out, int out_size) {
    (void)in_sizes; (void)n_in; (void)out_size;
    const float* q   = (const float*)d_in[0];
    // d_in[1] = lens (unused in eval mode)
    const float* Wq  = (const float*)d_in[2];
    const float* bq  = (const float*)d_in[3];
    const float* Wv  = (const float*)d_in[4];
    const float* bv  = (const float*)d_in[5];
    const float* Wo  = (const float*)d_in[6];
    const float* bo  = (const float*)d_in[7];
    const float* gm  = (const float*)d_in[8];
    const float* lng = (const float*)d_in[9];
    const float* lnb = (const float*)d_in[10];
    const float* fg  = (const float*)d_in[11];
    const float* fb  = (const float*)d_in[12];
    float* out = (float*)d_out;

    cudaFuncSetAttribute(attn_k, cudaFuncAttributeMaxDynamicSharedMemorySize, ATTN_SMEM);
    cudaFuncSetAttribute(gemm_qv, cudaFuncAttributeMaxDynamicSharedMemorySize, GEMM_SMEM);
    cudaFuncSetAttribute(gemm_o,  cudaFuncAttributeMaxDynamicSharedMemorySize, GEMM_SMEM);

    void* p;
    float *xg, *qhg, *vhg, *aog, *pjg, *pjg2;
    cudaGetSymbolAddress(&p, g_x);     xg   = (float*)p;
    cudaGetSymbolAddress(&p, g_qh);    qhg  = (float*)p;
    cudaGetSymbolAddress(&p, g_vh);    vhg  = (float*)p;
    cudaGetSymbolAddress(&p, g_ao);    aog  = (float*)p;
    cudaGetSymbolAddress(&p, g_proj);  pjg  = (float*)p;
    cudaGetSymbolAddress(&p, g_proj2); pjg2 = (float*)p;

    dim3 gqv(kD / BN, kBS / BM, 2);  // (8, 16, 2) = 256 CTAs
    dim3 ggo(kD / BN, kBS / BM, 2);  // (8, 16, 2) = 256 CTAs (split-K)
    for (int l = 0; l < kL; l++) {
        const float* xin = (l == 0) ? q : xg;   // layer 0 reads input directly
        gemm_qv<<<gqv, 256, GEMM_SMEM>>>(xin,
            Wq + (size_t)l * kD * kD, bq + l * kD,
            Wv + (size_t)l * kD * kD, bv + l * kD, qhg, vhg);
        attn_k<<<kBH * NT16, ATTN_THREADS, ATTN_SMEM>>>(gm + l * kH);
        gemm_o<<<ggo, 256, GEMM_SMEM>>>(aog, Wo + (size_t)l * kD * kD, bo + l * kD,
                                        pjg, pjg2);
        ln_k<2><<<kBS, 256>>>(xin, pjg, pjg2, lng + l * kD, lnb + l * kD, xg);
    }
    ln_k<0><<<kBS, 256>>>(xg, nullptr, nullptr, fg, fb, out);
}

// round 12
// speedup vs baseline: 1.1529x; 1.0658x over previous
#include <cuda_runtime.h>
#include <math.h>
#include <stdint.h>

namespace {
constexpr int kBn = 2, kS = 1024, kD = 1024, kH = 16, kDH = 64, kL = 4;
constexpr int kBS = kBn * kS;          // 2048 rows
constexpr int kBH = kBn * kH;          // 32 (b,h) pairs
constexpr int TR = 16;                 // query rows per attention block
constexpr int NT16 = kS / TR;          // 64 tiles per (b,h)
constexpr int SCP = 1028;              // padded score-row stride (stride%32==4)
constexpr int ATTN_THREADS = 256;      // 8 warps
// smem: scores + phase3 reduction buffer + per-warp softmax stats
constexpr int ATTN_SMEM = (TR * SCP + TR * kDH + TR * 8 * 2) * 4;  // 70912 B
// GEMM tiling: 128x128 block, 8 warps of 32x64
constexpr int BM = 128, BN = 128, BK = 32;
constexpr int ASTR = 36, BSTR = 136;   // padded smem strides
constexpr int GEMM_SMEM = (2 * BM * ASTR + 2 * BK * BSTR) * 4;  // 71680 B
}

// Scratch (static device allocations; no runtime allocs)
__device__ float g_x[kBS * kD];
__device__ float g_qh[kBH * kS * kDH];   // tf32-pre-rounded q heads (also keys)
__device__ float g_vh[kBH * kS * kDH];   // tf32-pre-rounded v heads
__device__ float g_ao[kBS * kD];
__device__ float g_proj[kBS * kD];
__device__ float g_proj2[kBS * kD];      // split-K partial for gemm_o

// ---------------------------------------------------------------------------
__device__ __forceinline__ uint32_t f2tf(float x) {
    uint32_t r;
    asm("cvt.rna.tf32.f32 %0, %1;" : "=r"(r) : "f"(x));
    return r;
}
__device__ __forceinline__ float sqrt_approx(float x) {
    float r;
    asm("sqrt.approx.f32 %0, %1;" : "=f"(r) : "f"(x));
    return r;
}
__device__ __forceinline__ void mma8(float* d, const uint32_t* a, const uint32_t* b) {
    asm volatile(
        "mma.sync.aligned.m16n8k8.row.col.f32.tf32.tf32.f32 "
        "{%0,%1,%2,%3}, {%4,%5,%6,%7}, {%8,%9}, {%0,%1,%2,%3};\n"
        : "+f"(d[0]), "+f"(d[1]), "+f"(d[2]), "+f"(d[3])
        : "r"(a[0]), "r"(a[1]), "r"(a[2]), "r"(a[3]), "r"(b[0]), "r"(b[1]));
}
// online softmax accumulate
__device__ __forceinline__ void osm(float v, float& m, float& s) {
    if (v > m) { s = s * __expf(m - v) + 1.f; m = v; }
    else       s += __expf(v - m);
}
// merge two (m,s) online-softmax states
__device__ __forceinline__ void osm_merge(float om, float os, float& m, float& s) {
    float nm = fmaxf(m, om);
    s = s * __expf(m - nm) + os * __expf(om - nm);
    m = nm;
}

// ---------------------------------------------------------------------------
// Shared GEMM body: C[2048,1024] = A[:, kbase:kbase+nK*BK] @ W + (bias).
// tf32 mma, cp.async double buffering. Block 128x128, 8 warps of 32x64.
// SCATTER path additionally pre-rounds outputs to tf32 (consumed only as
// mma operands in attn_k; cvt is idempotent so numerics are unchanged).
template<bool SCATTER>
__device__ __forceinline__ void gemm_body(const float* __restrict__ A,
                                          const float* __restrict__ W,
                                          const float* __restrict__ bias,
                                          float* __restrict__ C,
                                          int bxx, int byy, int kbase, int nK,
                                          float* sm) {
    float* As = sm;
    float* Bs = sm + 2 * BM * ASTR;
    const int tid = threadIdx.x, lane = tid & 31, w = tid >> 5;
    const int gid = lane >> 2, l4 = lane & 3;
    const int warpM = w & 3, warpN = w >> 2;
    const int mbase = byy * BM, nbase = bxx * BN;
    const uint32_t sA = (uint32_t)__cvta_generic_to_shared(As);
    const uint32_t sB = (uint32_t)__cvta_generic_to_shared(Bs);

    auto prefetch = [&](int kt, int buf) {
        #pragma unroll
        for (int i = 0; i < 4; i++) {
            int cid = tid + i * 256;
            int m = cid >> 3, kc = cid & 7;
            uint32_t dst = sA + (uint32_t)((buf * BM * ASTR + m * ASTR + kc * 4) * 4);
            const float* src = A + (size_t)(mbase + m) * kD + kbase + kt * BK + kc * 4;
            asm volatile("cp.async.cg.shared.global [%0], [%1], 16;\n" ::"r"(dst), "l"(src));
        }
        #pragma unroll
        for (int i = 0; i < 4; i++) {
            int cid = tid + i * 256;
            int k = cid >> 5, nc = cid & 31;   // full 32 x 128 tile
            uint32_t dst = sB + (uint32_t)((buf * BK * BSTR + k * BSTR + nc * 4) * 4);
            const float* src = W + (size_t)(kbase + kt * BK + k) * kD + nbase + nc * 4;
            asm volatile("cp.async.cg.shared.global [%0], [%1], 16;\n" ::"r"(dst), "l"(src));
        }
        asm volatile("cp.async.commit_group;\n");
    };

    float acc[2][8][4] = {};
    prefetch(0, 0);
    for (int kt = 0; kt < nK; kt++) {
        asm volatile("cp.async.wait_group 0;\n");
        __syncthreads();
        if (kt + 1 < nK) prefetch(kt + 1, (kt + 1) & 1);
        const float* as = As + (kt & 1) * BM * ASTR;
        const float* bs = Bs + (kt & 1) * BK * BSTR;
        #pragma unroll
        for (int ks = 0; ks < 4; ks++) {
            uint32_t af[2][4];
            #pragma unroll
            for (int mt = 0; mt < 2; mt++) {
                int r = warpM * 32 + mt * 16 + gid;
                const float* p = as + r * ASTR + ks * 8 + l4;
                af[mt][0] = f2tf(p[0]);
                af[mt][1] = f2tf(p[8 * ASTR]);
                af[mt][2] = f2tf(p[4]);
                af[mt][3] = f2tf(p[8 * ASTR + 4]);
            }
            #pragma unroll
            for (int nt = 0; nt < 8; nt++) {
                uint32_t bf[2];
                int cn = warpN * 64 + nt * 8 + gid;
                const float* p = bs + (ks * 8 + l4) * BSTR + cn;
                bf[0] = f2tf(p[0]);
                bf[1] = f2tf(p[4 * BSTR]);
                #pragma unroll
                for (int mt = 0; mt < 2; mt++) mma8(acc[mt][nt], af[mt], bf);
            }
        }
        __syncthreads();
    }
    #pragma unroll
    for (int mt = 0; mt < 2; mt++) {
        int r0 = mbase + warpM * 32 + mt * 16 + gid;
        #pragma unroll
        for (int nt = 0; nt < 8; nt++) {
            int cc = nbase + warpN * 64 + nt * 8 + l4 * 2;
            float b0 = bias ? bias[cc] : 0.f;
            float b1 = bias ? bias[cc + 1] : 0.f;
            float2 u = make_float2(acc[mt][nt][0] + b0, acc[mt][nt][1] + b1);
            float2 v = make_float2(acc[mt][nt][2] + b0, acc[mt][nt][3] + b1);
            if (SCATTER) {
                // pre-round to tf32 so attn_k can feed mma without cvt
                u.x = __uint_as_float(f2tf(u.x));
                u.y = __uint_as_float(f2tf(u.y));
                v.x = __uint_as_float(f2tf(v.x));
                v.y = __uint_as_float(f2tf(v.y));
                int bb = r0 / kS, s = r0 - bb * kS;
                int h = cc >> 6, d = cc & 63;
                *(float2*)&C[(((size_t)bb * kH + h) * kS + s) * kDH + d] = u;
                *(float2*)&C[(((size_t)bb * kH + h) * kS + s + 8) * kDH + d] = v;
            } else {
                *(float2*)&C[(size_t)r0 * kD + cc] = u;
                *(float2*)&C[(size_t)(r0 + 8) * kD + cc] = v;
            }
        }
    }
}

// Fused Wq+Wv projections: blockIdx.z selects which GEMM. 256 CTAs.
__global__ void __launch_bounds__(256) gemm_qv(const float* __restrict__ A,
                                               const float* __restrict__ Wq,
                                               const float* __restrict__ bq,
                                               const float* __restrict__ Wv,
                                               const float* __restrict__ bv,
                                               float* __restrict__ Cq,
                                               float* __restrict__ Cv) {
    extern __shared__ float sm[];
    const float* W = blockIdx.z ? Wv : Wq;
    const float* bias = blockIdx.z ? bv : bq;
    float* C = blockIdx.z ? Cv : Cq;
    gemm_body<true>(A, W, bias, C, blockIdx.x, blockIdx.y, 0, kD / BK, sm);
}

// Wo projection, split-K=2 over blockIdx.z: 256 CTAs fill the chip.
__global__ void __launch_bounds__(256) gemm_o(const float* __restrict__ A,
                                              const float* __restrict__ W,
                                              const float* __restrict__ bias,
                                              float* __restrict__ C1,
                                              float* __restrict__ C2) {
    extern __shared__ float sm[];
    const int z = blockIdx.z;
    gemm_body<false>(A, W, z ? nullptr : bias, z ? C2 : C1,
                     blockIdx.x, blockIdx.y, z * (kD / 2), (kD / 2) / BK, sm);
}

// ---------------------------------------------------------------------------
// Gamma attention, 16 query rows per block, 8 warps, 3 CTAs/SM.
// q/v arrive pre-rounded to tf32: operand loads feed mma directly (no cvt).
// Phase 2 uses a 64-col pair-scan to halve the serial carry chain.
__global__ void __launch_bounds__(ATTN_THREADS, 3) attn_k(const float* __restrict__ gam) {
    extern __shared__ float sc[];                 // [TR][SCP] score rows
    float* red = sc + TR * SCP;                   // [TR][64] phase-3 partials
    float* wstat = red + TR * kDH;                // [TR][8][2] per-warp (m,s)

    const int bx = blockIdx.x;
    const int bh = bx & (kBH - 1);
    const int tile = (NT16 - 1) - (bx >> 5);
    const int h = bh & (kH - 1);
    const int b = bh >> 4;
    const int base = tile * TR;
    const int tid = threadIdx.x, lane = tid & 31, w = tid >> 5;
    const int gid = lane >> 2, l4 = lane & 3;
    const float* qb = g_qh + (size_t)bh * kS * kDH;
    const float* vb = g_vh + (size_t)bh * kS * kDH;
    const int nkt = tile + 1, kLimit = nkt * TR;

    // ---- Phase 1: scores = QK^T / 8 with fused online softmax-1 stats.
    {
        uint32_t qa[8][4];
        #pragma unroll
        for (int ks = 0; ks < 8; ks++) {
            const uint32_t* p = (const uint32_t*)(qb + (size_t)(base + gid) * kDH + ks * 8 + l4);
            qa[ks][0] = p[0];
            qa[ks][1] = p[8 * kDH];
            qa[ks][2] = p[4];
            qa[ks][3] = p[8 * kDH + 4];
        }
        const int i0 = base + gid, i1 = base + gid + 8;  // this lane's rows
        float m0 = -3.4e38f, s0 = 0.f, m1 = -3.4e38f, s1 = 0.f;
        for (int kt = w; kt < nkt; kt += 8) {
            const float* kp = qb + (size_t)kt * TR * kDH;
            float acc[2][4] = {};
            #pragma unroll
            for (int ks = 0; ks < 8; ks++) {
                #pragma unroll
                for (int nt = 0; nt < 2; nt++) {
                    uint32_t bf[2];
                    const uint32_t* p = (const uint32_t*)(kp + (size_t)(nt * 8 + gid) * kDH + ks * 8 + l4);
                    bf[0] = p[0];
                    bf[1] = p[4];
                    mma8(acc[nt], qa[ks], bf);
                }
            }
            const bool diag = (kt == tile);
            #pragma unroll
            for (int nt = 0; nt < 2; nt++) {
                int c0 = kt * TR + nt * 8 + l4 * 2;
                float v00 = acc[nt][0] * 0.125f, v01 = acc[nt][1] * 0.125f;
                float v10 = acc[nt][2] * 0.125f, v11 = acc[nt][3] * 0.125f;
                *(float2*)&sc[gid * SCP + c0] = make_float2(v00, v01);
                *(float2*)&sc[(gid + 8) * SCP + c0] = make_float2(v10, v11);
                if (!diag) {            // all cols strictly below both rows
                    osm(v00, m0, s0); osm(v01, m0, s0);
                    osm(v10, m1, s1); osm(v11, m1, s1);
                } else {                // diagonal tile: mask j < i
                    if (c0 < i0)     osm(v00, m0, s0);
                    if (c0 + 1 < i0) osm(v01, m0, s0);
                    if (c0 < i1)     osm(v10, m1, s1);
                    if (c0 + 1 < i1) osm(v11, m1, s1);
                }
            }
        }
        // quad reduce (lanes sharing gid are l4 = 0..3)
        #pragma unroll
        for (int o = 1; o <= 2; o <<= 1) {
            float om = __shfl_xor_sync(~0u, m0, o), os = __shfl_xor_sync(~0u, s0, o);
            osm_merge(om, os, m0, s0);
            om = __shfl_xor_sync(~0u, m1, o); os = __shfl_xor_sync(~0u, s1, o);
            osm_merge(om, os, m1, s1);
        }
        if (l4 == 0) {
            wstat[(gid * 8 + w) * 2] = m0;
            wstat[(gid * 8 + w) * 2 + 1] = s0;
            wstat[((gid + 8) * 8 + w) * 2] = m1;
            wstat[((gid + 8) * 8 + w) * 2 + 1] = s1;
        }
    }
    __syncthreads();

    // ---- Phase 2: combine stats -> pair-scan decay (online stats2) -> finalize.
    {
        const float gm = -fabsf(gam[h]);
        const int i0r = base + w;
        const int i1r = i0r + 8;
        float* row0 = sc + w * SCP;
        float* row1 = sc + (w + 8) * SCP;
        const int nv0 = i0r, nv1 = i1r;   // strict causal: keys j < i

        // combine the 8 per-warp partials for this warp's two rows
        float m0 = -3.4e38f, s0 = 0.f, m1 = -3.4e38f, s1 = 0.f;
        #pragma unroll
        for (int p = 0; p < 8; p++) {
            osm_merge(wstat[(w * 8 + p) * 2], wstat[(w * 8 + p) * 2 + 1], m0, s0);
            osm_merge(wstat[((w + 8) * 8 + p) * 2], wstat[((w + 8) * 8 + p) * 2 + 1], m1, s1);
        }
        const float inv0 = (nv0 > 0) ? 1.f / s0 : 0.f;
        const float inv1 = 1.f / s1;

        // Pass B: 64-col pair-scan cumsum, decay, store s2, online stats2.
        // Lane holds cols (2*lane, 2*lane+1); scan pair-sums; halved carry chain.
        float carry0 = 0.f, carry1 = 0.f;
        float n0 = -3.4e38f, t0 = 0.f, n1 = -3.4e38f, t1 = 0.f;
        for (int c0 = 0; c0 < nv1; c0 += 64) {
            const int j = c0 + lane * 2;
            if (c0 < nv0) {
                bool v0 = j < nv0, v1 = j + 1 < nv0;
                float2 sv = *(const float2*)&row0[j];   // smem, always in-bounds
                float sv0 = v0 ? sv.x : 0.f, sv1 = v1 ? sv.y : 0.f;
                float p0 = v0 ? __expf(sv0 - m0) * inv0 : 0.f;
                float p1 = v1 ? __expf(sv1 - m0) * inv0 : 0.f;
                float ps = p0 + p1;
                float inc = ps;
                #pragma unroll
                for (int o = 1; o < 32; o <<= 1) {
                    float t = __shfl_up_sync(~0u, inc, o);
                    if (lane >= o) inc += t;
                }
                float ncar = __shfl_sync(~0u, inc, 31) + carry0;
                float cum0 = (inc - ps + carry0) + p0;
                float cum1 = cum0 + p1;
                carry0 = ncar;
                float tt0 = fmaxf((1.f - cum0) * (float)(i0r - j), 0.f);
                float tt1 = fmaxf((1.f - cum1) * (float)(i0r - j - 1), 0.f);
                float e0 = fmaxf(__expf(gm * sqrt_approx(tt0)), 1e-5f);
                float e1 = fmaxf(__expf(gm * sqrt_approx(tt1)), 1e-5f);
                float2 s2 = make_float2(sv0 * e0, sv1 * e1);
                *(float2*)&row0[j] = s2;
                if (v0) osm(s2.x, n0, t0);
                if (v1) osm(s2.y, n0, t0);
            }
            {
                bool v0 = j < nv1, v1 = j + 1 < nv1;
                float2 sv = *(const float2*)&row1[j];
                float sv0 = v0 ? sv.x : 0.f, sv1 = v1 ? sv.y : 0.f;
                float p0 = v0 ? __expf(sv0 - m1) * inv1 : 0.f;
                float p1 = v1 ? __expf(sv1 - m1) * inv1 : 0.f;
                float ps = p0 + p1;
                float inc = ps;
                #pragma unroll
                for (int o = 1; o < 32; o <<= 1) {
                    float t = __shfl_up_sync(~0u, inc, o);
                    if (lane >= o) inc += t;
                }
                float ncar = __shfl_sync(~0u, inc, 31) + carry1;
                float cum0 = (inc - ps + carry1) + p0;
                float cum1 = cum0 + p1;
                carry1 = ncar;
                float tt0 = fmaxf((1.f - cum0) * (float)(i1r - j), 0.f);
                float tt1 = fmaxf((1.f - cum1) * (float)(i1r - j - 1), 0.f);
                float e0 = fmaxf(__expf(gm * sqrt_approx(tt0)), 1e-5f);
                float e1 = fmaxf(__expf(gm * sqrt_approx(tt1)), 1e-5f);
                float2 s2 = make_float2(sv0 * e0, sv1 * e1);
                *(float2*)&row1[j] = s2;
                if (v0) osm(s2.x, n1, t1);
                if (v1) osm(s2.y, n1, t1);
            }
        }
        #pragma unroll
        for (int o = 16; o; o >>= 1) {
            float om = __shfl_xor_sync(~0u, n0, o), os = __shfl_xor_sync(~0u, t0, o);
            osm_merge(om, os, n0, t0);
            om = __shfl_xor_sync(~0u, n1, o); os = __shfl_xor_sync(~0u, t1, o);
            osm_merge(om, os, n1, t1);
        }
        // maxout: max(attn) = 1/sum2 exactly => scale = min(sum2,5)/sum2
        const float sf0 = (nv0 > 0) ? fminf(t0, 5.f) / t0 : 0.f;
        const float sf1 = fminf(t1, 5.f) / t1;

        // Pass C: finalize attn values as tf32 bits, zero-fill causal tail.
        for (int c0 = 0; c0 < kLimit; c0 += 64) {
            const int j = c0 + lane * 2;
            if (j < kLimit) {
                float2 a = *(const float2*)&row0[j];
                float2 bb2 = *(const float2*)&row1[j];
                float o00 = (j < nv0)     ? __uint_as_float(f2tf(__expf(a.x - n0) * sf0)) : 0.f;
                float o01 = (j + 1 < nv0) ? __uint_as_float(f2tf(__expf(a.y - n0) * sf0)) : 0.f;
                float o10 = (j < nv1)     ? __uint_as_float(f2tf(__expf(bb2.x - n1) * sf1)) : 0.f;
                float o11 = (j + 1 < nv1) ? __uint_as_float(f2tf(__expf(bb2.y - n1) * sf1)) : 0.f;
                *(float2*)&row0[j] = make_float2(o00, o01);
                *(float2*)&row1[j] = make_float2(o10, o11);
            }
        }
    }
    __syncthreads();

    // ---- Phase 3: out = attn @ V. 4 column groups (16 cols) x 2 kt halves.
    // attn (smem) and V (global) are already tf32 bit patterns -> no cvt.
    {
        const int cg = w & 3;          // cols [cg*16, cg*16+16)
        const int half = w >> 2;       // kt parity
        float oacc[2][4] = {};
        #pragma unroll 2
        for (int kt = half; kt < nkt; kt += 2) {
            const float* vp = vb + (size_t)kt * TR * kDH;
            #pragma unroll
            for (int kk = 0; kk < 2; kk++) {
                uint32_t af[4];
                const uint32_t* q = (const uint32_t*)(sc + gid * SCP + kt * TR + kk * 8 + l4);
                af[0] = q[0];
                af[1] = q[8 * SCP];
                af[2] = q[4];
                af[3] = q[8 * SCP + 4];
                #pragma unroll
                for (int nt = 0; nt < 2; nt++) {
                    uint32_t bf[2];
                    const uint32_t* p = (const uint32_t*)(vp + (size_t)(kk * 8 + l4) * kDH + cg * 16 + nt * 8 + gid);
                    bf[0] = p[0];
                    bf[1] = p[4 * kDH];
                    mma8(oacc[nt], af, bf);
                }
            }
        }
        if (half == 1) {
            #pragma unroll
            for (int nt = 0; nt < 2; nt++) {
                int cc = cg * 16 + nt * 8 + l4 * 2;
                *(float2*)&red[gid * kDH + cc] = make_float2(oacc[nt][0], oacc[nt][1]);
                *(float2*)&red[(gid + 8) * kDH + cc] = make_float2(oacc[nt][2], oacc[nt][3]);
            }
        }
        __syncthreads();
        if (half == 0) {
            const int i0 = base + gid;
            float* op0 = g_ao + ((size_t)b * kS + i0) * kD + h * kDH;
            #pragma unroll
            for (int nt = 0; nt < 2; nt++) {
                int cc = cg * 16 + nt * 8 + l4 * 2;
                float2 p0 = *(const float2*)&red[gid * kDH + cc];
                float2 p1 = *(const float2*)&red[(gid + 8) * kDH + cc];
                *(float2*)(op0 + cc) =
                    make_float2(oacc[nt][0] + p0.x, oacc[nt][1] + p0.y);
                *(float2*)(op0 + 8 * kD + cc) =
                    make_float2(oacc[nt][2] + p1.x, oacc[nt][3] + p1.y);
            }
        }
    }
}

// ---------------------------------------------------------------------------
// LayerNorm with NADD extra addends: out = LN(X (+A1) (+A2)) * g + b.
template<int NADD>
__global__ void __launch_bounds__(256) ln_k(const float* __restrict__ X,
                                            const float* __restrict__ A1,
                                            const float* __restrict__ A2,
                                            const float* __restrict__ g,
                                            const float* __restrict__ bt,
                                            float* __restrict__ out) {
    __shared__ float red[8];
    const int row = blockIdx.x;
    const int tid = threadIdx.x;
    const int lane = tid & 31, w = tid >> 5;
    const float* xr = X + (size_t)row * kD;
    float v[4];
    float s = 0.f;
    #pragma unroll
    for (int t = 0; t < 4; t++) {
        int d = tid + t * 256;
        float val = xr[d];
        if (NADD >= 1) val += A1[(size_t)row * kD + d];
        if (NADD >= 2) val += A2[(size_t)row * kD + d];
        v[t] = val;
        s += val;
    }
    #pragma unroll
    for (int o = 16; o; o >>= 1) s += __shfl_xor_sync(~0u, s, o);
    if (lane == 0) red[w] = s;
    __syncthreads();
    float tot = 0.f;
    #pragma unroll
    for (int k = 0; k < 8; k++) tot += red[k];
    const float mu = tot * (1.0f / kD);
    __syncthreads();
    float s2 = 0.f;
    #pragma unroll
    for (int t = 0; t < 4; t++) { float dv = v[t] - mu; s2 += dv * dv; }
    #pragma unroll
    for (int o = 16; o; o >>= 1) s2 += __shfl_xor_sync(~0u, s2, o);
    if (lane == 0) red[w] = s2;
    __syncthreads();
    float tot2 = 0.f;
    #pragma unroll
    for (int k = 0; k < 8; k++) tot2 += red[k];
    const float rs = rsqrtf(tot2 * (1.0f / kD) + 1e-5f);
    #pragma unroll
    for (int t = 0; t < 4; t++) {
        int d = tid + t * 256;
        out[(size_t)row * kD + d] = (v[t] - mu) * rs * g[d] + bt[d];
    }
}

// ---------------------------------------------------------------------------
extern "C" void kernel_launch(void* const* d_in, const int* in_sizes, int n_in,
                              void* d_out, int out_size) {
    (void)in_sizes; (void)n_in; (void)out_size;
    const float* q   = (const float*)d_in[0];
    // d_in[1] = lens (unused in eval mode)
    const float* Wq  = (const float*)d_in[2];
    const float* bq  = (const float*)d_in[3];
    const float* Wv  = (const float*)d_in[4];
    const float* bv  = (const float*)d_in[5];
    const float* Wo  = (const float*)d_in[6];
    const float* bo  = (const float*)d_in[7];
    const float* gm  = (const float*)d_in[8];
    const float* lng = (const float*)d_in[9];
    const float* lnb = (const float*)d_in[10];
    const float* fg  = (const float*)d_in[11];
    const float* fb  = (const float*)d_in[12];
    float* out = (float*)d_out;

    cudaFuncSetAttribute(attn_k, cudaFuncAttributeMaxDynamicSharedMemorySize, ATTN_SMEM);
    cudaFuncSetAttribute(gemm_qv, cudaFuncAttributeMaxDynamicSharedMemorySize, GEMM_SMEM);
    cudaFuncSetAttribute(gemm_o,  cudaFuncAttributeMaxDynamicSharedMemorySize, GEMM_SMEM);

    void* p;
    float *xg, *qhg, *vhg, *aog, *pjg, *pjg2;
    cudaGetSymbolAddress(&p, g_x);     xg   = (float*)p;
    cudaGetSymbolAddress(&p, g_qh);    qhg  = (float*)p;
    cudaGetSymbolAddress(&p, g_vh);    vhg  = (float*)p;
    cudaGetSymbolAddress(&p, g_ao);    aog  = (float*)p;
    cudaGetSymbolAddress(&p, g_proj);  pjg  = (float*)p;
    cudaGetSymbolAddress(&p, g_proj2); pjg2 = (float*)p;

    dim3 gqv(kD / BN, kBS / BM, 2);  // (8, 16, 2) = 256 CTAs
    dim3 ggo(kD / BN, kBS / BM, 2);  // (8, 16, 2) = 256 CTAs (split-K)
    for (int l = 0; l < kL; l++) {
        const float* xin = (l == 0) ? q : xg;   // layer 0 reads input directly
        gemm_qv<<<gqv, 256, GEMM_SMEM>>>(xin,
            Wq + (size_t)l * kD * kD, bq + l * kD,
            Wv + (size_t)l * kD * kD, bv + l * kD, qhg, vhg);
        attn_k<<<kBH * NT16, ATTN_THREADS, ATTN_SMEM>>>(gm + l * kH);
        gemm_o<<<ggo, 256, GEMM_SMEM>>>(aog, Wo + (size_t)l * kD * kD, bo + l * kD,
                                        pjg, pjg2);
        ln_k<2><<<kBS, 256>>>(xin, pjg, pjg2, lng + l * kD, lnb + l * kD, xg);
    }
    ln_k<0><<<kBS, 256>>>(xg, nullptr, nullptr, fg, fb, out);
}

// round 13
// speedup vs baseline: 1.1690x; 1.0139x over previous
#include <cuda_runtime.h>
#include <math.h>
#include <stdint.h>

namespace {
constexpr int kBn = 2, kS = 1024, kD = 1024, kH = 16, kDH = 64, kL = 4;
constexpr int kBS = kBn * kS;          // 2048 rows
constexpr int kBH = kBn * kH;          // 32 (b,h) pairs
constexpr int TR = 16;                 // query rows per attention block
constexpr int NT16 = kS / TR;          // 64 tiles per (b,h)
constexpr int SCP = 1028;              // padded score-row stride (%4==0, %32==4)
constexpr int ATTN_THREADS = 256;      // 8 warps
// smem: scores + phase3 reduction buffer + per-warp softmax stats
constexpr int ATTN_SMEM = (TR * SCP + TR * kDH + TR * 8 * 2) * 4;  // 70912 B
// GEMM tiling: 128x128 block, 8 warps of 32x64
constexpr int BM = 128, BN = 128, BK = 32;
constexpr int ASTR = 36, BSTR = 136;   // padded smem strides
constexpr int GEMM_SMEM = (2 * BM * ASTR + 2 * BK * BSTR) * 4;  // 71680 B
}

// Scratch (static device allocations; no runtime allocs)
__device__ float g_x[kBS * kD];
__device__ float g_qh[kBH * kS * kDH];   // tf32-pre-rounded q heads (also keys)
__device__ float g_vh[kBH * kS * kDH];   // tf32-pre-rounded v heads
__device__ float g_ao[kBS * kD];
__device__ float g_proj[kBS * kD];
__device__ float g_proj2[kBS * kD];      // split-K partial for gemm_o

// ---------------------------------------------------------------------------
__device__ __forceinline__ uint32_t f2tf(float x) {
    uint32_t r;
    asm("cvt.rna.tf32.f32 %0, %1;" : "=r"(r) : "f"(x));
    return r;
}
__device__ __forceinline__ float sqrt_approx(float x) {
    float r;
    asm("sqrt.approx.f32 %0, %1;" : "=f"(r) : "f"(x));
    return r;
}
__device__ __forceinline__ void mma8(float* d, const uint32_t* a, const uint32_t* b) {
    asm volatile(
        "mma.sync.aligned.m16n8k8.row.col.f32.tf32.tf32.f32 "
        "{%0,%1,%2,%3}, {%4,%5,%6,%7}, {%8,%9}, {%0,%1,%2,%3};\n"
        : "+f"(d[0]), "+f"(d[1]), "+f"(d[2]), "+f"(d[3])
        : "r"(a[0]), "r"(a[1]), "r"(a[2]), "r"(a[3]), "r"(b[0]), "r"(b[1]));
}
// online softmax accumulate
__device__ __forceinline__ void osm(float v, float& m, float& s) {
    if (v > m) { s = s * __expf(m - v) + 1.f; m = v; }
    else       s += __expf(v - m);
}
// merge two (m,s) online-softmax states
__device__ __forceinline__ void osm_merge(float om, float os, float& m, float& s) {
    float nm = fmaxf(m, om);
    s = s * __expf(m - nm) + os * __expf(om - nm);
    m = nm;
}

// ---------------------------------------------------------------------------
// Shared GEMM body: C[2048,1024] = A[:, kbase:kbase+nK*BK] @ W + (bias).
// tf32 mma, cp.async double buffering. Block 128x128, 8 warps of 32x64.
// SCATTER path additionally pre-rounds outputs to tf32 (consumed only as
// mma operands in attn_k; cvt is idempotent so numerics are unchanged).
template<bool SCATTER>
__device__ __forceinline__ void gemm_body(const float* __restrict__ A,
                                          const float* __restrict__ W,
                                          const float* __restrict__ bias,
                                          float* __restrict__ C,
                                          int bxx, int byy, int kbase, int nK,
                                          float* sm) {
    float* As = sm;
    float* Bs = sm + 2 * BM * ASTR;
    const int tid = threadIdx.x, lane = tid & 31, w = tid >> 5;
    const int gid = lane >> 2, l4 = lane & 3;
    const int warpM = w & 3, warpN = w >> 2;
    const int mbase = byy * BM, nbase = bxx * BN;
    const uint32_t sA = (uint32_t)__cvta_generic_to_shared(As);
    const uint32_t sB = (uint32_t)__cvta_generic_to_shared(Bs);

    auto prefetch = [&](int kt, int buf) {
        #pragma unroll
        for (int i = 0; i < 4; i++) {
            int cid = tid + i * 256;
            int m = cid >> 3, kc = cid & 7;
            uint32_t dst = sA + (uint32_t)((buf * BM * ASTR + m * ASTR + kc * 4) * 4);
            const float* src = A + (size_t)(mbase + m) * kD + kbase + kt * BK + kc * 4;
            asm volatile("cp.async.cg.shared.global [%0], [%1], 16;\n" ::"r"(dst), "l"(src));
        }
        #pragma unroll
        for (int i = 0; i < 4; i++) {
            int cid = tid + i * 256;
            int k = cid >> 5, nc = cid & 31;   // full 32 x 128 tile
            uint32_t dst = sB + (uint32_t)((buf * BK * BSTR + k * BSTR + nc * 4) * 4);
            const float* src = W + (size_t)(kbase + kt * BK + k) * kD + nbase + nc * 4;
            asm volatile("cp.async.cg.shared.global [%0], [%1], 16;\n" ::"r"(dst), "l"(src));
        }
        asm volatile("cp.async.commit_group;\n");
    };

    float acc[2][8][4] = {};
    prefetch(0, 0);
    for (int kt = 0; kt < nK; kt++) {
        asm volatile("cp.async.wait_group 0;\n");
        __syncthreads();
        if (kt + 1 < nK) prefetch(kt + 1, (kt + 1) & 1);
        const float* as = As + (kt & 1) * BM * ASTR;
        const float* bs = Bs + (kt & 1) * BK * BSTR;
        #pragma unroll
        for (int ks = 0; ks < 4; ks++) {
            uint32_t af[2][4];
            #pragma unroll
            for (int mt = 0; mt < 2; mt++) {
                int r = warpM * 32 + mt * 16 + gid;
                const float* p = as + r * ASTR + ks * 8 + l4;
                af[mt][0] = f2tf(p[0]);
                af[mt][1] = f2tf(p[8 * ASTR]);
                af[mt][2] = f2tf(p[4]);
                af[mt][3] = f2tf(p[8 * ASTR + 4]);
            }
            #pragma unroll
            for (int nt = 0; nt < 8; nt++) {
                uint32_t bf[2];
                int cn = warpN * 64 + nt * 8 + gid;
                const float* p = bs + (ks * 8 + l4) * BSTR + cn;
                bf[0] = f2tf(p[0]);
                bf[1] = f2tf(p[4 * BSTR]);
                #pragma unroll
                for (int mt = 0; mt < 2; mt++) mma8(acc[mt][nt], af[mt], bf);
            }
        }
        __syncthreads();
    }
    #pragma unroll
    for (int mt = 0; mt < 2; mt++) {
        int r0 = mbase + warpM * 32 + mt * 16 + gid;
        #pragma unroll
        for (int nt = 0; nt < 8; nt++) {
            int cc = nbase + warpN * 64 + nt * 8 + l4 * 2;
            float b0 = bias ? bias[cc] : 0.f;
            float b1 = bias ? bias[cc + 1] : 0.f;
            float2 u = make_float2(acc[mt][nt][0] + b0, acc[mt][nt][1] + b1);
            float2 v = make_float2(acc[mt][nt][2] + b0, acc[mt][nt][3] + b1);
            if (SCATTER) {
                // pre-round to tf32 so attn_k can feed mma without cvt
                u.x = __uint_as_float(f2tf(u.x));
                u.y = __uint_as_float(f2tf(u.y));
                v.x = __uint_as_float(f2tf(v.x));
                v.y = __uint_as_float(f2tf(v.y));
                int bb = r0 / kS, s = r0 - bb * kS;
                int h = cc >> 6, d = cc & 63;
                *(float2*)&C[(((size_t)bb * kH + h) * kS + s) * kDH + d] = u;
                *(float2*)&C[(((size_t)bb * kH + h) * kS + s + 8) * kDH + d] = v;
            } else {
                *(float2*)&C[(size_t)r0 * kD + cc] = u;
                *(float2*)&C[(size_t)(r0 + 8) * kD + cc] = v;
            }
        }
    }
}

// Fused Wq+Wv projections: blockIdx.z selects which GEMM. 256 CTAs.
__global__ void __launch_bounds__(256) gemm_qv(const float* __restrict__ A,
                                               const float* __restrict__ Wq,
                                               const float* __restrict__ bq,
                                               const float* __restrict__ Wv,
                                               const float* __restrict__ bv,
                                               float* __restrict__ Cq,
                                               float* __restrict__ Cv) {
    extern __shared__ float sm[];
    const float* W = blockIdx.z ? Wv : Wq;
    const float* bias = blockIdx.z ? bv : bq;
    float* C = blockIdx.z ? Cv : Cq;
    gemm_body<true>(A, W, bias, C, blockIdx.x, blockIdx.y, 0, kD / BK, sm);
}

// Wo projection, split-K=2 over blockIdx.z: 256 CTAs fill the chip.
__global__ void __launch_bounds__(256) gemm_o(const float* __restrict__ A,
                                              const float* __restrict__ W,
                                              const float* __restrict__ bias,
                                              float* __restrict__ C1,
                                              float* __restrict__ C2) {
    extern __shared__ float sm[];
    const int z = blockIdx.z;
    gemm_body<false>(A, W, z ? nullptr : bias, z ? C2 : C1,
                     blockIdx.x, blockIdx.y, z * (kD / 2), (kD / 2) / BK, sm);
}

// ---------------------------------------------------------------------------
// Gamma attention, 16 query rows per block, 8 warps, 3 CTAs/SM.
// q/v arrive pre-rounded to tf32: operand loads feed mma directly (no cvt).
// Phase 2 uses a 128-col quad-scan to quarter the serial carry chain.
__global__ void __launch_bounds__(ATTN_THREADS, 3) attn_k(const float* __restrict__ gam) {
    extern __shared__ float sc[];                 // [TR][SCP] score rows
    float* red = sc + TR * SCP;                   // [TR][64] phase-3 partials
    float* wstat = red + TR * kDH;                // [TR][8][2] per-warp (m,s)

    const int bx = blockIdx.x;
    const int bh = bx & (kBH - 1);
    const int tile = (NT16 - 1) - (bx >> 5);
    const int h = bh & (kH - 1);
    const int b = bh >> 4;
    const int base = tile * TR;
    const int tid = threadIdx.x, lane = tid & 31, w = tid >> 5;
    const int gid = lane >> 2, l4 = lane & 3;
    const float* qb = g_qh + (size_t)bh * kS * kDH;
    const float* vb = g_vh + (size_t)bh * kS * kDH;
    const int nkt = tile + 1, kLimit = nkt * TR;

    // ---- Phase 1: scores = QK^T / 8 with fused online softmax-1 stats.
    {
        uint32_t qa[8][4];
        #pragma unroll
        for (int ks = 0; ks < 8; ks++) {
            const uint32_t* p = (const uint32_t*)(qb + (size_t)(base + gid) * kDH + ks * 8 + l4);
            qa[ks][0] = p[0];
            qa[ks][1] = p[8 * kDH];
            qa[ks][2] = p[4];
            qa[ks][3] = p[8 * kDH + 4];
        }
        const int i0 = base + gid, i1 = base + gid + 8;  // this lane's rows
        float m0 = -3.4e38f, s0 = 0.f, m1 = -3.4e38f, s1 = 0.f;
        for (int kt = w; kt < nkt; kt += 8) {
            const float* kp = qb + (size_t)kt * TR * kDH;
            float acc[2][4] = {};
            #pragma unroll
            for (int ks = 0; ks < 8; ks++) {
                #pragma unroll
                for (int nt = 0; nt < 2; nt++) {
                    uint32_t bf[2];
                    const uint32_t* p = (const uint32_t*)(kp + (size_t)(nt * 8 + gid) * kDH + ks * 8 + l4);
                    bf[0] = p[0];
                    bf[1] = p[4];
                    mma8(acc[nt], qa[ks], bf);
                }
            }
            const bool diag = (kt == tile);
            #pragma unroll
            for (int nt = 0; nt < 2; nt++) {
                int c0 = kt * TR + nt * 8 + l4 * 2;
                float v00 = acc[nt][0] * 0.125f, v01 = acc[nt][1] * 0.125f;
                float v10 = acc[nt][2] * 0.125f, v11 = acc[nt][3] * 0.125f;
                *(float2*)&sc[gid * SCP + c0] = make_float2(v00, v01);
                *(float2*)&sc[(gid + 8) * SCP + c0] = make_float2(v10, v11);
                if (!diag) {            // all cols strictly below both rows
                    osm(v00, m0, s0); osm(v01, m0, s0);
                    osm(v10, m1, s1); osm(v11, m1, s1);
                } else {                // diagonal tile: mask j < i
                    if (c0 < i0)     osm(v00, m0, s0);
                    if (c0 + 1 < i0) osm(v01, m0, s0);
                    if (c0 < i1)     osm(v10, m1, s1);
                    if (c0 + 1 < i1) osm(v11, m1, s1);
                }
            }
        }
        // quad reduce (lanes sharing gid are l4 = 0..3)
        #pragma unroll
        for (int o = 1; o <= 2; o <<= 1) {
            float om = __shfl_xor_sync(~0u, m0, o), os = __shfl_xor_sync(~0u, s0, o);
            osm_merge(om, os, m0, s0);
            om = __shfl_xor_sync(~0u, m1, o); os = __shfl_xor_sync(~0u, s1, o);
            osm_merge(om, os, m1, s1);
        }
        if (l4 == 0) {
            wstat[(gid * 8 + w) * 2] = m0;
            wstat[(gid * 8 + w) * 2 + 1] = s0;
            wstat[((gid + 8) * 8 + w) * 2] = m1;
            wstat[((gid + 8) * 8 + w) * 2 + 1] = s1;
        }
    }
    __syncthreads();

    // ---- Phase 2: combine stats -> quad-scan decay (online stats2) -> finalize.
    {
        const float gm = -fabsf(gam[h]);
        const int i0r = base + w;
        const int i1r = i0r + 8;
        float* row0 = sc + w * SCP;
        float* row1 = sc + (w + 8) * SCP;
        const int nv0 = i0r, nv1 = i1r;   // strict causal: keys j < i

        // combine the 8 per-warp partials for this warp's two rows
        float m0 = -3.4e38f, s0 = 0.f, m1 = -3.4e38f, s1 = 0.f;
        #pragma unroll
        for (int p = 0; p < 8; p++) {
            osm_merge(wstat[(w * 8 + p) * 2], wstat[(w * 8 + p) * 2 + 1], m0, s0);
            osm_merge(wstat[((w + 8) * 8 + p) * 2], wstat[((w + 8) * 8 + p) * 2 + 1], m1, s1);
        }
        const float inv0 = (nv0 > 0) ? 1.f / s0 : 0.f;
        const float inv1 = 1.f / s1;

        // Pass B: 128-col quad-scan cumsum, decay, store s2, online stats2.
        // Lane holds cols (4*lane..4*lane+3); scan quad-sums; quartered chain.
        float carry0 = 0.f, carry1 = 0.f;
        float n0 = -3.4e38f, t0 = 0.f, n1 = -3.4e38f, t1 = 0.f;
        for (int c0 = 0; c0 < nv1; c0 += 128) {
            const int j = c0 + lane * 4;
            if (c0 < nv0) {
                bool v0 = j < nv0, v1 = j + 1 < nv0, v2 = j + 2 < nv0, v3 = j + 3 < nv0;
                float4 sv = *(const float4*)&row0[j];   // smem, in-bounds (SCP pad)
                float p0 = v0 ? __expf(sv.x - m0) * inv0 : 0.f;
                float p1 = v1 ? __expf(sv.y - m0) * inv0 : 0.f;
                float p2 = v2 ? __expf(sv.z - m0) * inv0 : 0.f;
                float p3 = v3 ? __expf(sv.w - m0) * inv0 : 0.f;
                float qs = ((p0 + p1) + p2) + p3;
                float inc = qs;
                #pragma unroll
                for (int o = 1; o < 32; o <<= 1) {
                    float t = __shfl_up_sync(~0u, inc, o);
                    if (lane >= o) inc += t;
                }
                float ncar = __shfl_sync(~0u, inc, 31) + carry0;
                float cum0 = (inc - qs + carry0) + p0;
                float cum1 = cum0 + p1;
                float cum2 = cum1 + p2;
                float cum3 = cum2 + p3;
                carry0 = ncar;
                float e0 = fmaxf(__expf(gm * sqrt_approx(fmaxf((1.f - cum0) * (float)(i0r - j), 0.f))), 1e-5f);
                float e1 = fmaxf(__expf(gm * sqrt_approx(fmaxf((1.f - cum1) * (float)(i0r - j - 1), 0.f))), 1e-5f);
                float e2 = fmaxf(__expf(gm * sqrt_approx(fmaxf((1.f - cum2) * (float)(i0r - j - 2), 0.f))), 1e-5f);
                float e3 = fmaxf(__expf(gm * sqrt_approx(fmaxf((1.f - cum3) * (float)(i0r - j - 3), 0.f))), 1e-5f);
                float4 s2 = make_float4(sv.x * e0, sv.y * e1, sv.z * e2, sv.w * e3);
                *(float4*)&row0[j] = s2;
                if (v0) osm(s2.x, n0, t0);
                if (v1) osm(s2.y, n0, t0);
                if (v2) osm(s2.z, n0, t0);
                if (v3) osm(s2.w, n0, t0);
            }
            {
                bool v0 = j < nv1, v1 = j + 1 < nv1, v2 = j + 2 < nv1, v3 = j + 3 < nv1;
                float4 sv = *(const float4*)&row1[j];
                float p0 = v0 ? __expf(sv.x - m1) * inv1 : 0.f;
                float p1 = v1 ? __expf(sv.y - m1) * inv1 : 0.f;
                float p2 = v2 ? __expf(sv.z - m1) * inv1 : 0.f;
                float p3 = v3 ? __expf(sv.w - m1) * inv1 : 0.f;
                float qs = ((p0 + p1) + p2) + p3;
                float inc = qs;
                #pragma unroll
                for (int o = 1; o < 32; o <<= 1) {
                    float t = __shfl_up_sync(~0u, inc, o);
                    if (lane >= o) inc += t;
                }
                float ncar = __shfl_sync(~0u, inc, 31) + carry1;
                float cum0 = (inc - qs + carry1) + p0;
                float cum1 = cum0 + p1;
                float cum2 = cum1 + p2;
                float cum3 = cum2 + p3;
                carry1 = ncar;
                float e0 = fmaxf(__expf(gm * sqrt_approx(fmaxf((1.f - cum0) * (float)(i1r - j), 0.f))), 1e-5f);
                float e1 = fmaxf(__expf(gm * sqrt_approx(fmaxf((1.f - cum1) * (float)(i1r - j - 1), 0.f))), 1e-5f);
                float e2 = fmaxf(__expf(gm * sqrt_approx(fmaxf((1.f - cum2) * (float)(i1r - j - 2), 0.f))), 1e-5f);
                float e3 = fmaxf(__expf(gm * sqrt_approx(fmaxf((1.f - cum3) * (float)(i1r - j - 3), 0.f))), 1e-5f);
                float4 s2 = make_float4(sv.x * e0, sv.y * e1, sv.z * e2, sv.w * e3);
                *(float4*)&row1[j] = s2;
                if (v0) osm(s2.x, n1, t1);
                if (v1) osm(s2.y, n1, t1);
                if (v2) osm(s2.z, n1, t1);
                if (v3) osm(s2.w, n1, t1);
            }
        }
        #pragma unroll
        for (int o = 16; o; o >>= 1) {
            float om = __shfl_xor_sync(~0u, n0, o), os = __shfl_xor_sync(~0u, t0, o);
            osm_merge(om, os, n0, t0);
            om = __shfl_xor_sync(~0u, n1, o); os = __shfl_xor_sync(~0u, t1, o);
            osm_merge(om, os, n1, t1);
        }
        // maxout: max(attn) = 1/sum2 exactly => scale = min(sum2,5)/sum2
        const float sf0 = (nv0 > 0) ? fminf(t0, 5.f) / t0 : 0.f;
        const float sf1 = fminf(t1, 5.f) / t1;

        // Pass C: finalize attn values as tf32 bits (float4), zero causal tail.
        for (int c0 = 0; c0 < kLimit; c0 += 128) {
            const int j = c0 + lane * 4;
            if (j < kLimit) {       // kLimit % 16 == 0 -> whole quad valid
                float4 a = *(const float4*)&row0[j];
                float4 c = *(const float4*)&row1[j];
                float4 o0, o1;
                o0.x = (j < nv0)     ? __uint_as_float(f2tf(__expf(a.x - n0) * sf0)) : 0.f;
                o0.y = (j + 1 < nv0) ? __uint_as_float(f2tf(__expf(a.y - n0) * sf0)) : 0.f;
                o0.z = (j + 2 < nv0) ? __uint_as_float(f2tf(__expf(a.z - n0) * sf0)) : 0.f;
                o0.w = (j + 3 < nv0) ? __uint_as_float(f2tf(__expf(a.w - n0) * sf0)) : 0.f;
                o1.x = (j < nv1)     ? __uint_as_float(f2tf(__expf(c.x - n1) * sf1)) : 0.f;
                o1.y = (j + 1 < nv1) ? __uint_as_float(f2tf(__expf(c.y - n1) * sf1)) : 0.f;
                o1.z = (j + 2 < nv1) ? __uint_as_float(f2tf(__expf(c.z - n1) * sf1)) : 0.f;
                o1.w = (j + 3 < nv1) ? __uint_as_float(f2tf(__expf(c.w - n1) * sf1)) : 0.f;
                *(float4*)&row0[j] = o0;
                *(float4*)&row1[j] = o1;
            }
        }
    }
    __syncthreads();

    // ---- Phase 3: out = attn @ V. 4 column groups (16 cols) x 2 kt halves.
    // attn (smem) and V (global) are already tf32 bit patterns -> no cvt.
    {
        const int cg = w & 3;          // cols [cg*16, cg*16+16)
        const int half = w >> 2;       // kt parity
        float oacc[2][4] = {};
        #pragma unroll 2
        for (int kt = half; kt < nkt; kt += 2) {
            const float* vp = vb + (size_t)kt * TR * kDH;
            #pragma unroll
            for (int kk = 0; kk < 2; kk++) {
                uint32_t af[4];
                const uint32_t* q = (const uint32_t*)(sc + gid * SCP + kt * TR + kk * 8 + l4);
                af[0] = q[0];
                af[1] = q[8 * SCP];
                af[2] = q[4];
                af[3] = q[8 * SCP + 4];
                #pragma unroll
                for (int nt = 0; nt < 2; nt++) {
                    uint32_t bf[2];
                    const uint32_t* p = (const uint32_t*)(vp + (size_t)(kk * 8 + l4) * kDH + cg * 16 + nt * 8 + gid);
                    bf[0] = p[0];
                    bf[1] = p[4 * kDH];
                    mma8(oacc[nt], af, bf);
                }
            }
        }
        if (half == 1) {
            #pragma unroll
            for (int nt = 0; nt < 2; nt++) {
                int cc = cg * 16 + nt * 8 + l4 * 2;
                *(float2*)&red[gid * kDH + cc] = make_float2(oacc[nt][0], oacc[nt][1]);
                *(float2*)&red[(gid + 8) * kDH + cc] = make_float2(oacc[nt][2], oacc[nt][3]);
            }
        }
        __syncthreads();
        if (half == 0) {
            const int i0 = base + gid;
            float* op0 = g_ao + ((size_t)b * kS + i0) * kD + h * kDH;
            #pragma unroll
            for (int nt = 0; nt < 2; nt++) {
                int cc = cg * 16 + nt * 8 + l4 * 2;
                float2 p0 = *(const float2*)&red[gid * kDH + cc];
                float2 p1 = *(const float2*)&red[(gid + 8) * kDH + cc];
                *(float2*)(op0 + cc) =
                    make_float2(oacc[nt][0] + p0.x, oacc[nt][1] + p0.y);
                *(float2*)(op0 + 8 * kD + cc) =
                    make_float2(oacc[nt][2] + p1.x, oacc[nt][3] + p1.y);
            }
        }
    }
}

// ---------------------------------------------------------------------------
// LayerNorm with NADD extra addends: out = LN(X (+A1) (+A2)) * g + b.
template<int NADD>
__global__ void __launch_bounds__(256) ln_k(const float* __restrict__ X,
                                            const float* __restrict__ A1,
                                            const float* __restrict__ A2,
                                            const float* __restrict__ g,
                                            const float* __restrict__ bt,
                                            float* __restrict__ out) {
    __shared__ float red[8];
    const int row = blockIdx.x;
    const int tid = threadIdx.x;
    const int lane = tid & 31, w = tid >> 5;
    const float* xr = X + (size_t)row * kD;
    float v[4];
    float s = 0.f;
    #pragma unroll
    for (int t = 0; t < 4; t++) {
        int d = tid + t * 256;
        float val = xr[d];
        if (NADD >= 1) val += A1[(size_t)row * kD + d];
        if (NADD >= 2) val += A2[(size_t)row * kD + d];
        v[t] = val;
        s += val;
    }
    #pragma unroll
    for (int o = 16; o; o >>= 1) s += __shfl_xor_sync(~0u, s, o);
    if (lane == 0) red[w] = s;
    __syncthreads();
    float tot = 0.f;
    #pragma unroll
    for (int k = 0; k < 8; k++) tot += red[k];
    const float mu = tot * (1.0f / kD);
    __syncthreads();
    float s2 = 0.f;
    #pragma unroll
    for (int t = 0; t < 4; t++) { float dv = v[t] - mu; s2 += dv * dv; }
    #pragma unroll
    for (int o = 16; o; o >>= 1) s2 += __shfl_xor_sync(~0u, s2, o);
    if (lane == 0) red[w] = s2;
    __syncthreads();
    float tot2 = 0.f;
    #pragma unroll
    for (int k = 0; k < 8; k++) tot2 += red[k];
    const float rs = rsqrtf(tot2 * (1.0f / kD) + 1e-5f);
    #pragma unroll
    for (int t = 0; t < 4; t++) {
        int d = tid + t * 256;
        out[(size_t)row * kD + d] = (v[t] - mu) * rs * g[d] + bt[d];
    }
}

// ---------------------------------------------------------------------------
extern "C" void kernel_launch(void* const* d_in, const int* in_sizes, int n_in,
                              void* d_out, int out_size) {
    (void)in_sizes; (void)n_in; (void)out_size;
    const float* q   = (const float*)d_in[0];
    // d_in[1] = lens (unused in eval mode)
    const float* Wq  = (const float*)d_in[2];
    const float* bq  = (const float*)d_in[3];
    const float* Wv  = (const float*)d_in[4];
    const float* bv  = (const float*)d_in[5];
    const float* Wo  = (const float*)d_in[6];
    const float* bo  = (const float*)d_in[7];
    const float* gm  = (const float*)d_in[8];
    const float* lng = (const float*)d_in[9];
    const float* lnb = (const float*)d_in[10];
    const float* fg  = (const float*)d_in[11];
    const float* fb  = (const float*)d_in[12];
    float* out = (float*)d_out;

    cudaFuncSetAttribute(attn_k, cudaFuncAttributeMaxDynamicSharedMemorySize, ATTN_SMEM);
    cudaFuncSetAttribute(gemm_qv, cudaFuncAttributeMaxDynamicSharedMemorySize, GEMM_SMEM);
    cudaFuncSetAttribute(gemm_o,  cudaFuncAttributeMaxDynamicSharedMemorySize, GEMM_SMEM);

    void* p;
    float *xg, *qhg, *vhg, *aog, *pjg, *pjg2;
    cudaGetSymbolAddress(&p, g_x);     xg   = (float*)p;
    cudaGetSymbolAddress(&p, g_qh);    qhg  = (float*)p;
    cudaGetSymbolAddress(&p, g_vh);    vhg  = (float*)p;
    cudaGetSymbolAddress(&p, g_ao);    aog  = (float*)p;
    cudaGetSymbolAddress(&p, g_proj);  pjg  = (float*)p;
    cudaGetSymbolAddress(&p, g_proj2); pjg2 = (float*)p;

    dim3 gqv(kD / BN, kBS / BM, 2);  // (8, 16, 2) = 256 CTAs
    dim3 ggo(kD / BN, kBS / BM, 2);  // (8, 16, 2) = 256 CTAs (split-K)
    for (int l = 0; l < kL; l++) {
        const float* xin = (l == 0) ? q : xg;   // layer 0 reads input directly
        gemm_qv<<<gqv, 256, GEMM_SMEM>>>(xin,
            Wq + (size_t)l * kD * kD, bq + l * kD,
            Wv + (size_t)l * kD * kD, bv + l * kD, qhg, vhg);
        attn_k<<<kBH * NT16, ATTN_THREADS, ATTN_SMEM>>>(gm + l * kH);
        gemm_o<<<ggo, 256, GEMM_SMEM>>>(aog, Wo + (size_t)l * kD * kD, bo + l * kD,
                                        pjg, pjg2);
        ln_k<2><<<kBS, 256>>>(xin, pjg, pjg2, lng + l * kD, lnb + l * kD, xg);
    }
    ln_k<0><<<kBS, 256>>>(xg, nullptr, nullptr, fg, fb, out);
}

// round 14
// speedup vs baseline: 1.2055x; 1.0312x over previous
#include <cuda_runtime.h>
#include <math.h>
#include <stdint.h>

namespace {
constexpr int kBn = 2, kS = 1024, kD = 1024, kH = 16, kDH = 64, kL = 4;
constexpr int kBS = kBn * kS;          // 2048 rows
constexpr int kBH = kBn * kH;          // 32 (b,h) pairs
constexpr int TR = 16;                 // query rows per attention block
constexpr int NT16 = kS / TR;          // 64 tiles per (b,h)
constexpr int SCP = 1028;              // padded score-row stride (%4==0, %32==4)
constexpr int ATTN_THREADS = 256;      // 8 warps
constexpr int ATTN_SMEM = (TR * SCP + TR * kDH + TR * 8 * 2) * 4;  // 70912 B
// GEMM tiling: 128x128 block, 8 warps of 32x64
constexpr int BM = 128, BN = 128, BK = 32;
constexpr int ASTR = 36, BSTR = 136;   // padded smem strides
constexpr int GEMM_SMEM = (2 * BM * ASTR + 2 * BK * BSTR) * 4;  // 71680 B
constexpr size_t kWSZ = (size_t)kL * kD * kD;    // floats per weight set
}

// Scratch (static device allocations; no runtime allocs)
__device__ float g_x[kBS * kD];          // fp32 activations (residual path)
__device__ float g_xt[kBS * kD];         // tf32-rounded activations (GEMM A)
__device__ float g_qh[kBH * kS * kDH];   // tf32-rounded q heads (also keys)
__device__ float g_vh[kBH * kS * kDH];   // tf32-rounded v heads
__device__ float g_ao[kBS * kD];         // tf32-rounded attention output
__device__ float g_proj[kBS * kD];
__device__ float g_proj2[kBS * kD];      // split-K partial for gemm_o
__device__ float g_wt[3 * kWSZ];         // tf32-rounded Wq|Wv|Wo (all layers)

// ---------------------------------------------------------------------------
__device__ __forceinline__ uint32_t f2tf(float x) {
    uint32_t r;
    asm("cvt.rna.tf32.f32 %0, %1;" : "=r"(r) : "f"(x));
    return r;
}
__device__ __forceinline__ float f2tff(float x) { return __uint_as_float(f2tf(x)); }
__device__ __forceinline__ float sqrt_approx(float x) {
    float r;
    asm("sqrt.approx.f32 %0, %1;" : "=f"(r) : "f"(x));
    return r;
}
__device__ __forceinline__ void mma8(float* d, const uint32_t* a, const uint32_t* b) {
    asm volatile(
        "mma.sync.aligned.m16n8k8.row.col.f32.tf32.tf32.f32 "
        "{%0,%1,%2,%3}, {%4,%5,%6,%7}, {%8,%9}, {%0,%1,%2,%3};\n"
        : "+f"(d[0]), "+f"(d[1]), "+f"(d[2]), "+f"(d[3])
        : "r"(a[0]), "r"(a[1]), "r"(a[2]), "r"(a[3]), "r"(b[0]), "r"(b[1]));
}
// online softmax accumulate
__device__ __forceinline__ void osm(float v, float& m, float& s) {
    if (v > m) { s = s * __expf(m - v) + 1.f; m = v; }
    else       s += __expf(v - m);
}
// merge two (m,s) online-softmax states
__device__ __forceinline__ void osm_merge(float om, float os, float& m, float& s) {
    float nm = fmaxf(m, om);
    s = s * __expf(m - nm) + os * __expf(om - nm);
    m = nm;
}

// ---------------------------------------------------------------------------
// Pre-round all GEMM operands to tf32 in one pass: Wq|Wv|Wo -> g_wt, q -> g_xt.
__global__ void __launch_bounds__(256) round_all(const float* __restrict__ q,
                                                 const float* __restrict__ Wq,
                                                 const float* __restrict__ Wv,
                                                 const float* __restrict__ Wo) {
    const size_t w4 = kWSZ / 4;            // float4 per weight set
    const size_t x4 = (size_t)kBS * kD / 4;
    size_t i = (size_t)blockIdx.x * 256 + threadIdx.x;
    const float4* src;
    float4* dst;
    size_t off;
    if (i < w4)            { src = (const float4*)Wq; dst = (float4*)g_wt;            off = i; }
    else if (i < 2 * w4)   { src = (const float4*)Wv; dst = (float4*)(g_wt + kWSZ);   off = i - w4; }
    else if (i < 3 * w4)   { src = (const float4*)Wo; dst = (float4*)(g_wt + 2*kWSZ); off = i - 2*w4; }
    else if (i < 3*w4+x4)  { src = (const float4*)q;  dst = (float4*)g_xt;            off = i - 3*w4; }
    else return;
    float4 v = src[off];
    v.x = f2tff(v.x); v.y = f2tff(v.y); v.z = f2tff(v.z); v.w = f2tff(v.w);
    dst[off] = v;
}

// ---------------------------------------------------------------------------
// Shared GEMM body: C = A[:, kbase:+nK*BK] @ W + (bias). All operands already
// tf32-rounded in memory -> inner loop has NO cvt. cp.async double buffered.
template<bool SCATTER>
__device__ __forceinline__ void gemm_body(const float* __restrict__ A,
                                          const float* __restrict__ W,
                                          const float* __restrict__ bias,
                                          float* __restrict__ C,
                                          int bxx, int byy, int kbase, int nK,
                                          float* sm) {
    float* As = sm;
    float* Bs = sm + 2 * BM * ASTR;
    const int tid = threadIdx.x, lane = tid & 31, w = tid >> 5;
    const int gid = lane >> 2, l4 = lane & 3;
    const int warpM = w & 3, warpN = w >> 2;
    const int mbase = byy * BM, nbase = bxx * BN;
    const uint32_t sA = (uint32_t)__cvta_generic_to_shared(As);
    const uint32_t sB = (uint32_t)__cvta_generic_to_shared(Bs);

    auto prefetch = [&](int kt, int buf) {
        #pragma unroll
        for (int i = 0; i < 4; i++) {
            int cid = tid + i * 256;
            int m = cid >> 3, kc = cid & 7;
            uint32_t dst = sA + (uint32_t)((buf * BM * ASTR + m * ASTR + kc * 4) * 4);
            const float* src = A + (size_t)(mbase + m) * kD + kbase + kt * BK + kc * 4;
            asm volatile("cp.async.cg.shared.global [%0], [%1], 16;\n" ::"r"(dst), "l"(src));
        }
        #pragma unroll
        for (int i = 0; i < 4; i++) {
            int cid = tid + i * 256;
            int k = cid >> 5, nc = cid & 31;   // full 32 x 128 tile
            uint32_t dst = sB + (uint32_t)((buf * BK * BSTR + k * BSTR + nc * 4) * 4);
            const float* src = W + (size_t)(kbase + kt * BK + k) * kD + nbase + nc * 4;
            asm volatile("cp.async.cg.shared.global [%0], [%1], 16;\n" ::"r"(dst), "l"(src));
        }
        asm volatile("cp.async.commit_group;\n");
    };

    float acc[2][8][4] = {};
    prefetch(0, 0);
    for (int kt = 0; kt < nK; kt++) {
        asm volatile("cp.async.wait_group 0;\n");
        __syncthreads();
        if (kt + 1 < nK) prefetch(kt + 1, (kt + 1) & 1);
        const uint32_t* as = (const uint32_t*)(As + (kt & 1) * BM * ASTR);
        const uint32_t* bs = (const uint32_t*)(Bs + (kt & 1) * BK * BSTR);
        #pragma unroll
        for (int ks = 0; ks < 4; ks++) {
            uint32_t af[2][4];
            #pragma unroll
            for (int mt = 0; mt < 2; mt++) {
                int r = warpM * 32 + mt * 16 + gid;
                const uint32_t* p = as + r * ASTR + ks * 8 + l4;
                af[mt][0] = p[0];
                af[mt][1] = p[8 * ASTR];
                af[mt][2] = p[4];
                af[mt][3] = p[8 * ASTR + 4];
            }
            #pragma unroll
            for (int nt = 0; nt < 8; nt++) {
                uint32_t bf[2];
                int cn = warpN * 64 + nt * 8 + gid;
                const uint32_t* p = bs + (ks * 8 + l4) * BSTR + cn;
                bf[0] = p[0];
                bf[1] = p[4 * BSTR];
                #pragma unroll
                for (int mt = 0; mt < 2; mt++) mma8(acc[mt][nt], af[mt], bf);
            }
        }
        __syncthreads();
    }
    #pragma unroll
    for (int mt = 0; mt < 2; mt++) {
        int r0 = mbase + warpM * 32 + mt * 16 + gid;
        #pragma unroll
        for (int nt = 0; nt < 8; nt++) {
            int cc = nbase + warpN * 64 + nt * 8 + l4 * 2;
            float b0 = bias ? bias[cc] : 0.f;
            float b1 = bias ? bias[cc + 1] : 0.f;
            float2 u = make_float2(acc[mt][nt][0] + b0, acc[mt][nt][1] + b1);
            float2 v = make_float2(acc[mt][nt][2] + b0, acc[mt][nt][3] + b1);
            if (SCATTER) {
                // pre-round to tf32 so attn_k can feed mma without cvt
                u.x = f2tff(u.x); u.y = f2tff(u.y);
                v.x = f2tff(v.x); v.y = f2tff(v.y);
                int bb = r0 / kS, s = r0 - bb * kS;
                int h = cc >> 6, d = cc & 63;
                *(float2*)&C[(((size_t)bb * kH + h) * kS + s) * kDH + d] = u;
                *(float2*)&C[(((size_t)bb * kH + h) * kS + s + 8) * kDH + d] = v;
            } else {
                *(float2*)&C[(size_t)r0 * kD + cc] = u;
                *(float2*)&C[(size_t)(r0 + 8) * kD + cc] = v;
            }
        }
    }
}

// Fused Wq+Wv projections: blockIdx.z selects which GEMM. 256 CTAs.
__global__ void __launch_bounds__(256) gemm_qv(const float* __restrict__ A,
                                               const float* __restrict__ Wq,
                                               const float* __restrict__ bq,
                                               const float* __restrict__ Wv,
                                               const float* __restrict__ bv,
                                               float* __restrict__ Cq,
                                               float* __restrict__ Cv) {
    extern __shared__ float sm[];
    const float* W = blockIdx.z ? Wv : Wq;
    const float* bias = blockIdx.z ? bv : bq;
    float* C = blockIdx.z ? Cv : Cq;
    gemm_body<true>(A, W, bias, C, blockIdx.x, blockIdx.y, 0, kD / BK, sm);
}

// Wo projection, split-K=2 over blockIdx.z: 256 CTAs fill the chip.
__global__ void __launch_bounds__(256) gemm_o(const float* __restrict__ A,
                                              const float* __restrict__ W,
                                              const float* __restrict__ bias,
                                              float* __restrict__ C1,
                                              float* __restrict__ C2) {
    extern __shared__ float sm[];
    const int z = blockIdx.z;
    gemm_body<false>(A, W, z ? nullptr : bias, z ? C2 : C1,
                     blockIdx.x, blockIdx.y, z * (kD / 2), (kD / 2) / BK, sm);
}

// ---------------------------------------------------------------------------
// Gamma attention, 16 query rows per block, 8 warps, 3 CTAs/SM.
// q/v arrive pre-rounded to tf32: operand loads feed mma directly (no cvt).
// Phase 2 uses a 128-col quad-scan to quarter the serial carry chain.
__global__ void __launch_bounds__(ATTN_THREADS, 3) attn_k(const float* __restrict__ gam) {
    extern __shared__ float sc[];                 // [TR][SCP] score rows
    float* red = sc + TR * SCP;                   // [TR][64] phase-3 partials
    float* wstat = red + TR * kDH;                // [TR][8][2] per-warp (m,s)

    const int bx = blockIdx.x;
    const int bh = bx & (kBH - 1);
    const int tile = (NT16 - 1) - (bx >> 5);
    const int h = bh & (kH - 1);
    const int b = bh >> 4;
    const int base = tile * TR;
    const int tid = threadIdx.x, lane = tid & 31, w = tid >> 5;
    const int gid = lane >> 2, l4 = lane & 3;
    const float* qb = g_qh + (size_t)bh * kS * kDH;
    const float* vb = g_vh + (size_t)bh * kS * kDH;
    const int nkt = tile + 1, kLimit = nkt * TR;

    // ---- Phase 1: scores = QK^T / 8 with fused online softmax-1 stats.
    {
        uint32_t qa[8][4];
        #pragma unroll
        for (int ks = 0; ks < 8; ks++) {
            const uint32_t* p = (const uint32_t*)(qb + (size_t)(base + gid) * kDH + ks * 8 + l4);
            qa[ks][0] = p[0];
            qa[ks][1] = p[8 * kDH];
            qa[ks][2] = p[4];
            qa[ks][3] = p[8 * kDH + 4];
        }
        const int i0 = base + gid, i1 = base + gid + 8;  // this lane's rows
        float m0 = -3.4e38f, s0 = 0.f, m1 = -3.4e38f, s1 = 0.f;
        for (int kt = w; kt < nkt; kt += 8) {
            const float* kp = qb + (size_t)kt * TR * kDH;
            float acc[2][4] = {};
            #pragma unroll
            for (int ks = 0; ks < 8; ks++) {
                #pragma unroll
                for (int nt = 0; nt < 2; nt++) {
                    uint32_t bf[2];
                    const uint32_t* p = (const uint32_t*)(kp + (size_t)(nt * 8 + gid) * kDH + ks * 8 + l4);
                    bf[0] = p[0];
                    bf[1] = p[4];
                    mma8(acc[nt], qa[ks], bf);
                }
            }
            const bool diag = (kt == tile);
            #pragma unroll
            for (int nt = 0; nt < 2; nt++) {
                int c0 = kt * TR + nt * 8 + l4 * 2;
                float v00 = acc[nt][0] * 0.125f, v01 = acc[nt][1] * 0.125f;
                float v10 = acc[nt][2] * 0.125f, v11 = acc[nt][3] * 0.125f;
                *(float2*)&sc[gid * SCP + c0] = make_float2(v00, v01);
                *(float2*)&sc[(gid + 8) * SCP + c0] = make_float2(v10, v11);
                if (!diag) {            // all cols strictly below both rows
                    osm(v00, m0, s0); osm(v01, m0, s0);
                    osm(v10, m1, s1); osm(v11, m1, s1);
                } else {                // diagonal tile: mask j < i
                    if (c0 < i0)     osm(v00, m0, s0);
                    if (c0 + 1 < i0) osm(v01, m0, s0);
                    if (c0 < i1)     osm(v10, m1, s1);
                    if (c0 + 1 < i1) osm(v11, m1, s1);
                }
            }
        }
        // quad reduce (lanes sharing gid are l4 = 0..3)
        #pragma unroll
        for (int o = 1; o <= 2; o <<= 1) {
            float om = __shfl_xor_sync(~0u, m0, o), os = __shfl_xor_sync(~0u, s0, o);
            osm_merge(om, os, m0, s0);
            om = __shfl_xor_sync(~0u, m1, o); os = __shfl_xor_sync(~0u, s1, o);
            osm_merge(om, os, m1, s1);
        }
        if (l4 == 0) {
            wstat[(gid * 8 + w) * 2] = m0;
            wstat[(gid * 8 + w) * 2 + 1] = s0;
            wstat[((gid + 8) * 8 + w) * 2] = m1;
            wstat[((gid + 8) * 8 + w) * 2 + 1] = s1;
        }
    }
    __syncthreads();

    // ---- Phase 2: combine stats -> quad-scan decay (online stats2) -> finalize.
    {
        const float gm = -fabsf(gam[h]);
        const int i0r = base + w;
        const int i1r = i0r + 8;
        float* row0 = sc + w * SCP;
        float* row1 = sc + (w + 8) * SCP;
        const int nv0 = i0r, nv1 = i1r;   // strict causal: keys j < i

        // combine the 8 per-warp partials for this warp's two rows
        float m0 = -3.4e38f, s0 = 0.f, m1 = -3.4e38f, s1 = 0.f;
        #pragma unroll
        for (int p = 0; p < 8; p++) {
            osm_merge(wstat[(w * 8 + p) * 2], wstat[(w * 8 + p) * 2 + 1], m0, s0);
            osm_merge(wstat[((w + 8) * 8 + p) * 2], wstat[((w + 8) * 8 + p) * 2 + 1], m1, s1);
        }
        const float inv0 = (nv0 > 0) ? 1.f / s0 : 0.f;
        const float inv1 = 1.f / s1;

        // Pass B: 128-col quad-scan cumsum, decay, store s2, online stats2.
        float carry0 = 0.f, carry1 = 0.f;
        float n0 = -3.4e38f, t0 = 0.f, n1 = -3.4e38f, t1 = 0.f;
        for (int c0 = 0; c0 < nv1; c0 += 128) {
            const int j = c0 + lane * 4;
            if (c0 < nv0) {
                bool v0 = j < nv0, v1 = j + 1 < nv0, v2 = j + 2 < nv0, v3 = j + 3 < nv0;
                float4 sv = *(const float4*)&row0[j];   // smem, in-bounds (SCP pad)
                float p0 = v0 ? __expf(sv.x - m0) * inv0 : 0.f;
                float p1 = v1 ? __expf(sv.y - m0) * inv0 : 0.f;
                float p2 = v2 ? __expf(sv.z - m0) * inv0 : 0.f;
                float p3 = v3 ? __expf(sv.w - m0) * inv0 : 0.f;
                float qs = ((p0 + p1) + p2) + p3;
                float inc = qs;
                #pragma unroll
                for (int o = 1; o < 32; o <<= 1) {
                    float t = __shfl_up_sync(~0u, inc, o);
                    if (lane >= o) inc += t;
                }
                float ncar = __shfl_sync(~0u, inc, 31) + carry0;
                float cum0 = (inc - qs + carry0) + p0;
                float cum1 = cum0 + p1;
                float cum2 = cum1 + p2;
                float cum3 = cum2 + p3;
                carry0 = ncar;
                float e0 = fmaxf(__expf(gm * sqrt_approx(fmaxf((1.f - cum0) * (float)(i0r - j), 0.f))), 1e-5f);
                float e1 = fmaxf(__expf(gm * sqrt_approx(fmaxf((1.f - cum1) * (float)(i0r - j - 1), 0.f))), 1e-5f);
                float e2 = fmaxf(__expf(gm * sqrt_approx(fmaxf((1.f - cum2) * (float)(i0r - j - 2), 0.f))), 1e-5f);
                float e3 = fmaxf(__expf(gm * sqrt_approx(fmaxf((1.f - cum3) * (float)(i0r - j - 3), 0.f))), 1e-5f);
                float4 s2 = make_float4(sv.x * e0, sv.y * e1, sv.z * e2, sv.w * e3);
                *(float4*)&row0[j] = s2;
                if (v0) osm(s2.x, n0, t0);
                if (v1) osm(s2.y, n0, t0);
                if (v2) osm(s2.z, n0, t0);
                if (v3) osm(s2.w, n0, t0);
            }
            {
                bool v0 = j < nv1, v1 = j + 1 < nv1, v2 = j + 2 < nv1, v3 = j + 3 < nv1;
                float4 sv = *(const float4*)&row1[j];
                float p0 = v0 ? __expf(sv.x - m1) * inv1 : 0.f;
                float p1 = v1 ? __expf(sv.y - m1) * inv1 : 0.f;
                float p2 = v2 ? __expf(sv.z - m1) * inv1 : 0.f;
                float p3 = v3 ? __expf(sv.w - m1) * inv1 : 0.f;
                float qs = ((p0 + p1) + p2) + p3;
                float inc = qs;
                #pragma unroll
                for (int o = 1; o < 32; o <<= 1) {
                    float t = __shfl_up_sync(~0u, inc, o);
                    if (lane >= o) inc += t;
                }
                float ncar = __shfl_sync(~0u, inc, 31) + carry1;
                float cum0 = (inc - qs + carry1) + p0;
                float cum1 = cum0 + p1;
                float cum2 = cum1 + p2;
                float cum3 = cum2 + p3;
                carry1 = ncar;
                float e0 = fmaxf(__expf(gm * sqrt_approx(fmaxf((1.f - cum0) * (float)(i1r - j), 0.f))), 1e-5f);
                float e1 = fmaxf(__expf(gm * sqrt_approx(fmaxf((1.f - cum1) * (float)(i1r - j - 1), 0.f))), 1e-5f);
                float e2 = fmaxf(__expf(gm * sqrt_approx(fmaxf((1.f - cum2) * (float)(i1r - j - 2), 0.f))), 1e-5f);
                float e3 = fmaxf(__expf(gm * sqrt_approx(fmaxf((1.f - cum3) * (float)(i1r - j - 3), 0.f))), 1e-5f);
                float4 s2 = make_float4(sv.x * e0, sv.y * e1, sv.z * e2, sv.w * e3);
                *(float4*)&row1[j] = s2;
                if (v0) osm(s2.x, n1, t1);
                if (v1) osm(s2.y, n1, t1);
                if (v2) osm(s2.z, n1, t1);
                if (v3) osm(s2.w, n1, t1);
            }
        }
        #pragma unroll
        for (int o = 16; o; o >>= 1) {
            float om = __shfl_xor_sync(~0u, n0, o), os = __shfl_xor_sync(~0u, t0, o);
            osm_merge(om, os, n0, t0);
            om = __shfl_xor_sync(~0u, n1, o); os = __shfl_xor_sync(~0u, t1, o);
            osm_merge(om, os, n1, t1);
        }
        // maxout: max(attn) = 1/sum2 exactly => scale = min(sum2,5)/sum2
        const float sf0 = (nv0 > 0) ? fminf(t0, 5.f) / t0 : 0.f;
        const float sf1 = fminf(t1, 5.f) / t1;

        // Pass C: finalize attn values as tf32 bits (float4), zero causal tail.
        for (int c0 = 0; c0 < kLimit; c0 += 128) {
            const int j = c0 + lane * 4;
            if (j < kLimit) {       // kLimit % 16 == 0 -> whole quad valid
                float4 a = *(const float4*)&row0[j];
                float4 c = *(const float4*)&row1[j];
                float4 o0, o1;
                o0.x = (j < nv0)     ? f2tff(__expf(a.x - n0) * sf0) : 0.f;
                o0.y = (j + 1 < nv0) ? f2tff(__expf(a.y - n0) * sf0) : 0.f;
                o0.z = (j + 2 < nv0) ? f2tff(__expf(a.z - n0) * sf0) : 0.f;
                o0.w = (j + 3 < nv0) ? f2tff(__expf(a.w - n0) * sf0) : 0.f;
                o1.x = (j < nv1)     ? f2tff(__expf(c.x - n1) * sf1) : 0.f;
                o1.y = (j + 1 < nv1) ? f2tff(__expf(c.y - n1) * sf1) : 0.f;
                o1.z = (j + 2 < nv1) ? f2tff(__expf(c.z - n1) * sf1) : 0.f;
                o1.w = (j + 3 < nv1) ? f2tff(__expf(c.w - n1) * sf1) : 0.f;
                *(float4*)&row0[j] = o0;
                *(float4*)&row1[j] = o1;
            }
        }
    }
    __syncthreads();

    // ---- Phase 3: out = attn @ V. 4 column groups (16 cols) x 2 kt halves.
    // Output to g_ao pre-rounded tf32 (gemm_o's A operand).
    {
        const int cg = w & 3;          // cols [cg*16, cg*16+16)
        const int half = w >> 2;       // kt parity
        float oacc[2][4] = {};
        #pragma unroll 2
        for (int kt = half; kt < nkt; kt += 2) {
            const float* vp = vb + (size_t)kt * TR * kDH;
            #pragma unroll
            for (int kk = 0; kk < 2; kk++) {
                uint32_t af[4];
                const uint32_t* q = (const uint32_t*)(sc + gid * SCP + kt * TR + kk * 8 + l4);
                af[0] = q[0];
                af[1] = q[8 * SCP];
                af[2] = q[4];
                af[3] = q[8 * SCP + 4];
                #pragma unroll
                for (int nt = 0; nt < 2; nt++) {
                    uint32_t bf[2];
                    const uint32_t* p = (const uint32_t*)(vp + (size_t)(kk * 8 + l4) * kDH + cg * 16 + nt * 8 + gid);
                    bf[0] = p[0];
                    bf[1] = p[4 * kDH];
                    mma8(oacc[nt], af, bf);
                }
            }
        }
        if (half == 1) {
            #pragma unroll
            for (int nt = 0; nt < 2; nt++) {
                int cc = cg * 16 + nt * 8 + l4 * 2;
                *(float2*)&red[gid * kDH + cc] = make_float2(oacc[nt][0], oacc[nt][1]);
                *(float2*)&red[(gid + 8) * kDH + cc] = make_float2(oacc[nt][2], oacc[nt][3]);
            }
        }
        __syncthreads();
        if (half == 0) {
            const int i0 = base + gid;
            float* op0 = g_ao + ((size_t)b * kS + i0) * kD + h * kDH;
            #pragma unroll
            for (int nt = 0; nt < 2; nt++) {
                int cc = cg * 16 + nt * 8 + l4 * 2;
                float2 p0 = *(const float2*)&red[gid * kDH + cc];
                float2 p1 = *(const float2*)&red[(gid + 8) * kDH + cc];
                *(float2*)(op0 + cc) =
                    make_float2(f2tff(oacc[nt][0] + p0.x), f2tff(oacc[nt][1] + p0.y));
                *(float2*)(op0 + 8 * kD + cc) =
                    make_float2(f2tff(oacc[nt][2] + p1.x), f2tff(oacc[nt][3] + p1.y));
            }
        }
    }
}

// ---------------------------------------------------------------------------
// LayerNorm with NADD extra addends: out = LN(X (+A1) (+A2)) * g + b.
// TFOUT: also write tf32-rounded copy (next layer's GEMM A operand).
template<int NADD, bool TFOUT>
__global__ void __launch_bounds__(256) ln_k(const float* __restrict__ X,
                                            const float* __restrict__ A1,
                                            const float* __restrict__ A2,
                                            const float* __restrict__ g,
                                            const float* __restrict__ bt,
                                            float* __restrict__ out,
                                            float* __restrict__ out_tf) {
    __shared__ float red[8];
    const int row = blockIdx.x;
    const int tid = threadIdx.x;
    const int lane = tid & 31, w = tid >> 5;
    const float* xr = X + (size_t)row * kD;
    float v[4];
    float s = 0.f;
    #pragma unroll
    for (int t = 0; t < 4; t++) {
        int d = tid + t * 256;
        float val = xr[d];
        if (NADD >= 1) val += A1[(size_t)row * kD + d];
        if (NADD >= 2) val += A2[(size_t)row * kD + d];
        v[t] = val;
        s += val;
    }
    #pragma unroll
    for (int o = 16; o; o >>= 1) s += __shfl_xor_sync(~0u, s, o);
    if (lane == 0) red[w] = s;
    __syncthreads();
    float tot = 0.f;
    #pragma unroll
    for (int k = 0; k < 8; k++) tot += red[k];
    const float mu = tot * (1.0f / kD);
    __syncthreads();
    float s2 = 0.f;
    #pragma unroll
    for (int t = 0; t < 4; t++) { float dv = v[t] - mu; s2 += dv * dv; }
    #pragma unroll
    for (int o = 16; o; o >>= 1) s2 += __shfl_xor_sync(~0u, s2, o);
    if (lane == 0) red[w] = s2;
    __syncthreads();
    float tot2 = 0.f;
    #pragma unroll
    for (int k = 0; k < 8; k++) tot2 += red[k];
    const float rs = rsqrtf(tot2 * (1.0f / kD) + 1e-5f);
    #pragma unroll
    for (int t = 0; t < 4; t++) {
        int d = tid + t * 256;
        float r = (v[t] - mu) * rs * g[d] + bt[d];
        out[(size_t)row * kD + d] = r;
        if (TFOUT) out_tf[(size_t)row * kD + d] = f2tff(r);
    }
}

// ---------------------------------------------------------------------------
extern "C" void kernel_launch(void* const* d_in, const int* in_sizes, int n_in,
                              void* d_out, int out_size) {
    (void)in_sizes; (void)n_in; (void)out_size;
    const float* q   = (const float*)d_in[0];
    // d_in[1] = lens (unused in eval mode)
    const float* Wq  = (const float*)d_in[2];
    const float* bq  = (const float*)d_in[3];
    const float* Wv  = (const float*)d_in[4];
    const float* bv  = (const float*)d_in[5];
    const float* Wo  = (const float*)d_in[6];
    const float* bo  = (const float*)d_in[7];
    const float* gm  = (const float*)d_in[8];
    const float* lng = (const float*)d_in[9];
    const float* lnb = (const float*)d_in[10];
    const float* fg  = (const float*)d_in[11];
    const float* fb  = (const float*)d_in[12];
    float* out = (float*)d_out;

    cudaFuncSetAttribute(attn_k, cudaFuncAttributeMaxDynamicSharedMemorySize, ATTN_SMEM);
    cudaFuncSetAttribute(gemm_qv, cudaFuncAttributeMaxDynamicSharedMemorySize, GEMM_SMEM);
    cudaFuncSetAttribute(gemm_o,  cudaFuncAttributeMaxDynamicSharedMemorySize, GEMM_SMEM);

    void* p;
    float *xg, *xt, *qhg, *vhg, *aog, *pjg, *pjg2, *wt;
    cudaGetSymbolAddress(&p, g_x);     xg   = (float*)p;
    cudaGetSymbolAddress(&p, g_xt);    xt   = (float*)p;
    cudaGetSymbolAddress(&p, g_qh);    qhg  = (float*)p;
    cudaGetSymbolAddress(&p, g_vh);    vhg  = (float*)p;
    cudaGetSymbolAddress(&p, g_ao);    aog  = (float*)p;
    cudaGetSymbolAddress(&p, g_proj);  pjg  = (float*)p;
    cudaGetSymbolAddress(&p, g_proj2); pjg2 = (float*)p;
    cudaGetSymbolAddress(&p, g_wt);    wt   = (float*)p;

    // Pre-round all GEMM operands once: weights + layer-0 input.
    {
        size_t total4 = 3 * (kWSZ / 4) + (size_t)kBS * kD / 4;
        int blocks = (int)((total4 + 255) / 256);
        round_all<<<blocks, 256>>>(q, Wq, Wv, Wo);
    }
    float* wqt = wt;
    float* wvt = wt + kWSZ;
    float* wot = wt + 2 * kWSZ;

    dim3 gqv(kD / BN, kBS / BM, 2);  // (8, 16, 2) = 256 CTAs
    dim3 ggo(kD / BN, kBS / BM, 2);  // (8, 16, 2) = 256 CTAs (split-K)
    for (int l = 0; l < kL; l++) {
        const float* xin = (l == 0) ? q : xg;   // fp32 residual input
        gemm_qv<<<gqv, 256, GEMM_SMEM>>>(xt,
            wqt + (size_t)l * kD * kD, bq + l * kD,
            wvt + (size_t)l * kD * kD, bv + l * kD, qhg, vhg);
        attn_k<<<kBH * NT16, ATTN_THREADS, ATTN_SMEM>>>(gm + l * kH);
        gemm_o<<<ggo, 256, GEMM_SMEM>>>(aog, wot + (size_t)l * kD * kD, bo + l * kD,
                                        pjg, pjg2);
        if (l + 1 < kL)
            ln_k<2, true ><<<kBS, 256>>>(xin, pjg, pjg2, lng + l * kD, lnb + l * kD, xg, xt);
        else
            ln_k<2, false><<<kBS, 256>>>(xin, pjg, pjg2, lng + l * kD, lnb + l * kD, xg, nullptr);
    }
    ln_k<0, false><<<kBS, 256>>>(xg, nullptr, nullptr, fg, fb, out, nullptr);
}

// round 15
// speedup vs baseline: 1.2076x; 1.0018x over previous
#include <cuda_runtime.h>
#include <math.h>
#include <stdint.h>

namespace {
constexpr int kBn = 2, kS = 1024, kD = 1024, kH = 16, kDH = 64, kL = 4;
constexpr int kBS = kBn * kS;          // 2048 rows
constexpr int kBH = kBn * kH;          // 32 (b,h) pairs
constexpr int TR = 16;                 // query rows per attention block
constexpr int NT16 = kS / TR;          // 64 tiles per (b,h)
constexpr int SCP = 1028;              // padded score-row stride (%4==0, %32==4)
constexpr int ATTN_THREADS = 256;      // 8 warps
constexpr int ATTN_SMEM = (TR * SCP + TR * kDH + TR * 8 * 2) * 4;  // 70912 B
// GEMM tiling: 128x128 block, 8 warps of 32x64, 3-stage cp.async pipeline
constexpr int BM = 128, BN = 128, BK = 32;
constexpr int ASTR = 36, BSTR = 136;   // padded smem strides
constexpr int GEMM_SMEM = 3 * (BM * ASTR + BK * BSTR) * 4;  // 107520 B
constexpr size_t kWSZ = (size_t)kL * kD * kD;    // floats per weight set
}

// Scratch (static device allocations; no runtime allocs)
__device__ float g_x[kBS * kD];          // fp32 activations (residual path)
__device__ float g_xt[kBS * kD];         // tf32-rounded activations (GEMM A)
__device__ float g_qh[kBH * kS * kDH];   // tf32-rounded q heads (also keys)
__device__ float g_vh[kBH * kS * kDH];   // tf32-rounded v heads
__device__ float g_ao[kBS * kD];         // tf32-rounded attention output
__device__ float g_proj[kBS * kD];
__device__ float g_proj2[kBS * kD];      // split-K partial for gemm_o
__device__ float g_wt[3 * kWSZ];         // tf32-rounded Wq|Wv|Wo (all layers)

// ---------------------------------------------------------------------------
__device__ __forceinline__ uint32_t f2tf(float x) {
    uint32_t r;
    asm("cvt.rna.tf32.f32 %0, %1;" : "=r"(r) : "f"(x));
    return r;
}
__device__ __forceinline__ float f2tff(float x) { return __uint_as_float(f2tf(x)); }
__device__ __forceinline__ float sqrt_approx(float x) {
    float r;
    asm("sqrt.approx.f32 %0, %1;" : "=f"(r) : "f"(x));
    return r;
}
__device__ __forceinline__ void mma8(float* d, const uint32_t* a, const uint32_t* b) {
    asm volatile(
        "mma.sync.aligned.m16n8k8.row.col.f32.tf32.tf32.f32 "
        "{%0,%1,%2,%3}, {%4,%5,%6,%7}, {%8,%9}, {%0,%1,%2,%3};\n"
        : "+f"(d[0]), "+f"(d[1]), "+f"(d[2]), "+f"(d[3])
        : "r"(a[0]), "r"(a[1]), "r"(a[2]), "r"(a[3]), "r"(b[0]), "r"(b[1]));
}
// online softmax accumulate
__device__ __forceinline__ void osm(float v, float& m, float& s) {
    if (v > m) { s = s * __expf(m - v) + 1.f; m = v; }
    else       s += __expf(v - m);
}
// merge two (m,s) online-softmax states
__device__ __forceinline__ void osm_merge(float om, float os, float& m, float& s) {
    float nm = fmaxf(m, om);
    s = s * __expf(m - nm) + os * __expf(om - nm);
    m = nm;
}

// ---------------------------------------------------------------------------
// Pre-round all GEMM operands to tf32 in one pass: Wq|Wv|Wo -> g_wt, q -> g_xt.
__global__ void __launch_bounds__(256) round_all(const float* __restrict__ q,
                                                 const float* __restrict__ Wq,
                                                 const float* __restrict__ Wv,
                                                 const float* __restrict__ Wo) {
    const size_t w4 = kWSZ / 4;            // float4 per weight set
    const size_t x4 = (size_t)kBS * kD / 4;
    size_t i = (size_t)blockIdx.x * 256 + threadIdx.x;
    const float4* src;
    float4* dst;
    size_t off;
    if (i < w4)            { src = (const float4*)Wq; dst = (float4*)g_wt;            off = i; }
    else if (i < 2 * w4)   { src = (const float4*)Wv; dst = (float4*)(g_wt + kWSZ);   off = i - w4; }
    else if (i < 3 * w4)   { src = (const float4*)Wo; dst = (float4*)(g_wt + 2*kWSZ); off = i - 2*w4; }
    else if (i < 3*w4+x4)  { src = (const float4*)q;  dst = (float4*)g_xt;            off = i - 3*w4; }
    else return;
    float4 v = src[off];
    v.x = f2tff(v.x); v.y = f2tff(v.y); v.z = f2tff(v.z); v.w = f2tff(v.w);
    dst[off] = v;
}

// ---------------------------------------------------------------------------
// Shared GEMM body: C = A[:, kbase:+nK*BK] @ W + (bias). Operands tf32 in
// memory (no cvt in inner loop). 3-stage cp.async pipeline: two tiles in
// flight; one __syncthreads per iteration.
template<bool SCATTER>
__device__ __forceinline__ void gemm_body(const float* __restrict__ A,
                                          const float* __restrict__ W,
                                          const float* __restrict__ bias,
                                          float* __restrict__ C,
                                          int bxx, int byy, int kbase, int nK,
                                          float* sm) {
    float* As = sm;                          // 3 * BM*ASTR
    float* Bs = sm + 3 * BM * ASTR;          // 3 * BK*BSTR
    const int tid = threadIdx.x, lane = tid & 31, w = tid >> 5;
    const int gid = lane >> 2, l4 = lane & 3;
    const int warpM = w & 3, warpN = w >> 2;
    const int mbase = byy * BM, nbase = bxx * BN;
    const uint32_t sA = (uint32_t)__cvta_generic_to_shared(As);
    const uint32_t sB = (uint32_t)__cvta_generic_to_shared(Bs);

    auto prefetch = [&](int kt, int buf) {
        #pragma unroll
        for (int i = 0; i < 4; i++) {
            int cid = tid + i * 256;
            int m = cid >> 3, kc = cid & 7;
            uint32_t dst = sA + (uint32_t)((buf * BM * ASTR + m * ASTR + kc * 4) * 4);
            const float* src = A + (size_t)(mbase + m) * kD + kbase + kt * BK + kc * 4;
            asm volatile("cp.async.cg.shared.global [%0], [%1], 16;\n" ::"r"(dst), "l"(src));
        }
        #pragma unroll
        for (int i = 0; i < 4; i++) {
            int cid = tid + i * 256;
            int k = cid >> 5, nc = cid & 31;   // full 32 x 128 tile
            uint32_t dst = sB + (uint32_t)((buf * BK * BSTR + k * BSTR + nc * 4) * 4);
            const float* src = W + (size_t)(kbase + kt * BK + k) * kD + nbase + nc * 4;
            asm volatile("cp.async.cg.shared.global [%0], [%1], 16;\n" ::"r"(dst), "l"(src));
        }
        asm volatile("cp.async.commit_group;\n");
    };

    float acc[2][8][4] = {};
    prefetch(0, 0);
    if (nK > 1) prefetch(1, 1);
    int cur = 0;                              // buffer index = kt % 3
    for (int kt = 0; kt < nK; kt++) {
        if (kt + 1 < nK) asm volatile("cp.async.wait_group 1;\n");
        else             asm volatile("cp.async.wait_group 0;\n");
        __syncthreads();
        if (kt + 2 < nK) {
            int nb = cur + 2; if (nb >= 3) nb -= 3;
            prefetch(kt + 2, nb);
        }
        const uint32_t* as = (const uint32_t*)(As + cur * BM * ASTR);
        const uint32_t* bs = (const uint32_t*)(Bs + cur * BK * BSTR);
        #pragma unroll
        for (int ks = 0; ks < 4; ks++) {
            uint32_t af[2][4];
            #pragma unroll
            for (int mt = 0; mt < 2; mt++) {
                int r = warpM * 32 + mt * 16 + gid;
                const uint32_t* p = as + r * ASTR + ks * 8 + l4;
                af[mt][0] = p[0];
                af[mt][1] = p[8 * ASTR];
                af[mt][2] = p[4];
                af[mt][3] = p[8 * ASTR + 4];
            }
            #pragma unroll
            for (int nt = 0; nt < 8; nt++) {
                uint32_t bf[2];
                int cn = warpN * 64 + nt * 8 + gid;
                const uint32_t* p = bs + (ks * 8 + l4) * BSTR + cn;
                bf[0] = p[0];
                bf[1] = p[4 * BSTR];
                #pragma unroll
                for (int mt = 0; mt < 2; mt++) mma8(acc[mt][nt], af[mt], bf);
            }
        }
        if (++cur == 3) cur = 0;
    }
    __syncthreads();
    #pragma unroll
    for (int mt = 0; mt < 2; mt++) {
        int r0 = mbase + warpM * 32 + mt * 16 + gid;
        #pragma unroll
        for (int nt = 0; nt < 8; nt++) {
            int cc = nbase + warpN * 64 + nt * 8 + l4 * 2;
            float b0 = bias ? bias[cc] : 0.f;
            float b1 = bias ? bias[cc + 1] : 0.f;
            float2 u = make_float2(acc[mt][nt][0] + b0, acc[mt][nt][1] + b1);
            float2 v = make_float2(acc[mt][nt][2] + b0, acc[mt][nt][3] + b1);
            if (SCATTER) {
                // pre-round to tf32 so attn_k can feed mma without cvt
                u.x = f2tff(u.x); u.y = f2tff(u.y);
                v.x = f2tff(v.x); v.y = f2tff(v.y);
                int bb = r0 / kS, s = r0 - bb * kS;
                int h = cc >> 6, d = cc & 63;
                *(float2*)&C[(((size_t)bb * kH + h) * kS + s) * kDH + d] = u;
                *(float2*)&C[(((size_t)bb * kH + h) * kS + s + 8) * kDH + d] = v;
            } else {
                *(float2*)&C[(size_t)r0 * kD + cc] = u;
                *(float2*)&C[(size_t)(r0 + 8) * kD + cc] = v;
            }
        }
    }
}

// Fused Wq+Wv projections: blockIdx.z selects which GEMM. 256 CTAs.
__global__ void __launch_bounds__(256) gemm_qv(const float* __restrict__ A,
                                               const float* __restrict__ Wq,
                                               const float* __restrict__ bq,
                                               const float* __restrict__ Wv,
                                               const float* __restrict__ bv,
                                               float* __restrict__ Cq,
                                               float* __restrict__ Cv) {
    extern __shared__ float sm[];
    const float* W = blockIdx.z ? Wv : Wq;
    const float* bias = blockIdx.z ? bv : bq;
    float* C = blockIdx.z ? Cv : Cq;
    gemm_body<true>(A, W, bias, C, blockIdx.x, blockIdx.y, 0, kD / BK, sm);
}

// Wo projection, split-K=2 over blockIdx.z: 256 CTAs fill the chip.
__global__ void __launch_bounds__(256) gemm_o(const float* __restrict__ A,
                                              const float* __restrict__ W,
                                              const float* __restrict__ bias,
                                              float* __restrict__ C1,
                                              float* __restrict__ C2) {
    extern __shared__ float sm[];
    const int z = blockIdx.z;
    gemm_body<false>(A, W, z ? nullptr : bias, z ? C2 : C1,
                     blockIdx.x, blockIdx.y, z * (kD / 2), (kD / 2) / BK, sm);
}

// ---------------------------------------------------------------------------
// Gamma attention, 16 query rows per block, 8 warps, 3 CTAs/SM.
// q/v arrive pre-rounded to tf32: operand loads feed mma directly (no cvt).
// Phase 2 uses a 128-col quad-scan to quarter the serial carry chain.
__global__ void __launch_bounds__(ATTN_THREADS, 3) attn_k(const float* __restrict__ gam) {
    extern __shared__ float sc[];                 // [TR][SCP] score rows
    float* red = sc + TR * SCP;                   // [TR][64] phase-3 partials
    float* wstat = red + TR * kDH;                // [TR][8][2] per-warp (m,s)

    const int bx = blockIdx.x;
    const int bh = bx & (kBH - 1);
    const int tile = (NT16 - 1) - (bx >> 5);
    const int h = bh & (kH - 1);
    const int b = bh >> 4;
    const int base = tile * TR;
    const int tid = threadIdx.x, lane = tid & 31, w = tid >> 5;
    const int gid = lane >> 2, l4 = lane & 3;
    const float* qb = g_qh + (size_t)bh * kS * kDH;
    const float* vb = g_vh + (size_t)bh * kS * kDH;
    const int nkt = tile + 1, kLimit = nkt * TR;

    // ---- Phase 1: scores = QK^T / 8 with fused online softmax-1 stats.
    {
        uint32_t qa[8][4];
        #pragma unroll
        for (int ks = 0; ks < 8; ks++) {
            const uint32_t* p = (const uint32_t*)(qb + (size_t)(base + gid) * kDH + ks * 8 + l4);
            qa[ks][0] = p[0];
            qa[ks][1] = p[8 * kDH];
            qa[ks][2] = p[4];
            qa[ks][3] = p[8 * kDH + 4];
        }
        const int i0 = base + gid, i1 = base + gid + 8;  // this lane's rows
        float m0 = -3.4e38f, s0 = 0.f, m1 = -3.4e38f, s1 = 0.f;
        for (int kt = w; kt < nkt; kt += 8) {
            const float* kp = qb + (size_t)kt * TR * kDH;
            float acc[2][4] = {};
            #pragma unroll
            for (int ks = 0; ks < 8; ks++) {
                #pragma unroll
                for (int nt = 0; nt < 2; nt++) {
                    uint32_t bf[2];
                    const uint32_t* p = (const uint32_t*)(kp + (size_t)(nt * 8 + gid) * kDH + ks * 8 + l4);
                    bf[0] = p[0];
                    bf[1] = p[4];
                    mma8(acc[nt], qa[ks], bf);
                }
            }
            const bool diag = (kt == tile);
            #pragma unroll
            for (int nt = 0; nt < 2; nt++) {
                int c0 = kt * TR + nt * 8 + l4 * 2;
                float v00 = acc[nt][0] * 0.125f, v01 = acc[nt][1] * 0.125f;
                float v10 = acc[nt][2] * 0.125f, v11 = acc[nt][3] * 0.125f;
                *(float2*)&sc[gid * SCP + c0] = make_float2(v00, v01);
                *(float2*)&sc[(gid + 8) * SCP + c0] = make_float2(v10, v11);
                if (!diag) {            // all cols strictly below both rows
                    osm(v00, m0, s0); osm(v01, m0, s0);
                    osm(v10, m1, s1); osm(v11, m1, s1);
                } else {                // diagonal tile: mask j < i
                    if (c0 < i0)     osm(v00, m0, s0);
                    if (c0 + 1 < i0) osm(v01, m0, s0);
                    if (c0 < i1)     osm(v10, m1, s1);
                    if (c0 + 1 < i1) osm(v11, m1, s1);
                }
            }
        }
        // quad reduce (lanes sharing gid are l4 = 0..3)
        #pragma unroll
        for (int o = 1; o <= 2; o <<= 1) {
            float om = __shfl_xor_sync(~0u, m0, o), os = __shfl_xor_sync(~0u, s0, o);
            osm_merge(om, os, m0, s0);
            om = __shfl_xor_sync(~0u, m1, o); os = __shfl_xor_sync(~0u, s1, o);
            osm_merge(om, os, m1, s1);
        }
        if (l4 == 0) {
            wstat[(gid * 8 + w) * 2] = m0;
            wstat[(gid * 8 + w) * 2 + 1] = s0;
            wstat[((gid + 8) * 8 + w) * 2] = m1;
            wstat[((gid + 8) * 8 + w) * 2 + 1] = s1;
        }
    }
    __syncthreads();

    // ---- Phase 2: combine stats -> quad-scan decay (online stats2) -> finalize.
    {
        const float gm = -fabsf(gam[h]);
        const int i0r = base + w;
        const int i1r = i0r + 8;
        float* row0 = sc + w * SCP;
        float* row1 = sc + (w + 8) * SCP;
        const int nv0 = i0r, nv1 = i1r;   // strict causal: keys j < i

        // combine the 8 per-warp partials for this warp's two rows
        float m0 = -3.4e38f, s0 = 0.f, m1 = -3.4e38f, s1 = 0.f;
        #pragma unroll
        for (int p = 0; p < 8; p++) {
            osm_merge(wstat[(w * 8 + p) * 2], wstat[(w * 8 + p) * 2 + 1], m0, s0);
            osm_merge(wstat[((w + 8) * 8 + p) * 2], wstat[((w + 8) * 8 + p) * 2 + 1], m1, s1);
        }
        const float inv0 = (nv0 > 0) ? 1.f / s0 : 0.f;
        const float inv1 = 1.f / s1;

        // Pass B: 128-col quad-scan cumsum, decay, store s2, online stats2.
        float carry0 = 0.f, carry1 = 0.f;
        float n0 = -3.4e38f, t0 = 0.f, n1 = -3.4e38f, t1 = 0.f;
        for (int c0 = 0; c0 < nv1; c0 += 128) {
            const int j = c0 + lane * 4;
            if (c0 < nv0) {
                bool v0 = j < nv0, v1 = j + 1 < nv0, v2 = j + 2 < nv0, v3 = j + 3 < nv0;
                float4 sv = *(const float4*)&row0[j];   // smem, in-bounds (SCP pad)
                float p0 = v0 ? __expf(sv.x - m0) * inv0 : 0.f;
                float p1 = v1 ? __expf(sv.y - m0) * inv0 : 0.f;
                float p2 = v2 ? __expf(sv.z - m0) * inv0 : 0.f;
                float p3 = v3 ? __expf(sv.w - m0) * inv0 : 0.f;
                float qs = ((p0 + p1) + p2) + p3;
                float inc = qs;
                #pragma unroll
                for (int o = 1; o < 32; o <<= 1) {
                    float t = __shfl_up_sync(~0u, inc, o);
                    if (lane >= o) inc += t;
                }
                float ncar = __shfl_sync(~0u, inc, 31) + carry0;
                float cum0 = (inc - qs + carry0) + p0;
                float cum1 = cum0 + p1;
                float cum2 = cum1 + p2;
                float cum3 = cum2 + p3;
                carry0 = ncar;
                float e0 = fmaxf(__expf(gm * sqrt_approx(fmaxf((1.f - cum0) * (float)(i0r - j), 0.f))), 1e-5f);
                float e1 = fmaxf(__expf(gm * sqrt_approx(fmaxf((1.f - cum1) * (float)(i0r - j - 1), 0.f))), 1e-5f);
                float e2 = fmaxf(__expf(gm * sqrt_approx(fmaxf((1.f - cum2) * (float)(i0r - j - 2), 0.f))), 1e-5f);
                float e3 = fmaxf(__expf(gm * sqrt_approx(fmaxf((1.f - cum3) * (float)(i0r - j - 3), 0.f))), 1e-5f);
                float4 s2 = make_float4(sv.x * e0, sv.y * e1, sv.z * e2, sv.w * e3);
                *(float4*)&row0[j] = s2;
                if (v0) osm(s2.x, n0, t0);
                if (v1) osm(s2.y, n0, t0);
                if (v2) osm(s2.z, n0, t0);
                if (v3) osm(s2.w, n0, t0);
            }
            {
                bool v0 = j < nv1, v1 = j + 1 < nv1, v2 = j + 2 < nv1, v3 = j + 3 < nv1;
                float4 sv = *(const float4*)&row1[j];
                float p0 = v0 ? __expf(sv.x - m1) * inv1 : 0.f;
                float p1 = v1 ? __expf(sv.y - m1) * inv1 : 0.f;
                float p2 = v2 ? __expf(sv.z - m1) * inv1 : 0.f;
                float p3 = v3 ? __expf(sv.w - m1) * inv1 : 0.f;
                float qs = ((p0 + p1) + p2) + p3;
                float inc = qs;
                #pragma unroll
                for (int o = 1; o < 32; o <<= 1) {
                    float t = __shfl_up_sync(~0u, inc, o);
                    if (lane >= o) inc += t;
                }
                float ncar = __shfl_sync(~0u, inc, 31) + carry1;
                float cum0 = (inc - qs + carry1) + p0;
                float cum1 = cum0 + p1;
                float cum2 = cum1 + p2;
                float cum3 = cum2 + p3;
                carry1 = ncar;
                float e0 = fmaxf(__expf(gm * sqrt_approx(fmaxf((1.f - cum0) * (float)(i1r - j), 0.f))), 1e-5f);
                float e1 = fmaxf(__expf(gm * sqrt_approx(fmaxf((1.f - cum1) * (float)(i1r - j - 1), 0.f))), 1e-5f);
                float e2 = fmaxf(__expf(gm * sqrt_approx(fmaxf((1.f - cum2) * (float)(i1r - j - 2), 0.f))), 1e-5f);
                float e3 = fmaxf(__expf(gm * sqrt_approx(fmaxf((1.f - cum3) * (float)(i1r - j - 3), 0.f))), 1e-5f);
                float4 s2 = make_float4(sv.x * e0, sv.y * e1, sv.z * e2, sv.w * e3);
                *(float4*)&row1[j] = s2;
                if (v0) osm(s2.x, n1, t1);
                if (v1) osm(s2.y, n1, t1);
                if (v2) osm(s2.z, n1, t1);
                if (v3) osm(s2.w, n1, t1);
            }
        }
        #pragma unroll
        for (int o = 16; o; o >>= 1) {
            float om = __shfl_xor_sync(~0u, n0, o), os = __shfl_xor_sync(~0u, t0, o);
            osm_merge(om, os, n0, t0);
            om = __shfl_xor_sync(~0u, n1, o); os = __shfl_xor_sync(~0u, t1, o);
            osm_merge(om, os, n1, t1);
        }
        // maxout: max(attn) = 1/sum2 exactly => scale = min(sum2,5)/sum2
        const float sf0 = (nv0 > 0) ? fminf(t0, 5.f) / t0 : 0.f;
        const float sf1 = fminf(t1, 5.f) / t1;

        // Pass C: finalize attn values as tf32 bits (float4), zero causal tail.
        for (int c0 = 0; c0 < kLimit; c0 += 128) {
            const int j = c0 + lane * 4;
            if (j < kLimit) {       // kLimit % 16 == 0 -> whole quad valid
                float4 a = *(const float4*)&row0[j];
                float4 c = *(const float4*)&row1[j];
                float4 o0, o1;
                o0.x = (j < nv0)     ? f2tff(__expf(a.x - n0) * sf0) : 0.f;
                o0.y = (j + 1 < nv0) ? f2tff(__expf(a.y - n0) * sf0) : 0.f;
                o0.z = (j + 2 < nv0) ? f2tff(__expf(a.z - n0) * sf0) : 0.f;
                o0.w = (j + 3 < nv0) ? f2tff(__expf(a.w - n0) * sf0) : 0.f;
                o1.x = (j < nv1)     ? f2tff(__expf(c.x - n1) * sf1) : 0.f;
                o1.y = (j + 1 < nv1) ? f2tff(__expf(c.y - n1) * sf1) : 0.f;
                o1.z = (j + 2 < nv1) ? f2tff(__expf(c.z - n1) * sf1) : 0.f;
                o1.w = (j + 3 < nv1) ? f2tff(__expf(c.w - n1) * sf1) : 0.f;
                *(float4*)&row0[j] = o0;
                *(float4*)&row1[j] = o1;
            }
        }
    }
    __syncthreads();

    // ---- Phase 3: out = attn @ V. 4 column groups (16 cols) x 2 kt halves.
    // Output to g_ao pre-rounded tf32 (gemm_o's A operand).
    {
        const int cg = w & 3;          // cols [cg*16, cg*16+16)
        const int half = w >> 2;       // kt parity
        float oacc[2][4] = {};
        #pragma unroll 2
        for (int kt = half; kt < nkt; kt += 2) {
            const float* vp = vb + (size_t)kt * TR * kDH;
            #pragma unroll
            for (int kk = 0; kk < 2; kk++) {
                uint32_t af[4];
                const uint32_t* q = (const uint32_t*)(sc + gid * SCP + kt * TR + kk * 8 + l4);
                af[0] = q[0];
                af[1] = q[8 * SCP];
                af[2] = q[4];
                af[3] = q[8 * SCP + 4];
                #pragma unroll
                for (int nt = 0; nt < 2; nt++) {
                    uint32_t bf[2];
                    const uint32_t* p = (const uint32_t*)(vp + (size_t)(kk * 8 + l4) * kDH + cg * 16 + nt * 8 + gid);
                    bf[0] = p[0];
                    bf[1] = p[4 * kDH];
                    mma8(oacc[nt], af, bf);
                }
            }
        }
        if (half == 1) {
            #pragma unroll
            for (int nt = 0; nt < 2; nt++) {
                int cc = cg * 16 + nt * 8 + l4 * 2;
                *(float2*)&red[gid * kDH + cc] = make_float2(oacc[nt][0], oacc[nt][1]);
                *(float2*)&red[(gid + 8) * kDH + cc] = make_float2(oacc[nt][2], oacc[nt][3]);
            }
        }
        __syncthreads();
        if (half == 0) {
            const int i0 = base + gid;
            float* op0 = g_ao + ((size_t)b * kS + i0) * kD + h * kDH;
            #pragma unroll
            for (int nt = 0; nt < 2; nt++) {
                int cc = cg * 16 + nt * 8 + l4 * 2;
                float2 p0 = *(const float2*)&red[gid * kDH + cc];
                float2 p1 = *(const float2*)&red[(gid + 8) * kDH + cc];
                *(float2*)(op0 + cc) =
                    make_float2(f2tff(oacc[nt][0] + p0.x), f2tff(oacc[nt][1] + p0.y));
                *(float2*)(op0 + 8 * kD + cc) =
                    make_float2(f2tff(oacc[nt][2] + p1.x), f2tff(oacc[nt][3] + p1.y));
            }
        }
    }
}

// ---------------------------------------------------------------------------
// LayerNorm with NADD extra addends: out = LN(X (+A1) (+A2)) * g + b.
// TFOUT: also write tf32-rounded copy (next layer's GEMM A operand).
template<int NADD, bool TFOUT>
__global__ void __launch_bounds__(256) ln_k(const float* __restrict__ X,
                                            const float* __restrict__ A1,
                                            const float* __restrict__ A2,
                                            const float* __restrict__ g,
                                            const float* __restrict__ bt,
                                            float* __restrict__ out,
                                            float* __restrict__ out_tf) {
    __shared__ float red[8];
    const int row = blockIdx.x;
    const int tid = threadIdx.x;
    const int lane = tid & 31, w = tid >> 5;
    const float* xr = X + (size_t)row * kD;
    float v[4];
    float s = 0.f;
    #pragma unroll
    for (int t = 0; t < 4; t++) {
        int d = tid + t * 256;
        float val = xr[d];
        if (NADD >= 1) val += A1[(size_t)row * kD + d];
        if (NADD >= 2) val += A2[(size_t)row * kD + d];
        v[t] = val;
        s += val;
    }
    #pragma unroll
    for (int o = 16; o; o >>= 1) s += __shfl_xor_sync(~0u, s, o);
    if (lane == 0) red[w] = s;
    __syncthreads();
    float tot = 0.f;
    #pragma unroll
    for (int k = 0; k < 8; k++) tot += red[k];
    const float mu = tot * (1.0f / kD);
    __syncthreads();
    float s2 = 0.f;
    #pragma unroll
    for (int t = 0; t < 4; t++) { float dv = v[t] - mu; s2 += dv * dv; }
    #pragma unroll
    for (int o = 16; o; o >>= 1) s2 += __shfl_xor_sync(~0u, s2, o);
    if (lane == 0) red[w] = s2;
    __syncthreads();
    float tot2 = 0.f;
    #pragma unroll
    for (int k = 0; k < 8; k++) tot2 += red[k];
    const float rs = rsqrtf(tot2 * (1.0f / kD) + 1e-5f);
    #pragma unroll
    for (int t = 0; t < 4; t++) {
        int d = tid + t * 256;
        float r = (v[t] - mu) * rs * g[d] + bt[d];
        out[(size_t)row * kD + d] = r;
        if (TFOUT) out_tf[(size_t)row * kD + d] = f2tff(r);
    }
}

// ---------------------------------------------------------------------------
extern "C" void kernel_launch(void* const* d_in, const int* in_sizes, int n_in,
                              void* d_out, int out_size) {
    (void)in_sizes; (void)n_in; (void)out_size;
    const float* q   = (const float*)d_in[0];
    // d_in[1] = lens (unused in eval mode)
    const float* Wq  = (const float*)d_in[2];
    const float* bq  = (const float*)d_in[3];
    const float* Wv  = (const float*)d_in[4];
    const float* bv  = (const float*)d_in[5];
    const float* Wo  = (const float*)d_in[6];
    const float* bo  = (const float*)d_in[7];
    const float* gm  = (const float*)d_in[8];
    const float* lng = (const float*)d_in[9];
    const float* lnb = (const float*)d_in[10];
    const float* fg  = (const float*)d_in[11];
    const float* fb  = (const float*)d_in[12];
    float* out = (float*)d_out;

    cudaFuncSetAttribute(attn_k, cudaFuncAttributeMaxDynamicSharedMemorySize, ATTN_SMEM);
    cudaFuncSetAttribute(gemm_qv, cudaFuncAttributeMaxDynamicSharedMemorySize, GEMM_SMEM);
    cudaFuncSetAttribute(gemm_o,  cudaFuncAttributeMaxDynamicSharedMemorySize, GEMM_SMEM);

    void* p;
    float *xg, *xt, *qhg, *vhg, *aog, *pjg, *pjg2, *wt;
    cudaGetSymbolAddress(&p, g_x);     xg   = (float*)p;
    cudaGetSymbolAddress(&p, g_xt);    xt   = (float*)p;
    cudaGetSymbolAddress(&p, g_qh);    qhg  = (float*)p;
    cudaGetSymbolAddress(&p, g_vh);    vhg  = (float*)p;
    cudaGetSymbolAddress(&p, g_ao);    aog  = (float*)p;
    cudaGetSymbolAddress(&p, g_proj);  pjg  = (float*)p;
    cudaGetSymbolAddress(&p, g_proj2); pjg2 = (float*)p;
    cudaGetSymbolAddress(&p, g_wt);    wt   = (float*)p;

    // Pre-round all GEMM operands once: weights + layer-0 input.
    {
        size_t total4 = 3 * (kWSZ / 4) + (size_t)kBS * kD / 4;
        int blocks = (int)((total4 + 255) / 256);
        round_all<<<blocks, 256>>>(q, Wq, Wv, Wo);
    }
    float* wqt = wt;
    float* wvt = wt + kWSZ;
    float* wot = wt + 2 * kWSZ;

    dim3 gqv(kD / BN, kBS / BM, 2);  // (8, 16, 2) = 256 CTAs
    dim3 ggo(kD / BN, kBS / BM, 2);  // (8, 16, 2) = 256 CTAs (split-K)
    for (int l = 0; l < kL; l++) {
        const float* xin = (l == 0) ? q : xg;   // fp32 residual input
        gemm_qv<<<gqv, 256, GEMM_SMEM>>>(xt,
            wqt + (size_t)l * kD * kD, bq + l * kD,
            wvt + (size_t)l * kD * kD, bv + l * kD, qhg, vhg);
        attn_k<<<kBH * NT16, ATTN_THREADS, ATTN_SMEM>>>(gm + l * kH);
        gemm_o<<<ggo, 256, GEMM_SMEM>>>(aog, wot + (size_t)l * kD * kD, bo + l * kD,
                                        pjg, pjg2);
        if (l + 1 < kL)
            ln_k<2, true ><<<kBS, 256>>>(xin, pjg, pjg2, lng + l * kD, lnb + l * kD, xg, xt);
        else
            ln_k<2, false><<<kBS, 256>>>(xin, pjg, pjg2, lng + l * kD, lnb + l * kD, xg, nullptr);
    }
    ln_k<0, false><<<kBS, 256>>>(xg, nullptr, nullptr, fg, fb, out, nullptr);
}

// round 16
// speedup vs baseline: 1.2927x; 1.0704x over previous
#include <cuda_runtime.h>
#include <math.h>
#include <stdint.h>

namespace {
constexpr int kBn = 2, kS = 1024, kD = 1024, kH = 16, kDH = 64, kL = 4;
constexpr int kBS = kBn * kS;          // 2048 rows
constexpr int kBH = kBn * kH;          // 32 (b,h) pairs
constexpr int TR = 16;                 // query rows per attention block
constexpr int NT16 = kS / TR;          // 64 tiles per (b,h)
constexpr int SCP = 1028;              // padded score-row stride (%4==0, %32==4)
constexpr int ATTN_THREADS = 256;      // 8 warps
constexpr int ATTN_SMEM = (TR * SCP + TR * kDH + TR * 8 * 2) * 4;  // 70912 B
// GEMM tiling: 128x128 block, 8 warps of 32x64, 3-stage cp.async pipeline
constexpr int BM = 128, BN = 128, BK = 32;
constexpr int ASTR = 36, BSTR = 136;   // padded smem strides
constexpr int GEMM_SMEM = 3 * (BM * ASTR + BK * BSTR) * 4;  // 107520 B
constexpr size_t kWSZ = (size_t)kL * kD * kD;    // floats per weight set
}

// Scratch (static device allocations; no runtime allocs)
__device__ float g_x[kBS * kD];          // fp32 activations (residual path)
__device__ float g_xt[kBS * kD];         // tf32-rounded activations (GEMM A)
__device__ float g_qh[kBH * kS * kDH];   // tf32-rounded q heads (also keys)
__device__ float g_vh[kBH * kS * kDH];   // tf32-rounded v heads
__device__ float g_ao[kBS * kD];         // tf32-rounded attention output
__device__ float g_proj[kBS * kD];
__device__ float g_proj2[kBS * kD];      // split-K partial for gemm_o
__device__ float g_wt[3 * kWSZ];         // tf32-rounded Wq|Wv|Wo (all layers)

// ---------------------------------------------------------------------------
__device__ __forceinline__ uint32_t f2tf(float x) {
    uint32_t r;
    asm("cvt.rna.tf32.f32 %0, %1;" : "=r"(r) : "f"(x));
    return r;
}
__device__ __forceinline__ float f2tff(float x) { return __uint_as_float(f2tf(x)); }
__device__ __forceinline__ float sqrt_approx(float x) {
    float r;
    asm("sqrt.approx.f32 %0, %1;" : "=f"(r) : "f"(x));
    return r;
}
__device__ __forceinline__ void mma8(float* d, const uint32_t* a, const uint32_t* b) {
    asm volatile(
        "mma.sync.aligned.m16n8k8.row.col.f32.tf32.tf32.f32 "
        "{%0,%1,%2,%3}, {%4,%5,%6,%7}, {%8,%9}, {%0,%1,%2,%3};\n"
        : "+f"(d[0]), "+f"(d[1]), "+f"(d[2]), "+f"(d[3])
        : "r"(a[0]), "r"(a[1]), "r"(a[2]), "r"(a[3]), "r"(b[0]), "r"(b[1]));
}
// online softmax accumulate (used in phase 1 only)
__device__ __forceinline__ void osm(float v, float& m, float& s) {
    if (v > m) { s = s * __expf(m - v) + 1.f; m = v; }
    else       s += __expf(v - m);
}
// merge two (m,s) online-softmax states
__device__ __forceinline__ void osm_merge(float om, float os, float& m, float& s) {
    float nm = fmaxf(m, om);
    s = s * __expf(m - nm) + os * __expf(om - nm);
    m = nm;
}

// ---------------------------------------------------------------------------
// Pre-round all GEMM operands to tf32 in one pass: Wq|Wv|Wo -> g_wt, q -> g_xt.
__global__ void __launch_bounds__(256) round_all(const float* __restrict__ q,
                                                 const float* __restrict__ Wq,
                                                 const float* __restrict__ Wv,
                                                 const float* __restrict__ Wo) {
    const size_t w4 = kWSZ / 4;            // float4 per weight set
    const size_t x4 = (size_t)kBS * kD / 4;
    size_t i = (size_t)blockIdx.x * 256 + threadIdx.x;
    const float4* src;
    float4* dst;
    size_t off;
    if (i < w4)            { src = (const float4*)Wq; dst = (float4*)g_wt;            off = i; }
    else if (i < 2 * w4)   { src = (const float4*)Wv; dst = (float4*)(g_wt + kWSZ);   off = i - w4; }
    else if (i < 3 * w4)   { src = (const float4*)Wo; dst = (float4*)(g_wt + 2*kWSZ); off = i - 2*w4; }
    else if (i < 3*w4+x4)  { src = (const float4*)q;  dst = (float4*)g_xt;            off = i - 3*w4; }
    else return;
    float4 v = src[off];
    v.x = f2tff(v.x); v.y = f2tff(v.y); v.z = f2tff(v.z); v.w = f2tff(v.w);
    dst[off] = v;
}

// ---------------------------------------------------------------------------
// Shared GEMM body: C = A[:, kbase:+nK*BK] @ W + (bias). Operands tf32 in
// memory (no cvt in inner loop). 3-stage cp.async pipeline.
template<bool SCATTER>
__device__ __forceinline__ void gemm_body(const float* __restrict__ A,
                                          const float* __restrict__ W,
                                          const float* __restrict__ bias,
                                          float* __restrict__ C,
                                          int bxx, int byy, int kbase, int nK,
                                          float* sm) {
    float* As = sm;                          // 3 * BM*ASTR
    float* Bs = sm + 3 * BM * ASTR;          // 3 * BK*BSTR
    const int tid = threadIdx.x, lane = tid & 31, w = tid >> 5;
    const int gid = lane >> 2, l4 = lane & 3;
    const int warpM = w & 3, warpN = w >> 2;
    const int mbase = byy * BM, nbase = bxx * BN;
    const uint32_t sA = (uint32_t)__cvta_generic_to_shared(As);
    const uint32_t sB = (uint32_t)__cvta_generic_to_shared(Bs);

    auto prefetch = [&](int kt, int buf) {
        #pragma unroll
        for (int i = 0; i < 4; i++) {
            int cid = tid + i * 256;
            int m = cid >> 3, kc = cid & 7;
            uint32_t dst = sA + (uint32_t)((buf * BM * ASTR + m * ASTR + kc * 4) * 4);
            const float* src = A + (size_t)(mbase + m) * kD + kbase + kt * BK + kc * 4;
            asm volatile("cp.async.cg.shared.global [%0], [%1], 16;\n" ::"r"(dst), "l"(src));
        }
        #pragma unroll
        for (int i = 0; i < 4; i++) {
            int cid = tid + i * 256;
            int k = cid >> 5, nc = cid & 31;   // full 32 x 128 tile
            uint32_t dst = sB + (uint32_t)((buf * BK * BSTR + k * BSTR + nc * 4) * 4);
            const float* src = W + (size_t)(kbase + kt * BK + k) * kD + nbase + nc * 4;
            asm volatile("cp.async.cg.shared.global [%0], [%1], 16;\n" ::"r"(dst), "l"(src));
        }
        asm volatile("cp.async.commit_group;\n");
    };

    float acc[2][8][4] = {};
    prefetch(0, 0);
    if (nK > 1) prefetch(1, 1);
    int cur = 0;                              // buffer index = kt % 3
    for (int kt = 0; kt < nK; kt++) {
        if (kt + 1 < nK) asm volatile("cp.async.wait_group 1;\n");
        else             asm volatile("cp.async.wait_group 0;\n");
        __syncthreads();
        if (kt + 2 < nK) {
            int nb = cur + 2; if (nb >= 3) nb -= 3;
            prefetch(kt + 2, nb);
        }
        const uint32_t* as = (const uint32_t*)(As + cur * BM * ASTR);
        const uint32_t* bs = (const uint32_t*)(Bs + cur * BK * BSTR);
        #pragma unroll
        for (int ks = 0; ks < 4; ks++) {
            uint32_t af[2][4];
            #pragma unroll
            for (int mt = 0; mt < 2; mt++) {
                int r = warpM * 32 + mt * 16 + gid;
                const uint32_t* p = as + r * ASTR + ks * 8 + l4;
                af[mt][0] = p[0];
                af[mt][1] = p[8 * ASTR];
                af[mt][2] = p[4];
                af[mt][3] = p[8 * ASTR + 4];
            }
            #pragma unroll
            for (int nt = 0; nt < 8; nt++) {
                uint32_t bf[2];
                int cn = warpN * 64 + nt * 8 + gid;
                const uint32_t* p = bs + (ks * 8 + l4) * BSTR + cn;
                bf[0] = p[0];
                bf[1] = p[4 * BSTR];
                #pragma unroll
                for (int mt = 0; mt < 2; mt++) mma8(acc[mt][nt], af[mt], bf);
            }
        }
        if (++cur == 3) cur = 0;
    }
    __syncthreads();
    #pragma unroll
    for (int mt = 0; mt < 2; mt++) {
        int r0 = mbase + warpM * 32 + mt * 16 + gid;
        #pragma unroll
        for (int nt = 0; nt < 8; nt++) {
            int cc = nbase + warpN * 64 + nt * 8 + l4 * 2;
            float b0 = bias ? bias[cc] : 0.f;
            float b1 = bias ? bias[cc + 1] : 0.f;
            float2 u = make_float2(acc[mt][nt][0] + b0, acc[mt][nt][1] + b1);
            float2 v = make_float2(acc[mt][nt][2] + b0, acc[mt][nt][3] + b1);
            if (SCATTER) {
                // pre-round to tf32 so attn_k can feed mma without cvt
                u.x = f2tff(u.x); u.y = f2tff(u.y);
                v.x = f2tff(v.x); v.y = f2tff(v.y);
                int bb = r0 / kS, s = r0 - bb * kS;
                int h = cc >> 6, d = cc & 63;
                *(float2*)&C[(((size_t)bb * kH + h) * kS + s) * kDH + d] = u;
                *(float2*)&C[(((size_t)bb * kH + h) * kS + s + 8) * kDH + d] = v;
            } else {
                *(float2*)&C[(size_t)r0 * kD + cc] = u;
                *(float2*)&C[(size_t)(r0 + 8) * kD + cc] = v;
            }
        }
    }
}

// Fused Wq+Wv projections: blockIdx.z selects which GEMM. 256 CTAs.
__global__ void __launch_bounds__(256) gemm_qv(const float* __restrict__ A,
                                               const float* __restrict__ Wq,
                                               const float* __restrict__ bq,
                                               const float* __restrict__ Wv,
                                               const float* __restrict__ bv,
                                               float* __restrict__ Cq,
                                               float* __restrict__ Cv) {
    extern __shared__ float sm[];
    const float* W = blockIdx.z ? Wv : Wq;
    const float* bias = blockIdx.z ? bv : bq;
    float* C = blockIdx.z ? Cv : Cq;
    gemm_body<true>(A, W, bias, C, blockIdx.x, blockIdx.y, 0, kD / BK, sm);
}

// Wo projection, split-K=2 over blockIdx.z: 256 CTAs fill the chip.
__global__ void __launch_bounds__(256) gemm_o(const float* __restrict__ A,
                                              const float* __restrict__ W,
                                              const float* __restrict__ bias,
                                              float* __restrict__ C1,
                                              float* __restrict__ C2) {
    extern __shared__ float sm[];
    const int z = blockIdx.z;
    gemm_body<false>(A, W, z ? nullptr : bias, z ? C2 : C1,
                     blockIdx.x, blockIdx.y, z * (kD / 2), (kD / 2) / BK, sm);
}

// ---------------------------------------------------------------------------
// Gamma attention, 16 query rows per block, 8 warps, 3 CTAs/SM.
// Phase 2: quad-scan decay with fmaxf-only max tracking (no online softmax
// chains); sum2 fused into pass C's exp; maxout scale folded into phase 3.
__global__ void __launch_bounds__(ATTN_THREADS, 3) attn_k(const float* __restrict__ gam) {
    extern __shared__ float sc[];                 // [TR][SCP] score rows
    float* red = sc + TR * SCP;                   // [TR][64] phase-3 partials
    float* wstat = red + TR * kDH;                // [TR][8][2] per-warp (m,s)
    float* sfrow = wstat;                         // [TR] row scales (reused)

    const int bx = blockIdx.x;
    const int bh = bx & (kBH - 1);
    const int tile = (NT16 - 1) - (bx >> 5);
    const int h = bh & (kH - 1);
    const int b = bh >> 4;
    const int base = tile * TR;
    const int tid = threadIdx.x, lane = tid & 31, w = tid >> 5;
    const int gid = lane >> 2, l4 = lane & 3;
    const float* qb = g_qh + (size_t)bh * kS * kDH;
    const float* vb = g_vh + (size_t)bh * kS * kDH;
    const int nkt = tile + 1, kLimit = nkt * TR;

    // ---- Phase 1: scores = QK^T / 8 with fused online softmax-1 stats.
    {
        uint32_t qa[8][4];
        #pragma unroll
        for (int ks = 0; ks < 8; ks++) {
            const uint32_t* p = (const uint32_t*)(qb + (size_t)(base + gid) * kDH + ks * 8 + l4);
            qa[ks][0] = p[0];
            qa[ks][1] = p[8 * kDH];
            qa[ks][2] = p[4];
            qa[ks][3] = p[8 * kDH + 4];
        }
        const int i0 = base + gid, i1 = base + gid + 8;  // this lane's rows
        float m0 = -3.4e38f, s0 = 0.f, m1 = -3.4e38f, s1 = 0.f;
        for (int kt = w; kt < nkt; kt += 8) {
            const float* kp = qb + (size_t)kt * TR * kDH;
            float acc[2][4] = {};
            #pragma unroll
            for (int ks = 0; ks < 8; ks++) {
                #pragma unroll
                for (int nt = 0; nt < 2; nt++) {
                    uint32_t bf[2];
                    const uint32_t* p = (const uint32_t*)(kp + (size_t)(nt * 8 + gid) * kDH + ks * 8 + l4);
                    bf[0] = p[0];
                    bf[1] = p[4];
                    mma8(acc[nt], qa[ks], bf);
                }
            }
            const bool diag = (kt == tile);
            #pragma unroll
            for (int nt = 0; nt < 2; nt++) {
                int c0 = kt * TR + nt * 8 + l4 * 2;
                float v00 = acc[nt][0] * 0.125f, v01 = acc[nt][1] * 0.125f;
                float v10 = acc[nt][2] * 0.125f, v11 = acc[nt][3] * 0.125f;
                *(float2*)&sc[gid * SCP + c0] = make_float2(v00, v01);
                *(float2*)&sc[(gid + 8) * SCP + c0] = make_float2(v10, v11);
                if (!diag) {            // all cols strictly below both rows
                    osm(v00, m0, s0); osm(v01, m0, s0);
                    osm(v10, m1, s1); osm(v11, m1, s1);
                } else {                // diagonal tile: mask j < i
                    if (c0 < i0)     osm(v00, m0, s0);
                    if (c0 + 1 < i0) osm(v01, m0, s0);
                    if (c0 < i1)     osm(v10, m1, s1);
                    if (c0 + 1 < i1) osm(v11, m1, s1);
                }
            }
        }
        // quad reduce (lanes sharing gid are l4 = 0..3)
        #pragma unroll
        for (int o = 1; o <= 2; o <<= 1) {
            float om = __shfl_xor_sync(~0u, m0, o), os = __shfl_xor_sync(~0u, s0, o);
            osm_merge(om, os, m0, s0);
            om = __shfl_xor_sync(~0u, m1, o); os = __shfl_xor_sync(~0u, s1, o);
            osm_merge(om, os, m1, s1);
        }
        if (l4 == 0) {
            wstat[(gid * 8 + w) * 2] = m0;
            wstat[(gid * 8 + w) * 2 + 1] = s0;
            wstat[((gid + 8) * 8 + w) * 2] = m1;
            wstat[((gid + 8) * 8 + w) * 2 + 1] = s1;
        }
    }
    __syncthreads();

    // ---- Phase 2: combine stats -> quad-scan decay (fmax only) -> exp+sum.
    {
        const float gm = -fabsf(gam[h]);
        const int i0r = base + w;
        const int i1r = i0r + 8;
        float* row0 = sc + w * SCP;
        float* row1 = sc + (w + 8) * SCP;
        const int nv0 = i0r, nv1 = i1r;   // strict causal: keys j < i

        // combine the 8 per-warp partials for this warp's two rows
        float m0 = -3.4e38f, s0 = 0.f, m1 = -3.4e38f, s1 = 0.f;
        #pragma unroll
        for (int p = 0; p < 8; p++) {
            osm_merge(wstat[(w * 8 + p) * 2], wstat[(w * 8 + p) * 2 + 1], m0, s0);
            osm_merge(wstat[((w + 8) * 8 + p) * 2], wstat[((w + 8) * 8 + p) * 2 + 1], m1, s1);
        }
        const float inv0 = (nv0 > 0) ? 1.f / s0 : 0.f;
        const float inv1 = 1.f / s1;

        // Pass B: quad-scan cumsum, decay, store s2; track max via fmaxf only.
        float carry0 = 0.f, carry1 = 0.f;
        float n0 = -3.4e38f, n1 = -3.4e38f;
        for (int c0 = 0; c0 < nv1; c0 += 128) {
            const int j = c0 + lane * 4;
            if (c0 < nv0) {
                bool v0 = j < nv0, v1 = j + 1 < nv0, v2 = j + 2 < nv0, v3 = j + 3 < nv0;
                float4 sv = *(const float4*)&row0[j];   // smem, in-bounds (SCP pad)
                float p0 = v0 ? __expf(sv.x - m0) * inv0 : 0.f;
                float p1 = v1 ? __expf(sv.y - m0) * inv0 : 0.f;
                float p2 = v2 ? __expf(sv.z - m0) * inv0 : 0.f;
                float p3 = v3 ? __expf(sv.w - m0) * inv0 : 0.f;
                float qs = ((p0 + p1) + p2) + p3;
                float inc = qs;
                #pragma unroll
                for (int o = 1; o < 32; o <<= 1) {
                    float t = __shfl_up_sync(~0u, inc, o);
                    if (lane >= o) inc += t;
                }
                float ncar = __shfl_sync(~0u, inc, 31) + carry0;
                float cum0 = (inc - qs + carry0) + p0;
                float cum1 = cum0 + p1;
                float cum2 = cum1 + p2;
                float cum3 = cum2 + p3;
                carry0 = ncar;
                float e0 = fmaxf(__expf(gm * sqrt_approx(fmaxf((1.f - cum0) * (float)(i0r - j), 0.f))), 1e-5f);
                float e1 = fmaxf(__expf(gm * sqrt_approx(fmaxf((1.f - cum1) * (float)(i0r - j - 1), 0.f))), 1e-5f);
                float e2 = fmaxf(__expf(gm * sqrt_approx(fmaxf((1.f - cum2) * (float)(i0r - j - 2), 0.f))), 1e-5f);
                float e3 = fmaxf(__expf(gm * sqrt_approx(fmaxf((1.f - cum3) * (float)(i0r - j - 3), 0.f))), 1e-5f);
                float4 s2 = make_float4(sv.x * e0, sv.y * e1, sv.z * e2, sv.w * e3);
                *(float4*)&row0[j] = s2;
                if (v0) n0 = fmaxf(n0, s2.x);
                if (v1) n0 = fmaxf(n0, s2.y);
                if (v2) n0 = fmaxf(n0, s2.z);
                if (v3) n0 = fmaxf(n0, s2.w);
            }
            {
                bool v0 = j < nv1, v1 = j + 1 < nv1, v2 = j + 2 < nv1, v3 = j + 3 < nv1;
                float4 sv = *(const float4*)&row1[j];
                float p0 = v0 ? __expf(sv.x - m1) * inv1 : 0.f;
                float p1 = v1 ? __expf(sv.y - m1) * inv1 : 0.f;
                float p2 = v2 ? __expf(sv.z - m1) * inv1 : 0.f;
                float p3 = v3 ? __expf(sv.w - m1) * inv1 : 0.f;
                float qs = ((p0 + p1) + p2) + p3;
                float inc = qs;
                #pragma unroll
                for (int o = 1; o < 32; o <<= 1) {
                    float t = __shfl_up_sync(~0u, inc, o);
                    if (lane >= o) inc += t;
                }
                float ncar = __shfl_sync(~0u, inc, 31) + carry1;
                float cum0 = (inc - qs + carry1) + p0;
                float cum1 = cum0 + p1;
                float cum2 = cum1 + p2;
                float cum3 = cum2 + p3;
                carry1 = ncar;
                float e0 = fmaxf(__expf(gm * sqrt_approx(fmaxf((1.f - cum0) * (float)(i1r - j), 0.f))), 1e-5f);
                float e1 = fmaxf(__expf(gm * sqrt_approx(fmaxf((1.f - cum1) * (float)(i1r - j - 1), 0.f))), 1e-5f);
                float e2 = fmaxf(__expf(gm * sqrt_approx(fmaxf((1.f - cum2) * (float)(i1r - j - 2), 0.f))), 1e-5f);
                float e3 = fmaxf(__expf(gm * sqrt_approx(fmaxf((1.f - cum3) * (float)(i1r - j - 3), 0.f))), 1e-5f);
                float4 s2 = make_float4(sv.x * e0, sv.y * e1, sv.z * e2, sv.w * e3);
                *(float4*)&row1[j] = s2;
                if (v0) n1 = fmaxf(n1, s2.x);
                if (v1) n1 = fmaxf(n1, s2.y);
                if (v2) n1 = fmaxf(n1, s2.z);
                if (v3) n1 = fmaxf(n1, s2.w);
            }
        }
        #pragma unroll
        for (int o = 16; o; o >>= 1) {
            n0 = fmaxf(n0, __shfl_xor_sync(~0u, n0, o));
            n1 = fmaxf(n1, __shfl_xor_sync(~0u, n1, o));
        }

        // Pass C: e = exp(s2 - n); accumulate sum2; store tf32 e (unscaled).
        float t0 = 0.f, t1 = 0.f;
        for (int c0 = 0; c0 < kLimit; c0 += 128) {
            const int j = c0 + lane * 4;
            if (j < kLimit) {       // kLimit % 16 == 0 -> whole quad valid
                float4 a = *(const float4*)&row0[j];
                float4 c = *(const float4*)&row1[j];
                float e00 = (j < nv0)     ? __expf(a.x - n0) : 0.f;
                float e01 = (j + 1 < nv0) ? __expf(a.y - n0) : 0.f;
                float e02 = (j + 2 < nv0) ? __expf(a.z - n0) : 0.f;
                float e03 = (j + 3 < nv0) ? __expf(a.w - n0) : 0.f;
                float e10 = (j < nv1)     ? __expf(c.x - n1) : 0.f;
                float e11 = (j + 1 < nv1) ? __expf(c.y - n1) : 0.f;
                float e12 = (j + 2 < nv1) ? __expf(c.z - n1) : 0.f;
                float e13 = (j + 3 < nv1) ? __expf(c.w - n1) : 0.f;
                t0 += ((e00 + e01) + e02) + e03;
                t1 += ((e10 + e11) + e12) + e13;
                *(float4*)&row0[j] = make_float4(f2tff(e00), f2tff(e01), f2tff(e02), f2tff(e03));
                *(float4*)&row1[j] = make_float4(f2tff(e10), f2tff(e11), f2tff(e12), f2tff(e13));
            }
        }
        #pragma unroll
        for (int o = 16; o; o >>= 1) {
            t0 += __shfl_xor_sync(~0u, t0, o);
            t1 += __shfl_xor_sync(~0u, t1, o);
        }
        // maxout: max(attn) = 1/sum2 exactly => scale = min(sum2,5)/sum2
        if (lane == 0) {
            sfrow[w]     = (nv0 > 0) ? fminf(t0, 5.f) / t0 : 0.f;
            sfrow[w + 8] = fminf(t1, 5.f) / t1;
        }
    }
    __syncthreads();

    // ---- Phase 3: out = (e @ V) * sf_row. 4 col groups x 2 kt halves.
    {
        const int cg = w & 3;          // cols [cg*16, cg*16+16)
        const int half = w >> 2;       // kt parity
        float oacc[2][4] = {};
        #pragma unroll 2
        for (int kt = half; kt < nkt; kt += 2) {
            const float* vp = vb + (size_t)kt * TR * kDH;
            #pragma unroll
            for (int kk = 0; kk < 2; kk++) {
                uint32_t af[4];
                const uint32_t* q = (const uint32_t*)(sc + gid * SCP + kt * TR + kk * 8 + l4);
                af[0] = q[0];
                af[1] = q[8 * SCP];
                af[2] = q[4];
                af[3] = q[8 * SCP + 4];
                #pragma unroll
                for (int nt = 0; nt < 2; nt++) {
                    uint32_t bf[2];
                    const uint32_t* p = (const uint32_t*)(vp + (size_t)(kk * 8 + l4) * kDH + cg * 16 + nt * 8 + gid);
                    bf[0] = p[0];
                    bf[1] = p[4 * kDH];
                    mma8(oacc[nt], af, bf);
                }
            }
        }
        if (half == 1) {
            #pragma unroll
            for (int nt = 0; nt < 2; nt++) {
                int cc = cg * 16 + nt * 8 + l4 * 2;
                *(float2*)&red[gid * kDH + cc] = make_float2(oacc[nt][0], oacc[nt][1]);
                *(float2*)&red[(gid + 8) * kDH + cc] = make_float2(oacc[nt][2], oacc[nt][3]);
            }
        }
        __syncthreads();
        if (half == 0) {
            const int i0 = base + gid;
            const float sfa = sfrow[gid];        // row gid scale
            const float sfb = sfrow[gid + 8];    // row gid+8 scale
            float* op0 = g_ao + ((size_t)b * kS + i0) * kD + h * kDH;
            #pragma unroll
            for (int nt = 0; nt < 2; nt++) {
                int cc = cg * 16 + nt * 8 + l4 * 2;
                float2 p0 = *(const float2*)&red[gid * kDH + cc];
                float2 p1 = *(const float2*)&red[(gid + 8) * kDH + cc];
                *(float2*)(op0 + cc) =
                    make_float2(f2tff((oacc[nt][0] + p0.x) * sfa),
                                f2tff((oacc[nt][1] + p0.y) * sfa));
                *(float2*)(op0 + 8 * kD + cc) =
                    make_float2(f2tff((oacc[nt][2] + p1.x) * sfb),
                                f2tff((oacc[nt][3] + p1.y) * sfb));
            }
        }
    }
}

// ---------------------------------------------------------------------------
// LayerNorm with NADD extra addends: out = LN(X (+A1) (+A2)) * g + b.
// TFOUT: also write tf32-rounded copy (next layer's GEMM A operand).
template<int NADD, bool TFOUT>
__global__ void __launch_bounds__(256) ln_k(const float* __restrict__ X,
                                            const float* __restrict__ A1,
                                            const float* __restrict__ A2,
                                            const float* __restrict__ g,
                                            const float* __restrict__ bt,
                                            float* __restrict__ out,
                                            float* __restrict__ out_tf) {
    __shared__ float red[8];
    const int row = blockIdx.x;
    const int tid = threadIdx.x;
    const int lane = tid & 31, w = tid >> 5;
    const float* xr = X + (size_t)row * kD;
    float v[4];
    float s = 0.f;
    #pragma unroll
    for (int t = 0; t < 4; t++) {
        int d = tid + t * 256;
        float val = xr[d];
        if (NADD >= 1) val += A1[(size_t)row * kD + d];
        if (NADD >= 2) val += A2[(size_t)row * kD + d];
        v[t] = val;
        s += val;
    }
    #pragma unroll
    for (int o = 16; o; o >>= 1) s += __shfl_xor_sync(~0u, s, o);
    if (lane == 0) red[w] = s;
    __syncthreads();
    float tot = 0.f;
    #pragma unroll
    for (int k = 0; k < 8; k++) tot += red[k];
    const float mu = tot * (1.0f / kD);
    __syncthreads();
    float s2 = 0.f;
    #pragma unroll
    for (int t = 0; t < 4; t++) { float dv = v[t] - mu; s2 += dv * dv; }
    #pragma unroll
    for (int o = 16; o; o >>= 1) s2 += __shfl_xor_sync(~0u, s2, o);
    if (lane == 0) red[w] = s2;
    __syncthreads();
    float tot2 = 0.f;
    #pragma unroll
    for (int k = 0; k < 8; k++) tot2 += red[k];
    const float rs = rsqrtf(tot2 * (1.0f / kD) + 1e-5f);
    #pragma unroll
    for (int t = 0; t < 4; t++) {
        int d = tid + t * 256;
        float r = (v[t] - mu) * rs * g[d] + bt[d];
        out[(size_t)row * kD + d] = r;
        if (TFOUT) out_tf[(size_t)row * kD + d] = f2tff(r);
    }
}

// ---------------------------------------------------------------------------
extern "C" void kernel_launch(void* const* d_in, const int* in_sizes, int n_in,
                              void* d_out, int out_size) {
    (void)in_sizes; (void)n_in; (void)out_size;
    const float* q   = (const float*)d_in[0];
    // d_in[1] = lens (unused in eval mode)
    const float* Wq  = (const float*)d_in[2];
    const float* bq  = (const float*)d_in[3];
    const float* Wv  = (const float*)d_in[4];
    const float* bv  = (const float*)d_in[5];
    const float* Wo  = (const float*)d_in[6];
    const float* bo  = (const float*)d_in[7];
    const float* gm  = (const float*)d_in[8];
    const float* lng = (const float*)d_in[9];
    const float* lnb = (const float*)d_in[10];
    const float* fg  = (const float*)d_in[11];
    const float* fb  = (const float*)d_in[12];
    float* out = (float*)d_out;

    cudaFuncSetAttribute(attn_k, cudaFuncAttributeMaxDynamicSharedMemorySize, ATTN_SMEM);
    cudaFuncSetAttribute(gemm_qv, cudaFuncAttributeMaxDynamicSharedMemorySize, GEMM_SMEM);
    cudaFuncSetAttribute(gemm_o,  cudaFuncAttributeMaxDynamicSharedMemorySize, GEMM_SMEM);

    void* p;
    float *xg, *xt, *qhg, *vhg, *aog, *pjg, *pjg2, *wt;
    cudaGetSymbolAddress(&p, g_x);     xg   = (float*)p;
    cudaGetSymbolAddress(&p, g_xt);    xt   = (float*)p;
    cudaGetSymbolAddress(&p, g_qh);    qhg  = (float*)p;
    cudaGetSymbolAddress(&p, g_vh);    vhg  = (float*)p;
    cudaGetSymbolAddress(&p, g_ao);    aog  = (float*)p;
    cudaGetSymbolAddress(&p, g_proj);  pjg  = (float*)p;
    cudaGetSymbolAddress(&p, g_proj2); pjg2 = (float*)p;
    cudaGetSymbolAddress(&p, g_wt);    wt   = (float*)p;

    // Pre-round all GEMM operands once: weights + layer-0 input.
    {
        size_t total4 = 3 * (kWSZ / 4) + (size_t)kBS * kD / 4;
        int blocks = (int)((total4 + 255) / 256);
        round_all<<<blocks, 256>>>(q, Wq, Wv, Wo);
    }
    float* wqt = wt;
    float* wvt = wt + kWSZ;
    float* wot = wt + 2 * kWSZ;

    dim3 gqv(kD / BN, kBS / BM, 2);  // (8, 16, 2) = 256 CTAs
    dim3 ggo(kD / BN, kBS / BM, 2);  // (8, 16, 2) = 256 CTAs (split-K)
    for (int l = 0; l < kL; l++) {
        const float* xin = (l == 0) ? q : xg;   // fp32 residual input
        gemm_qv<<<gqv, 256, GEMM_SMEM>>>(xt,
            wqt + (size_t)l * kD * kD, bq + l * kD,
            wvt + (size_t)l * kD * kD, bv + l * kD, qhg, vhg);
        attn_k<<<kBH * NT16, ATTN_THREADS, ATTN_SMEM>>>(gm + l * kH);
        gemm_o<<<ggo, 256, GEMM_SMEM>>>(aog, wot + (size_t)l * kD * kD, bo + l * kD,
                                        pjg, pjg2);
        if (l + 1 < kL)
            ln_k<2, true ><<<kBS, 256>>>(xin, pjg, pjg2, lng + l * kD, lnb + l * kD, xg, xt);
        else
            ln_k<2, false><<<kBS, 256>>>(xin, pjg, pjg2, lng + l * kD, lnb + l * kD, xg, nullptr);
    }
    ln_k<0, false><<<kBS, 256>>>(xg, nullptr, nullptr, fg, fb, out, nullptr);
}